// round 8
// baseline (speedup 1.0000x reference)
#include <cuda_runtime.h>
#include <cuda_bf16.h>
#include <math.h>
#include <stdint.h>

// ---------------- problem dims ----------------
#define BSZ     64
#define TSEQ    64
#define EDIM    512
#define DMODEL  1024
#define DINNER  2048
#define NTOK    (BSZ*TSEQ)       // 4096
#define DSTATE  16
#define DTRANK  64
#define PROJW   96

// ---------------- scratch (device globals, zero-initialized at load) ----------------
__device__ float g_xz  [NTOK * 2 * DINNER];
__device__ float g_xc  [NTOK * DINNER];
__device__ float g_proj[NTOK * PROJW];
__device__ float g_dt  [NTOK * DINNER];
__device__ float g_h2  [NTOK * 256];
// bf16 split-3: A'' = [Ah|Al|Ah] (MxK''), B'' = [Bh|Bh|Bl] (NxK'')
__device__ __nv_bfloat16 g_Ax   [NTOK * 3 * DMODEL];
__device__ __nv_bfloat16 g_Bwin [2 * DINNER * 3 * DMODEL];
__device__ __nv_bfloat16 g_Axc  [NTOK * 3 * DINNER];
__device__ __nv_bfloat16 g_Bwx  [128 * 3 * DINNER];         // rows 96..127 stay 0
__device__ __nv_bfloat16 g_Adt  [NTOK * 3 * DTRANK];
__device__ __nv_bfloat16 g_Bwdt [DINNER * 3 * DTRANK];
__device__ __nv_bfloat16 g_Ay   [NTOK * 3 * DINNER];
__device__ __nv_bfloat16 g_Bwout[DMODEL * 3 * DINNER];
__device__ __nv_bfloat16 g_Af   [NTOK * 3 * DMODEL];
__device__ __nv_bfloat16 g_Bw1  [512 * 3 * DMODEL];
__device__ __nv_bfloat16 g_Ah1  [NTOK * 3 * 512];
__device__ __nv_bfloat16 g_Bw2  [256 * 3 * 512];

// ---------------- MUFU transcendentals ----------------
__device__ __forceinline__ float ex2f(float x) { float y; asm("ex2.approx.f32 %0, %1;" : "=f"(y) : "f"(x)); return y; }
__device__ __forceinline__ float lg2f(float x) { float y; asm("lg2.approx.f32 %0, %1;" : "=f"(y) : "f"(x)); return y; }
__device__ __forceinline__ float rcpf(float x) { float y; asm("rcp.approx.f32 %0, %1;" : "=f"(y) : "f"(x)); return y; }
#define LOG2E 1.4426950408889634f
#define LN2   0.6931471805599453f

__device__ __forceinline__ float softplus_f(float x) {
    if (x > 15.0f) return x;
    return LN2 * lg2f(1.0f + ex2f(LOG2E * x));
}
__device__ __forceinline__ float silu_f(float x) {
    return x * rcpf(1.0f + ex2f(-LOG2E * x));
}

// ---------------- PTX helpers (portable sm_80+ subset) ----------------
__device__ __forceinline__ uint32_t smem_u32(const void* p) {
    uint32_t a;
    asm("{ .reg .u64 t; cvta.to.shared.u64 t, %1; cvt.u32.u64 %0, t; }" : "=r"(a) : "l"(p));
    return a;
}
#define SWZ(off) ((off) ^ (((off) >> 3) & 0x70))

#define CP16(dst, src) asm volatile("cp.async.cg.shared.global [%0], [%1], 16;\n" :: "r"(dst), "l"(src) : "memory")
#define CP_COMMIT()    asm volatile("cp.async.commit_group;\n" ::: "memory")
#define CP_WAIT(n)     asm volatile("cp.async.wait_group %0;\n" :: "n"(n) : "memory")

#define LDSM_X4(r0, r1, r2, r3, addr) \
    asm volatile("ldmatrix.sync.aligned.m8n8.x4.shared.b16 {%0,%1,%2,%3}, [%4];" \
        : "=r"(r0), "=r"(r1), "=r"(r2), "=r"(r3) : "r"(addr))

#define MMA_BF16(c0, c1, c2, c3, a0, a1, a2, a3, b0, b1) \
    asm volatile("mma.sync.aligned.m16n8k16.row.col.f32.bf16.bf16.f32 " \
        "{%0,%1,%2,%3}, {%4,%5,%6,%7}, {%8,%9}, {%0,%1,%2,%3};" \
        : "+f"(c0), "+f"(c1), "+f"(c2), "+f"(c3) \
        : "r"(a0), "r"(a1), "r"(a2), "r"(a3), "r"(b0), "r"(b1))

__device__ __forceinline__ void split_bf16(float v, __nv_bfloat16& hi, __nv_bfloat16& lo) {
    hi = __float2bfloat16(v);
    lo = __float2bfloat16(v - __bfloat162float(hi));
}

// ======================================================================
// BIG GEMM: BM=128, BN=128, BK=64, 128 threads (4 warps, 2m x 2n),
// warp tile 64x64 (1:1 crossbar:tensor ratio), 3-stage cp.async,
// 2 CTAs/SM (smem 97KB/CTA, regs up to 255/thread -> exactly fits).
// Independent co-resident CTAs hide each other's barrier/epilogue stalls.
// ======================================================================
__device__ __forceinline__ void load_stage_big(uint32_t abase,
    const __nv_bfloat16* __restrict__ A, const __nv_bfloat16* __restrict__ B,
    int bm, int bn, int K2, int k0, int tid)
{
    const uint32_t bbase = abase + 128 * 128;
    #pragma unroll
    for (int i = 0; i < 8; i++) {                  // A: 128 rows x 8 chunks
        int c = tid + i * 128;
        int row = c >> 3, ch = c & 7;
        uint32_t dst = abase + SWZ((uint32_t)(row * 128 + ch * 16));
        CP16(dst, A + (size_t)(bm + row) * K2 + k0 + ch * 8);
    }
    #pragma unroll
    for (int i = 0; i < 8; i++) {                  // B: 128 rows x 8 chunks
        int c = tid + i * 128;
        int row = c >> 3, ch = c & 7;
        uint32_t dst = bbase + SWZ((uint32_t)(row * 128 + ch * 16));
        CP16(dst, B + (size_t)(bn + row) * K2 + k0 + ch * 8);
    }
    CP_COMMIT();
}

template<int ACT, bool SPLIT3>
__global__ void __launch_bounds__(128, 2) tgbig_k(
    const __nv_bfloat16* __restrict__ A,
    const __nv_bfloat16* __restrict__ B,
    const float* __restrict__ bias,
    float* __restrict__ Cout,
    __nv_bfloat16* __restrict__ Cs,
    int M, int N, int K2)
{
    constexpr int STAGE = (128 + 128) * 128;       // 32768 B
    extern __shared__ char dsm[];
    const uint32_t base = (smem_u32(dsm) + 1023u) & ~1023u;

    const int tid  = threadIdx.x;
    const int wid  = tid >> 5;
    const int lane = tid & 31;
    const int bm   = blockIdx.y * 128;
    const int bn   = blockIdx.x * 128;

    const int wm = wid & 1;           // 2 m-warps, 64 rows each
    const int wn = wid >> 1;          // 2 n-warps, 64 cols each

    const uint32_t aRow  = (uint32_t)(wm * 64 + (lane & 15));
    const uint32_t aKsel = (uint32_t)(((lane >> 4) & 1) * 16);
    const uint32_t bRow  = (uint32_t)(wn * 64 + (lane & 7) + ((lane >> 4) & 1) * 8);
    const uint32_t bKsel = (uint32_t)(((lane >> 3) & 1) * 16);

    float c[4][8][4];                 // 128 accumulator regs
    #pragma unroll
    for (int mt = 0; mt < 4; mt++)
        #pragma unroll
        for (int nt = 0; nt < 8; nt++)
            #pragma unroll
            for (int r = 0; r < 4; r++) c[mt][nt][r] = 0.0f;

    const int S = K2 / 64;            // users guarantee S >= 3

    load_stage_big(base,             A, B, bm, bn, K2, 0,   tid);
    load_stage_big(base + STAGE,     A, B, bm, bn, K2, 64,  tid);
    load_stage_big(base + 2 * STAGE, A, B, bm, bn, K2, 128, tid);

    for (int s = 0; s < S; s++) {
        if (s + 3 <= S)      { CP_WAIT(2); }
        else if (s + 2 == S) { CP_WAIT(1); }
        else                 { CP_WAIT(0); }
        __syncthreads();

        const int buf = s % 3;
        const uint32_t ab = base + (uint32_t)buf * STAGE;
        const uint32_t bb = ab + 128 * 128;

        #pragma unroll
        for (int ks = 0; ks < 4; ks++) {
            uint32_t a[4][4];
            #pragma unroll
            for (int mt = 0; mt < 4; mt++) {
                uint32_t addr = ab + SWZ((aRow + mt * 16) * 128 + (uint32_t)ks * 32 + aKsel);
                LDSM_X4(a[mt][0], a[mt][1], a[mt][2], a[mt][3], addr);
            }
            #pragma unroll
            for (int ntp = 0; ntp < 4; ntp++) {
                uint32_t b0, b1, b2, b3;
                uint32_t addr = bb + SWZ((bRow + ntp * 16) * 128 + (uint32_t)ks * 32 + bKsel);
                LDSM_X4(b0, b1, b2, b3, addr);
                #pragma unroll
                for (int mt = 0; mt < 4; mt++) {
                    MMA_BF16(c[mt][2 * ntp][0], c[mt][2 * ntp][1],
                             c[mt][2 * ntp][2], c[mt][2 * ntp][3],
                             a[mt][0], a[mt][1], a[mt][2], a[mt][3], b0, b1);
                    MMA_BF16(c[mt][2 * ntp + 1][0], c[mt][2 * ntp + 1][1],
                             c[mt][2 * ntp + 1][2], c[mt][2 * ntp + 1][3],
                             a[mt][0], a[mt][1], a[mt][2], a[mt][3], b2, b3);
                }
            }
        }

        __syncthreads();
        if (s + 3 < S)
            load_stage_big(base + (uint32_t)buf * STAGE, A, B, bm, bn, K2,
                           (s + 3) * 64, tid);
    }

    // epilogue: each warp owns 64 rows x 64 cols
    const int g    = lane >> 2;
    const int tcol = (lane & 3) * 2;
    #pragma unroll
    for (int mt = 0; mt < 4; mt++) {
        #pragma unroll
        for (int half = 0; half < 2; half++) {
            const int row = bm + wm * 64 + mt * 16 + half * 8 + g;
            #pragma unroll
            for (int nt = 0; nt < 8; nt++) {
                const int col = bn + wn * 64 + nt * 8 + tcol;
                float v0 = c[mt][nt][half * 2 + 0];
                float v1 = c[mt][nt][half * 2 + 1];
                if (bias) { v0 += __ldg(&bias[col]); v1 += __ldg(&bias[col + 1]); }
                if (ACT == 2) { v0 = softplus_f(v0); v1 = softplus_f(v1); }
                if (SPLIT3) {
                    __nv_bfloat16 h0, l0, h1, l1;
                    split_bf16(v0, h0, l0);
                    split_bf16(v1, h1, l1);
                    __nv_bfloat16* rp = Cs + (size_t)row * 3 * N;
                    *(__nv_bfloat162*)(rp + col)         = __nv_bfloat162(h0, h1);
                    *(__nv_bfloat162*)(rp + N + col)     = __nv_bfloat162(l0, l1);
                    *(__nv_bfloat162*)(rp + 2 * N + col) = __nv_bfloat162(h0, h1);
                } else {
                    *(float2*)(Cout + (size_t)row * N + col) = make_float2(v0, v1);
                }
            }
        }
    }
}

// ======================================================================
// SMALL GEMM: BM=64, BN=128 tile, 256 threads, 3-stage. (unchanged)
// ======================================================================
template<int BM_, bool SPLITK, int ACT, bool SPLIT3>
__global__ void __launch_bounds__(256, 2) tgsm_k(
    const __nv_bfloat16* __restrict__ A,
    const __nv_bfloat16* __restrict__ B,
    const float* __restrict__ bias,
    float* __restrict__ Cout,
    __nv_bfloat16* __restrict__ Cs,
    int M, int Nout, int K2, int kchunk)
{
    constexpr int NWM = BM_ / 32;
    constexpr int NWN = 8 / NWM;
    constexpr int WNW = 128 / NWN;
    constexpr int NT  = WNW / 8;
    constexpr int STAGE = (BM_ + 128) * 128;
    extern __shared__ char dsm[];
    const uint32_t base = (smem_u32(dsm) + 1023u) & ~1023u;

    const int tid  = threadIdx.x;
    const int wid  = tid >> 5;
    const int lane = tid & 31;
    const int bm   = blockIdx.y * BM_;
    const int bn   = blockIdx.x * 128;

    const int kbeg = SPLITK ? blockIdx.z * kchunk : 0;
    const int S    = (SPLITK ? kchunk : K2) / 64;

    const int wm = wid % NWM;
    const int wn = wid / NWM;

    const uint32_t aRow  = (uint32_t)(wm * 32 + (lane & 15));
    const uint32_t aKsel = (uint32_t)(((lane >> 4) & 1) * 16);
    const uint32_t bRow  = (uint32_t)(wn * WNW + (lane & 7) + ((lane >> 4) & 1) * 8);
    const uint32_t bKsel = (uint32_t)(((lane >> 3) & 1) * 16);

    float c[2][NT][4];
    #pragma unroll
    for (int mt = 0; mt < 2; mt++)
        #pragma unroll
        for (int nt = 0; nt < NT; nt++)
            #pragma unroll
            for (int r = 0; r < 4; r++) c[mt][nt][r] = 0.0f;

    auto load_stage = [&](uint32_t abase, int k0) {
        const uint32_t bbase = abase + BM_ * 128;
        #pragma unroll
        for (int i = 0; i < (BM_ * 8) / 256; i++) {
            int cc = tid + i * 256;
            int row = cc >> 3, ch = cc & 7;
            uint32_t dst = abase + SWZ((uint32_t)(row * 128 + ch * 16));
            CP16(dst, A + (size_t)(bm + row) * K2 + k0 + ch * 8);
        }
        #pragma unroll
        for (int i = 0; i < 4; i++) {
            int cc = tid + i * 256;
            int row = cc >> 3, ch = cc & 7;
            uint32_t dst = bbase + SWZ((uint32_t)(row * 128 + ch * 16));
            CP16(dst, B + (size_t)(bn + row) * K2 + k0 + ch * 8);
        }
        CP_COMMIT();
    };

    load_stage(base,             kbeg);
    load_stage(base + STAGE,     kbeg + 64);
    load_stage(base + 2 * STAGE, kbeg + 128);

    for (int s = 0; s < S; s++) {
        if (s + 3 <= S)      { CP_WAIT(2); }
        else if (s + 2 == S) { CP_WAIT(1); }
        else                 { CP_WAIT(0); }
        __syncthreads();

        const int buf = s % 3;
        const uint32_t ab = base + (uint32_t)buf * STAGE;
        const uint32_t bb = ab + BM_ * 128;

        #pragma unroll
        for (int ks = 0; ks < 4; ks++) {
            uint32_t a[2][4], b[NT / 2][4];
            #pragma unroll
            for (int mt = 0; mt < 2; mt++) {
                uint32_t addr = ab + SWZ((aRow + mt * 16) * 128 + (uint32_t)ks * 32 + aKsel);
                LDSM_X4(a[mt][0], a[mt][1], a[mt][2], a[mt][3], addr);
            }
            #pragma unroll
            for (int ntp = 0; ntp < NT / 2; ntp++) {
                uint32_t addr = bb + SWZ((bRow + ntp * 16) * 128 + (uint32_t)ks * 32 + bKsel);
                LDSM_X4(b[ntp][0], b[ntp][1], b[ntp][2], b[ntp][3], addr);
            }
            #pragma unroll
            for (int mt = 0; mt < 2; mt++)
                #pragma unroll
                for (int nt = 0; nt < NT; nt++) {
                    const int ntp = nt >> 1, hi = nt & 1;
                    MMA_BF16(c[mt][nt][0], c[mt][nt][1], c[mt][nt][2], c[mt][nt][3],
                             a[mt][0], a[mt][1], a[mt][2], a[mt][3],
                             b[ntp][hi * 2], b[ntp][hi * 2 + 1]);
                }
        }

        __syncthreads();
        if (s + 3 < S)
            load_stage(base + (uint32_t)buf * STAGE, kbeg + (s + 3) * 64);
    }

    const int g    = lane >> 2;
    const int tcol = (lane & 3) * 2;
    #pragma unroll
    for (int mt = 0; mt < 2; mt++) {
        #pragma unroll
        for (int half = 0; half < 2; half++) {
            const int row = bm + wm * 32 + mt * 16 + half * 8 + g;
            #pragma unroll
            for (int nt = 0; nt < NT; nt++) {
                const int col = bn + wn * WNW + nt * 8 + tcol;
                if (col >= Nout) continue;
                float v0 = c[mt][nt][half * 2 + 0];
                float v1 = c[mt][nt][half * 2 + 1];
                if (SPLITK) {
                    atomicAdd(&Cout[(size_t)row * Nout + col], v0);
                    if (col + 1 < Nout)
                        atomicAdd(&Cout[(size_t)row * Nout + col + 1], v1);
                } else {
                    if (bias) { v0 += __ldg(&bias[col]); v1 += __ldg(&bias[col + 1]); }
                    if (ACT == 1) { v0 = fmaxf(v0, 0.0f); v1 = fmaxf(v1, 0.0f); }
                    if (SPLIT3) {
                        __nv_bfloat16 h0, l0, h1, l1;
                        split_bf16(v0, h0, l0);
                        split_bf16(v1, h1, l1);
                        __nv_bfloat16* rp = Cs + (size_t)row * 3 * Nout;
                        *(__nv_bfloat162*)(rp + col)            = __nv_bfloat162(h0, h1);
                        *(__nv_bfloat162*)(rp + Nout + col)     = __nv_bfloat162(l0, l1);
                        *(__nv_bfloat162*)(rp + 2 * Nout + col) = __nv_bfloat162(h0, h1);
                    } else {
                        *(float2*)(Cout + (size_t)row * Nout + col) = make_float2(v0, v1);
                    }
                }
            }
        }
    }
}

// ---------------- concat + split3 ----------------
__global__ void concat_split_kernel(const float* __restrict__ sp,
                                    const float* __restrict__ te,
                                    __nv_bfloat16* __restrict__ ax) {
    int i = blockIdx.x * 256 + threadIdx.x;
    if (i < NTOK * DMODEL) {
        int row = i >> 10, c = i & 1023;
        float v = (c < EDIM) ? sp[(size_t)row * EDIM + c]
                             : te[(size_t)row * EDIM + (c - EDIM)];
        __nv_bfloat16 hi, lo; split_bf16(v, hi, lo);
        size_t b = (size_t)row * (3 * DMODEL);
        ax[b + c]              = hi;
        ax[b + DMODEL + c]     = lo;
        ax[b + 2 * DMODEL + c] = hi;
    }
}

// ---------------- weight transpose + split3: W(KxN) -> B''(N x 3K) ----------------
__global__ void wt_split_kernel(const float* __restrict__ W,
                                __nv_bfloat16* __restrict__ out,
                                int K, int N) {
    __shared__ float s[32][33];
    const int tx = threadIdx.x, ty = threadIdx.y;
    const int n0 = blockIdx.x * 32, k0 = blockIdx.y * 32;
    #pragma unroll
    for (int i = 0; i < 4; i++)
        s[ty + 8 * i][tx] = W[(size_t)(k0 + ty + 8 * i) * N + n0 + tx];
    __syncthreads();
    #pragma unroll
    for (int i = 0; i < 4; i++) {
        int n = n0 + ty + 8 * i;
        float v = s[tx][ty + 8 * i];
        __nv_bfloat16 hi, lo; split_bf16(v, hi, lo);
        size_t b = (size_t)n * (3 * K) + k0 + tx;
        out[b]         = hi;
        out[b + K]     = hi;
        out[b + 2 * K] = lo;
    }
}

// ---------------- dt_raw split3 ----------------
__global__ void dtraw_split_kernel(const float* __restrict__ proj,
                                   __nv_bfloat16* __restrict__ out) {
    int i = blockIdx.x * 256 + threadIdx.x;
    if (i < NTOK * DTRANK) {
        int r = i >> 6, c = i & 63;
        float v = proj[(size_t)r * PROJW + c];
        __nv_bfloat16 hi, lo; split_bf16(v, hi, lo);
        size_t b = (size_t)r * (3 * DTRANK);
        out[b + c]       = hi;
        out[b + 64 + c]  = lo;
        out[b + 128 + c] = hi;
    }
}

__global__ void zero_kernel(float* __restrict__ p, int n) {
    int i = blockIdx.x * 256 + threadIdx.x;
    if (i < n) p[i] = 0.0f;
}

// ---------------- causal depthwise conv1d (K=4) + silu; writes fp32 + split3 ----------------
__global__ void conv_silu_kernel(const float* __restrict__ xz,
                                 const float* __restrict__ cw,
                                 const float* __restrict__ cb,
                                 float* __restrict__ xc,
                                 __nv_bfloat16* __restrict__ xc3)
{
    const int d = blockIdx.x * 256 + threadIdx.x;
    const int b = blockIdx.y;
    if (d >= DINNER) return;
    const float w0 = cw[d * 4 + 0], w1 = cw[d * 4 + 1];
    const float w2 = cw[d * 4 + 2], w3 = cw[d * 4 + 3];
    const float bias = cb[d];
    const float* src = xz + (size_t)b * TSEQ * (2 * DINNER) + d;
    float x0 = 0.f, x1 = 0.f, x2 = 0.f;
    const size_t rbase = (size_t)b * TSEQ;
    for (int t = 0; t < TSEQ; t++) {
        float x3 = src[(size_t)t * (2 * DINNER)];
        float v  = fmaf(w3, x3, fmaf(w2, x2, fmaf(w1, x1, w0 * x0))) + bias;
        float s  = silu_f(v);
        const size_t row = rbase + t;
        xc[row * DINNER + d] = s;
        __nv_bfloat16 hi, lo; split_bf16(s, hi, lo);
        const size_t ob = row * (3 * DINNER);
        xc3[ob + d]              = hi;
        xc3[ob + DINNER + d]     = lo;
        xc3[ob + 2 * DINNER + d] = hi;
        x0 = x1; x1 = x2; x2 = x3;
    }
}

// ---------------- selective scan + skip + gate; writes split3 y'' ----------------
__global__ void __launch_bounds__(512) scan_kernel(
    const float* __restrict__ proj,
    const float* __restrict__ dt,
    const float* __restrict__ xc,
    const float* __restrict__ xz,
    const float* __restrict__ A_log,
    const float* __restrict__ D_skip,
    __nv_bfloat16* __restrict__ y2)
{
    const int b = blockIdx.y;
    const int d = blockIdx.x * 512 + threadIdx.x;

    __shared__ float sBC[TSEQ][32];
    for (int i = threadIdx.x; i < TSEQ * 32; i += 512) {
        int t = i >> 5, c = i & 31;
        sBC[t][c] = proj[((size_t)(b * TSEQ + t)) * PROJW + DTRANK + c];
    }
    __syncthreads();

    float A2[DSTATE];
    #pragma unroll
    for (int n = 0; n < DSTATE; n++)
        A2[n] = -ex2f(A_log[(size_t)d * DSTATE + n] * LOG2E) * LOG2E;
    const float Dv = D_skip[d];

    float h[DSTATE];
    #pragma unroll
    for (int n = 0; n < DSTATE; n++) h[n] = 0.0f;

    const size_t rbase = (size_t)b * TSEQ;
    for (int t = 0; t < TSEQ; t++) {
        const size_t row = rbase + t;
        const float dtv = dt[row * DINNER + d];
        const float xv  = xc[row * DINNER + d];
        const float zv  = xz[row * (2 * DINNER) + DINNER + d];
        const float dtx = dtv * xv;
        float yv = 0.0f;
        #pragma unroll
        for (int n = 0; n < DSTATE; n++) {
            const float dA = ex2f(dtv * A2[n]);
            h[n] = fmaf(dA, h[n], dtx * sBC[t][n]);
            yv   = fmaf(h[n], sBC[t][16 + n], yv);
        }
        yv = fmaf(xv, Dv, yv);
        const float val = yv * zv * rcpf(1.0f + ex2f(-LOG2E * zv));
        __nv_bfloat16 hi, lo; split_bf16(val, hi, lo);
        const size_t ob = row * (3 * DINNER);
        y2[ob + d]              = hi;
        y2[ob + DINNER + d]     = lo;
        y2[ob + 2 * DINNER + d] = hi;
    }
}

// ---------------- head: out = h2 @ W3 + b3 (N=6) ----------------
__global__ void head_kernel(const float* __restrict__ h2,
                            const float* __restrict__ W3,
                            const float* __restrict__ b3,
                            float* __restrict__ out)
{
    __shared__ float sW[256 * 6];
    const int tid = threadIdx.x;
    for (int i = tid; i < 256 * 6; i += 256) sW[i] = W3[i];
    __syncthreads();

    const int warp = tid >> 5, lane = tid & 31;
    const int row  = blockIdx.x * 8 + warp;
    const float* hrow = h2 + (size_t)row * 256;

    float acc[6] = {0.f, 0.f, 0.f, 0.f, 0.f, 0.f};
    #pragma unroll
    for (int kk = 0; kk < 8; kk++) {
        const int k = kk * 32 + lane;
        const float v = hrow[k];
        #pragma unroll
        for (int j = 0; j < 6; j++) acc[j] = fmaf(v, sW[k * 6 + j], acc[j]);
    }
    #pragma unroll
    for (int j = 0; j < 6; j++) {
        #pragma unroll
        for (int o = 16; o > 0; o >>= 1)
            acc[j] += __shfl_xor_sync(0xffffffffu, acc[j], o);
    }
    if (lane == 0) {
        #pragma unroll
        for (int j = 0; j < 6; j++)
            out[(size_t)row * 6 + j] = acc[j] + b3[j];
    }
}

// ---------------- launch ----------------
extern "C" void kernel_launch(void* const* d_in, const int* in_sizes, int n_in,
                              void* d_out, int out_size)
{
    const float* spatial  = (const float*)d_in[0];
    const float* temporal = (const float*)d_in[1];
    const float* W_in     = (const float*)d_in[2];
    const float* conv_w   = (const float*)d_in[3];
    const float* conv_b   = (const float*)d_in[4];
    const float* W_x      = (const float*)d_in[5];
    const float* W_dt     = (const float*)d_in[6];
    const float* b_dt     = (const float*)d_in[7];
    const float* A_log    = (const float*)d_in[8];
    const float* D_skip   = (const float*)d_in[9];
    const float* W_out    = (const float*)d_in[10];
    const float* W1       = (const float*)d_in[11];
    const float* b1       = (const float*)d_in[12];
    const float* W2       = (const float*)d_in[13];
    const float* b2       = (const float*)d_in[14];
    const float* W3       = (const float*)d_in[15];
    const float* b3       = (const float*)d_in[16];
    float* out = (float*)d_out;

    float *pxz, *pxc, *pproj, *pdt, *ph2;
    __nv_bfloat16 *pAx, *pBwin, *pAxc, *pBwx, *pAdt, *pBwdt, *pAy, *pBwout,
                  *pAf, *pBw1, *pAh1, *pBw2;
    cudaGetSymbolAddress((void**)&pxz,   g_xz);
    cudaGetSymbolAddress((void**)&pxc,   g_xc);
    cudaGetSymbolAddress((void**)&pproj, g_proj);
    cudaGetSymbolAddress((void**)&pdt,   g_dt);
    cudaGetSymbolAddress((void**)&ph2,   g_h2);
    cudaGetSymbolAddress((void**)&pAx,   g_Ax);
    cudaGetSymbolAddress((void**)&pBwin, g_Bwin);
    cudaGetSymbolAddress((void**)&pAxc,  g_Axc);
    cudaGetSymbolAddress((void**)&pBwx,  g_Bwx);
    cudaGetSymbolAddress((void**)&pAdt,  g_Adt);
    cudaGetSymbolAddress((void**)&pBwdt, g_Bwdt);
    cudaGetSymbolAddress((void**)&pAy,   g_Ay);
    cudaGetSymbolAddress((void**)&pBwout,g_Bwout);
    cudaGetSymbolAddress((void**)&pAf,   g_Af);
    cudaGetSymbolAddress((void**)&pBw1,  g_Bw1);
    cudaGetSymbolAddress((void**)&pAh1,  g_Ah1);
    cudaGetSymbolAddress((void**)&pBw2,  g_Bw2);

    const int SMEM_BIG  = 3 * (128 + 128) * 128 + 1024;   // 99328 (2 CTAs/SM)
    const int SMEM_S64  = 3 * (64  + 128) * 128 + 1024;   // 74752
    cudaFuncSetAttribute(tgbig_k<0, false>, cudaFuncAttributeMaxDynamicSharedMemorySize, SMEM_BIG);
    cudaFuncSetAttribute(tgbig_k<2, false>, cudaFuncAttributeMaxDynamicSharedMemorySize, SMEM_BIG);
    cudaFuncSetAttribute(tgbig_k<0, true>,  cudaFuncAttributeMaxDynamicSharedMemorySize, SMEM_BIG);
    cudaFuncSetAttribute(tgsm_k<64, true,  0, false>, cudaFuncAttributeMaxDynamicSharedMemorySize, SMEM_S64);
    cudaFuncSetAttribute(tgsm_k<64, false, 1, true>,  cudaFuncAttributeMaxDynamicSharedMemorySize, SMEM_S64);
    cudaFuncSetAttribute(tgsm_k<64, false, 1, false>, cudaFuncAttributeMaxDynamicSharedMemorySize, SMEM_S64);

    // 0) concat + split3
    concat_split_kernel<<<(NTOK * DMODEL + 255) / 256, 256>>>(spatial, temporal, pAx);
    // 1) W_in split
    wt_split_kernel<<<dim3(2 * DINNER / 32, DMODEL / 32), dim3(32, 8)>>>(W_in, pBwin, DMODEL, 2 * DINNER);
    // 2) W_x split (96 rows; rows 96..127 of g_Bwx remain zero)
    wt_split_kernel<<<dim3(PROJW / 32, DINNER / 32), dim3(32, 8)>>>(W_x, pBwx, DINNER, PROJW);
    // 3) G1: xz = X @ W_in   M=4096, N=4096, K''=3072   <-- profiled slot
    tgbig_k<0, false><<<dim3(4096 / 128, NTOK / 128), 128, SMEM_BIG>>>(
        pAx, pBwin, nullptr, pxz, nullptr, NTOK, 4096, 3072);
    // 4) conv + silu (fp32 + split3)
    conv_silu_kernel<<<dim3(DINNER / 256, BSZ), 256>>>(pxz, conv_w, conv_b, pxc, pAxc);
    // 5) zero proj
    zero_kernel<<<(NTOK * PROJW + 255) / 256, 256>>>(pproj, NTOK * PROJW);
    // 6) Gx: proj = xc @ W_x  (split-K x4, atomic fp32, Nout=96)
    tgsm_k<64, true, 0, false><<<dim3(1, NTOK / 64, 4), 256, SMEM_S64>>>(
        pAxc, pBwx, nullptr, pproj, nullptr, NTOK, PROJW, 3 * DINNER, 3 * DINNER / 4);
    // 7) W_dt split
    wt_split_kernel<<<dim3(DINNER / 32, DTRANK / 32), dim3(32, 8)>>>(W_dt, pBwdt, DTRANK, DINNER);
    // 8) dt_raw split3
    dtraw_split_kernel<<<(NTOK * DTRANK + 255) / 256, 256>>>(pproj, pAdt);
    // 9) G3: dt = softplus(dt_raw @ W_dt + b_dt)  N=2048, K''=192
    tgbig_k<2, false><<<dim3(DINNER / 128, NTOK / 128), 128, SMEM_BIG>>>(
        pAdt, pBwdt, b_dt, pdt, nullptr, NTOK, DINNER, 192);
    // 10) scan -> y'' split3
    scan_kernel<<<dim3(DINNER / 512, BSZ), 512>>>(pproj, pdt, pxc, pxz, A_log, D_skip, pAy);
    // 11) W_out split
    wt_split_kernel<<<dim3(DMODEL / 32, DINNER / 32), dim3(32, 8)>>>(W_out, pBwout, DINNER, DMODEL);
    // 12) G4: f'' = split3(y @ W_out)  N=1024, K''=6144
    tgbig_k<0, true><<<dim3(DMODEL / 128, NTOK / 128), 128, SMEM_BIG>>>(
        pAy, pBwout, nullptr, nullptr, pAf, NTOK, DMODEL, 6144);
    // 13) W1 split
    wt_split_kernel<<<dim3(512 / 32, DMODEL / 32), dim3(32, 8)>>>(W1, pBw1, DMODEL, 512);
    // 14) G5: h1'' = split3(relu(f @ W1 + b1))  N=512, K''=3072  (BM=64)
    tgsm_k<64, false, 1, true><<<dim3(512 / 128, NTOK / 64), 256, SMEM_S64>>>(
        pAf, pBw1, b1, nullptr, pAh1, NTOK, 512, 3072, 0);
    // 15) W2 split
    wt_split_kernel<<<dim3(256 / 32, 512 / 32), dim3(32, 8)>>>(W2, pBw2, 512, 256);
    // 16) G6: h2 = relu(h1 @ W2 + b2)  N=256, K''=1536  (BM=64)
    tgsm_k<64, false, 1, false><<<dim3(256 / 128, NTOK / 64), 256, SMEM_S64>>>(
        pAh1, pBw2, b2, ph2, nullptr, NTOK, 256, 1536, 0);
    // 17) head
    head_kernel<<<NTOK / 8, 256>>>(ph2, W3, b3, out);
}

// round 9
// speedup vs baseline: 1.0027x; 1.0027x over previous
#include <cuda_runtime.h>
#include <cuda_bf16.h>
#include <math.h>
#include <stdint.h>

// ---------------- problem dims ----------------
#define BSZ     64
#define TSEQ    64
#define EDIM    512
#define DMODEL  1024
#define DINNER  2048
#define NTOK    (BSZ*TSEQ)       // 4096
#define DSTATE  16
#define DTRANK  64
#define PROJW   96

// ---------------- scratch (device globals, zero-initialized at load) ----------------
__device__ float g_xz  [NTOK * 2 * DINNER];
__device__ float g_xc  [NTOK * DINNER];
__device__ float g_proj[NTOK * PROJW];
__device__ float g_dt  [NTOK * DINNER];
__device__ float g_h2  [NTOK * 256];
// bf16 split-3: A'' = [Ah|Al|Ah] (MxK''), B'' = [Bh|Bh|Bl] (NxK'')
__device__ __nv_bfloat16 g_Ax   [NTOK * 3 * DMODEL];
__device__ __nv_bfloat16 g_Bwin [2 * DINNER * 3 * DMODEL];
__device__ __nv_bfloat16 g_Axc  [NTOK * 3 * DINNER];
__device__ __nv_bfloat16 g_Bwx  [128 * 3 * DINNER];         // rows 96..127 stay 0
__device__ __nv_bfloat16 g_Adt  [NTOK * 3 * DTRANK];
__device__ __nv_bfloat16 g_Bwdt [DINNER * 3 * DTRANK];
__device__ __nv_bfloat16 g_Ay   [NTOK * 3 * DINNER];
__device__ __nv_bfloat16 g_Bwout[DMODEL * 3 * DINNER];
__device__ __nv_bfloat16 g_Af   [NTOK * 3 * DMODEL];
__device__ __nv_bfloat16 g_Bw1  [512 * 3 * DMODEL];
__device__ __nv_bfloat16 g_Ah1  [NTOK * 3 * 512];
__device__ __nv_bfloat16 g_Bw2  [256 * 3 * 512];

// ---------------- MUFU transcendentals ----------------
__device__ __forceinline__ float ex2f(float x) { float y; asm("ex2.approx.f32 %0, %1;" : "=f"(y) : "f"(x)); return y; }
__device__ __forceinline__ float lg2f(float x) { float y; asm("lg2.approx.f32 %0, %1;" : "=f"(y) : "f"(x)); return y; }
__device__ __forceinline__ float rcpf(float x) { float y; asm("rcp.approx.f32 %0, %1;" : "=f"(y) : "f"(x)); return y; }
#define LOG2E 1.4426950408889634f
#define LN2   0.6931471805599453f

__device__ __forceinline__ float softplus_f(float x) {
    if (x > 15.0f) return x;
    return LN2 * lg2f(1.0f + ex2f(LOG2E * x));
}
__device__ __forceinline__ float silu_f(float x) {
    return x * rcpf(1.0f + ex2f(-LOG2E * x));
}

// ---------------- PTX helpers (portable sm_80+ subset) ----------------
__device__ __forceinline__ uint32_t smem_u32(const void* p) {
    uint32_t a;
    asm("{ .reg .u64 t; cvta.to.shared.u64 t, %1; cvt.u32.u64 %0, t; }" : "=r"(a) : "l"(p));
    return a;
}
#define SWZ(off) ((off) ^ (((off) >> 3) & 0x70))

#define CP16(dst, src) asm volatile("cp.async.cg.shared.global [%0], [%1], 16;\n" :: "r"(dst), "l"(src) : "memory")
#define CP_COMMIT()    asm volatile("cp.async.commit_group;\n" ::: "memory")
#define CP_WAIT(n)     asm volatile("cp.async.wait_group %0;\n" :: "n"(n) : "memory")

#define LDSM_X4(r0, r1, r2, r3, addr) \
    asm volatile("ldmatrix.sync.aligned.m8n8.x4.shared.b16 {%0,%1,%2,%3}, [%4];" \
        : "=r"(r0), "=r"(r1), "=r"(r2), "=r"(r3) : "r"(addr))

#define MMA_BF16(c0, c1, c2, c3, a0, a1, a2, a3, b0, b1) \
    asm volatile("mma.sync.aligned.m16n8k16.row.col.f32.bf16.bf16.f32 " \
        "{%0,%1,%2,%3}, {%4,%5,%6,%7}, {%8,%9}, {%0,%1,%2,%3};" \
        : "+f"(c0), "+f"(c1), "+f"(c2), "+f"(c3) \
        : "r"(a0), "r"(a1), "r"(a2), "r"(a3), "r"(b0), "r"(b1))

__device__ __forceinline__ void split_bf16(float v, __nv_bfloat16& hi, __nv_bfloat16& lo) {
    hi = __float2bfloat16(v);
    lo = __float2bfloat16(v - __bfloat162float(hi));
}

// ======================================================================
// BIG GEMM: BMT in {64,128}, BN=128, BK=64, 128 threads (4 warps, 2m x 2n),
// warp tile (BMT/2)x64, 3-stage cp.async, 2 CTAs/SM.
// BMT=64 gives fine-grained tiles for wave-quantization-free grids.
// ======================================================================
template<int BMT, int ACT, bool SPLIT3>
__global__ void __launch_bounds__(128, 2) tgbig_k(
    const __nv_bfloat16* __restrict__ A,
    const __nv_bfloat16* __restrict__ B,
    const float* __restrict__ bias,
    float* __restrict__ Cout,
    __nv_bfloat16* __restrict__ Cs,
    int M, int N, int K2)
{
    constexpr int MT    = BMT / 32;                 // m-tiles of 16 rows per warp
    constexpr int STAGE = (BMT + 128) * 128;
    extern __shared__ char dsm[];
    const uint32_t base = (smem_u32(dsm) + 1023u) & ~1023u;

    const int tid  = threadIdx.x;
    const int wid  = tid >> 5;
    const int lane = tid & 31;
    const int bm   = blockIdx.y * BMT;
    const int bn   = blockIdx.x * 128;

    const int wm = wid & 1;           // 2 m-warps, BMT/2 rows each
    const int wn = wid >> 1;          // 2 n-warps, 64 cols each

    const uint32_t aRow  = (uint32_t)(wm * (BMT / 2) + (lane & 15));
    const uint32_t aKsel = (uint32_t)(((lane >> 4) & 1) * 16);
    const uint32_t bRow  = (uint32_t)(wn * 64 + (lane & 7) + ((lane >> 4) & 1) * 8);
    const uint32_t bKsel = (uint32_t)(((lane >> 3) & 1) * 16);

    float c[MT][8][4];
    #pragma unroll
    for (int mt = 0; mt < MT; mt++)
        #pragma unroll
        for (int nt = 0; nt < 8; nt++)
            #pragma unroll
            for (int r = 0; r < 4; r++) c[mt][nt][r] = 0.0f;

    const int S = K2 / 64;            // users guarantee S >= 3

    auto load_stage = [&](uint32_t abase, int k0) {
        const uint32_t bbase = abase + BMT * 128;
        #pragma unroll
        for (int i = 0; i < (BMT * 8) / 128; i++) {
            int cc = tid + i * 128;
            int row = cc >> 3, ch = cc & 7;
            uint32_t dst = abase + SWZ((uint32_t)(row * 128 + ch * 16));
            CP16(dst, A + (size_t)(bm + row) * K2 + k0 + ch * 8);
        }
        #pragma unroll
        for (int i = 0; i < 8; i++) {
            int cc = tid + i * 128;
            int row = cc >> 3, ch = cc & 7;
            uint32_t dst = bbase + SWZ((uint32_t)(row * 128 + ch * 16));
            CP16(dst, B + (size_t)(bn + row) * K2 + k0 + ch * 8);
        }
        CP_COMMIT();
    };

    load_stage(base,             0);
    load_stage(base + STAGE,     64);
    load_stage(base + 2 * STAGE, 128);

    for (int s = 0; s < S; s++) {
        if (s + 3 <= S)      { CP_WAIT(2); }
        else if (s + 2 == S) { CP_WAIT(1); }
        else                 { CP_WAIT(0); }
        __syncthreads();

        const int buf = s % 3;
        const uint32_t ab = base + (uint32_t)buf * STAGE;
        const uint32_t bb = ab + BMT * 128;

        #pragma unroll
        for (int ks = 0; ks < 4; ks++) {
            uint32_t a[MT][4];
            #pragma unroll
            for (int mt = 0; mt < MT; mt++) {
                uint32_t addr = ab + SWZ((aRow + mt * 16) * 128 + (uint32_t)ks * 32 + aKsel);
                LDSM_X4(a[mt][0], a[mt][1], a[mt][2], a[mt][3], addr);
            }
            #pragma unroll
            for (int ntp = 0; ntp < 4; ntp++) {
                uint32_t b0, b1, b2, b3;
                uint32_t addr = bb + SWZ((bRow + ntp * 16) * 128 + (uint32_t)ks * 32 + bKsel);
                LDSM_X4(b0, b1, b2, b3, addr);
                #pragma unroll
                for (int mt = 0; mt < MT; mt++) {
                    MMA_BF16(c[mt][2 * ntp][0], c[mt][2 * ntp][1],
                             c[mt][2 * ntp][2], c[mt][2 * ntp][3],
                             a[mt][0], a[mt][1], a[mt][2], a[mt][3], b0, b1);
                    MMA_BF16(c[mt][2 * ntp + 1][0], c[mt][2 * ntp + 1][1],
                             c[mt][2 * ntp + 1][2], c[mt][2 * ntp + 1][3],
                             a[mt][0], a[mt][1], a[mt][2], a[mt][3], b2, b3);
                }
            }
        }

        __syncthreads();
        if (s + 3 < S)
            load_stage(base + (uint32_t)buf * STAGE, (s + 3) * 64);
    }

    // epilogue
    const int g    = lane >> 2;
    const int tcol = (lane & 3) * 2;
    #pragma unroll
    for (int mt = 0; mt < MT; mt++) {
        #pragma unroll
        for (int half = 0; half < 2; half++) {
            const int row = bm + wm * (BMT / 2) + mt * 16 + half * 8 + g;
            #pragma unroll
            for (int nt = 0; nt < 8; nt++) {
                const int col = bn + wn * 64 + nt * 8 + tcol;
                float v0 = c[mt][nt][half * 2 + 0];
                float v1 = c[mt][nt][half * 2 + 1];
                if (bias) { v0 += __ldg(&bias[col]); v1 += __ldg(&bias[col + 1]); }
                if (ACT == 2) { v0 = softplus_f(v0); v1 = softplus_f(v1); }
                if (SPLIT3) {
                    __nv_bfloat16 h0, l0, h1, l1;
                    split_bf16(v0, h0, l0);
                    split_bf16(v1, h1, l1);
                    __nv_bfloat16* rp = Cs + (size_t)row * 3 * N;
                    *(__nv_bfloat162*)(rp + col)         = __nv_bfloat162(h0, h1);
                    *(__nv_bfloat162*)(rp + N + col)     = __nv_bfloat162(l0, l1);
                    *(__nv_bfloat162*)(rp + 2 * N + col) = __nv_bfloat162(h0, h1);
                } else {
                    *(float2*)(Cout + (size_t)row * N + col) = make_float2(v0, v1);
                }
            }
        }
    }
}

// ======================================================================
// SMALL GEMM: BM=64, BN=128 tile, 256 threads, 3-stage. (unchanged)
// ======================================================================
template<int BM_, bool SPLITK, int ACT, bool SPLIT3>
__global__ void __launch_bounds__(256, 2) tgsm_k(
    const __nv_bfloat16* __restrict__ A,
    const __nv_bfloat16* __restrict__ B,
    const float* __restrict__ bias,
    float* __restrict__ Cout,
    __nv_bfloat16* __restrict__ Cs,
    int M, int Nout, int K2, int kchunk)
{
    constexpr int NWM = BM_ / 32;
    constexpr int NWN = 8 / NWM;
    constexpr int WNW = 128 / NWN;
    constexpr int NT  = WNW / 8;
    constexpr int STAGE = (BM_ + 128) * 128;
    extern __shared__ char dsm[];
    const uint32_t base = (smem_u32(dsm) + 1023u) & ~1023u;

    const int tid  = threadIdx.x;
    const int wid  = tid >> 5;
    const int lane = tid & 31;
    const int bm   = blockIdx.y * BM_;
    const int bn   = blockIdx.x * 128;

    const int kbeg = SPLITK ? blockIdx.z * kchunk : 0;
    const int S    = (SPLITK ? kchunk : K2) / 64;

    const int wm = wid % NWM;
    const int wn = wid / NWM;

    const uint32_t aRow  = (uint32_t)(wm * 32 + (lane & 15));
    const uint32_t aKsel = (uint32_t)(((lane >> 4) & 1) * 16);
    const uint32_t bRow  = (uint32_t)(wn * WNW + (lane & 7) + ((lane >> 4) & 1) * 8);
    const uint32_t bKsel = (uint32_t)(((lane >> 3) & 1) * 16);

    float c[2][NT][4];
    #pragma unroll
    for (int mt = 0; mt < 2; mt++)
        #pragma unroll
        for (int nt = 0; nt < NT; nt++)
            #pragma unroll
            for (int r = 0; r < 4; r++) c[mt][nt][r] = 0.0f;

    auto load_stage = [&](uint32_t abase, int k0) {
        const uint32_t bbase = abase + BM_ * 128;
        #pragma unroll
        for (int i = 0; i < (BM_ * 8) / 256; i++) {
            int cc = tid + i * 256;
            int row = cc >> 3, ch = cc & 7;
            uint32_t dst = abase + SWZ((uint32_t)(row * 128 + ch * 16));
            CP16(dst, A + (size_t)(bm + row) * K2 + k0 + ch * 8);
        }
        #pragma unroll
        for (int i = 0; i < 4; i++) {
            int cc = tid + i * 256;
            int row = cc >> 3, ch = cc & 7;
            uint32_t dst = bbase + SWZ((uint32_t)(row * 128 + ch * 16));
            CP16(dst, B + (size_t)(bn + row) * K2 + k0 + ch * 8);
        }
        CP_COMMIT();
    };

    load_stage(base,             kbeg);
    load_stage(base + STAGE,     kbeg + 64);
    load_stage(base + 2 * STAGE, kbeg + 128);

    for (int s = 0; s < S; s++) {
        if (s + 3 <= S)      { CP_WAIT(2); }
        else if (s + 2 == S) { CP_WAIT(1); }
        else                 { CP_WAIT(0); }
        __syncthreads();

        const int buf = s % 3;
        const uint32_t ab = base + (uint32_t)buf * STAGE;
        const uint32_t bb = ab + BM_ * 128;

        #pragma unroll
        for (int ks = 0; ks < 4; ks++) {
            uint32_t a[2][4], b[NT / 2][4];
            #pragma unroll
            for (int mt = 0; mt < 2; mt++) {
                uint32_t addr = ab + SWZ((aRow + mt * 16) * 128 + (uint32_t)ks * 32 + aKsel);
                LDSM_X4(a[mt][0], a[mt][1], a[mt][2], a[mt][3], addr);
            }
            #pragma unroll
            for (int ntp = 0; ntp < NT / 2; ntp++) {
                uint32_t addr = bb + SWZ((bRow + ntp * 16) * 128 + (uint32_t)ks * 32 + bKsel);
                LDSM_X4(b[ntp][0], b[ntp][1], b[ntp][2], b[ntp][3], addr);
            }
            #pragma unroll
            for (int mt = 0; mt < 2; mt++)
                #pragma unroll
                for (int nt = 0; nt < NT; nt++) {
                    const int ntp = nt >> 1, hi = nt & 1;
                    MMA_BF16(c[mt][nt][0], c[mt][nt][1], c[mt][nt][2], c[mt][nt][3],
                             a[mt][0], a[mt][1], a[mt][2], a[mt][3],
                             b[ntp][hi * 2], b[ntp][hi * 2 + 1]);
                }
        }

        __syncthreads();
        if (s + 3 < S)
            load_stage(base + (uint32_t)buf * STAGE, kbeg + (s + 3) * 64);
    }

    const int g    = lane >> 2;
    const int tcol = (lane & 3) * 2;
    #pragma unroll
    for (int mt = 0; mt < 2; mt++) {
        #pragma unroll
        for (int half = 0; half < 2; half++) {
            const int row = bm + wm * 32 + mt * 16 + half * 8 + g;
            #pragma unroll
            for (int nt = 0; nt < NT; nt++) {
                const int col = bn + wn * WNW + nt * 8 + tcol;
                if (col >= Nout) continue;
                float v0 = c[mt][nt][half * 2 + 0];
                float v1 = c[mt][nt][half * 2 + 1];
                if (SPLITK) {
                    atomicAdd(&Cout[(size_t)row * Nout + col], v0);
                    if (col + 1 < Nout)
                        atomicAdd(&Cout[(size_t)row * Nout + col + 1], v1);
                } else {
                    if (bias) { v0 += __ldg(&bias[col]); v1 += __ldg(&bias[col + 1]); }
                    if (ACT == 1) { v0 = fmaxf(v0, 0.0f); v1 = fmaxf(v1, 0.0f); }
                    if (SPLIT3) {
                        __nv_bfloat16 h0, l0, h1, l1;
                        split_bf16(v0, h0, l0);
                        split_bf16(v1, h1, l1);
                        __nv_bfloat16* rp = Cs + (size_t)row * 3 * Nout;
                        *(__nv_bfloat162*)(rp + col)            = __nv_bfloat162(h0, h1);
                        *(__nv_bfloat162*)(rp + Nout + col)     = __nv_bfloat162(l0, l1);
                        *(__nv_bfloat162*)(rp + 2 * Nout + col) = __nv_bfloat162(h0, h1);
                    } else {
                        *(float2*)(Cout + (size_t)row * Nout + col) = make_float2(v0, v1);
                    }
                }
            }
        }
    }
}

// ---------------- concat + split3 ----------------
__global__ void concat_split_kernel(const float* __restrict__ sp,
                                    const float* __restrict__ te,
                                    __nv_bfloat16* __restrict__ ax) {
    int i = blockIdx.x * 256 + threadIdx.x;
    if (i < NTOK * DMODEL) {
        int row = i >> 10, c = i & 1023;
        float v = (c < EDIM) ? sp[(size_t)row * EDIM + c]
                             : te[(size_t)row * EDIM + (c - EDIM)];
        __nv_bfloat16 hi, lo; split_bf16(v, hi, lo);
        size_t b = (size_t)row * (3 * DMODEL);
        ax[b + c]              = hi;
        ax[b + DMODEL + c]     = lo;
        ax[b + 2 * DMODEL + c] = hi;
    }
}

// ---------------- weight transpose + split3: W(KxN) -> B''(N x 3K) ----------------
__global__ void wt_split_kernel(const float* __restrict__ W,
                                __nv_bfloat16* __restrict__ out,
                                int K, int N) {
    __shared__ float s[32][33];
    const int tx = threadIdx.x, ty = threadIdx.y;
    const int n0 = blockIdx.x * 32, k0 = blockIdx.y * 32;
    #pragma unroll
    for (int i = 0; i < 4; i++)
        s[ty + 8 * i][tx] = W[(size_t)(k0 + ty + 8 * i) * N + n0 + tx];
    __syncthreads();
    #pragma unroll
    for (int i = 0; i < 4; i++) {
        int n = n0 + ty + 8 * i;
        float v = s[tx][ty + 8 * i];
        __nv_bfloat16 hi, lo; split_bf16(v, hi, lo);
        size_t b = (size_t)n * (3 * K) + k0 + tx;
        out[b]         = hi;
        out[b + K]     = hi;
        out[b + 2 * K] = lo;
    }
}

// ---------------- dt_raw split3 ----------------
__global__ void dtraw_split_kernel(const float* __restrict__ proj,
                                   __nv_bfloat16* __restrict__ out) {
    int i = blockIdx.x * 256 + threadIdx.x;
    if (i < NTOK * DTRANK) {
        int r = i >> 6, c = i & 63;
        float v = proj[(size_t)r * PROJW + c];
        __nv_bfloat16 hi, lo; split_bf16(v, hi, lo);
        size_t b = (size_t)r * (3 * DTRANK);
        out[b + c]       = hi;
        out[b + 64 + c]  = lo;
        out[b + 128 + c] = hi;
    }
}

__global__ void zero_kernel(float* __restrict__ p, int n) {
    int i = blockIdx.x * 256 + threadIdx.x;
    if (i < n) p[i] = 0.0f;
}

// ---------------- causal depthwise conv1d (K=4) + silu; writes fp32 + split3 ----------------
__global__ void conv_silu_kernel(const float* __restrict__ xz,
                                 const float* __restrict__ cw,
                                 const float* __restrict__ cb,
                                 float* __restrict__ xc,
                                 __nv_bfloat16* __restrict__ xc3)
{
    const int d = blockIdx.x * 256 + threadIdx.x;
    const int b = blockIdx.y;
    if (d >= DINNER) return;
    const float w0 = cw[d * 4 + 0], w1 = cw[d * 4 + 1];
    const float w2 = cw[d * 4 + 2], w3 = cw[d * 4 + 3];
    const float bias = cb[d];
    const float* src = xz + (size_t)b * TSEQ * (2 * DINNER) + d;
    float x0 = 0.f, x1 = 0.f, x2 = 0.f;
    const size_t rbase = (size_t)b * TSEQ;
    for (int t = 0; t < TSEQ; t++) {
        float x3 = src[(size_t)t * (2 * DINNER)];
        float v  = fmaf(w3, x3, fmaf(w2, x2, fmaf(w1, x1, w0 * x0))) + bias;
        float s  = silu_f(v);
        const size_t row = rbase + t;
        xc[row * DINNER + d] = s;
        __nv_bfloat16 hi, lo; split_bf16(s, hi, lo);
        const size_t ob = row * (3 * DINNER);
        xc3[ob + d]              = hi;
        xc3[ob + DINNER + d]     = lo;
        xc3[ob + 2 * DINNER + d] = hi;
        x0 = x1; x1 = x2; x2 = x3;
    }
}

// ---------------- selective scan + skip + gate; writes split3 y'' ----------------
__global__ void __launch_bounds__(512) scan_kernel(
    const float* __restrict__ proj,
    const float* __restrict__ dt,
    const float* __restrict__ xc,
    const float* __restrict__ xz,
    const float* __restrict__ A_log,
    const float* __restrict__ D_skip,
    __nv_bfloat16* __restrict__ y2)
{
    const int b = blockIdx.y;
    const int d = blockIdx.x * 512 + threadIdx.x;

    __shared__ float sBC[TSEQ][32];
    for (int i = threadIdx.x; i < TSEQ * 32; i += 512) {
        int t = i >> 5, c = i & 31;
        sBC[t][c] = proj[((size_t)(b * TSEQ + t)) * PROJW + DTRANK + c];
    }
    __syncthreads();

    float A2[DSTATE];
    #pragma unroll
    for (int n = 0; n < DSTATE; n++)
        A2[n] = -ex2f(A_log[(size_t)d * DSTATE + n] * LOG2E) * LOG2E;
    const float Dv = D_skip[d];

    float h[DSTATE];
    #pragma unroll
    for (int n = 0; n < DSTATE; n++) h[n] = 0.0f;

    const size_t rbase = (size_t)b * TSEQ;
    for (int t = 0; t < TSEQ; t++) {
        const size_t row = rbase + t;
        const float dtv = dt[row * DINNER + d];
        const float xv  = xc[row * DINNER + d];
        const float zv  = xz[row * (2 * DINNER) + DINNER + d];
        const float dtx = dtv * xv;
        float yv = 0.0f;
        #pragma unroll
        for (int n = 0; n < DSTATE; n++) {
            const float dA = ex2f(dtv * A2[n]);
            h[n] = fmaf(dA, h[n], dtx * sBC[t][n]);
            yv   = fmaf(h[n], sBC[t][16 + n], yv);
        }
        yv = fmaf(xv, Dv, yv);
        const float val = yv * zv * rcpf(1.0f + ex2f(-LOG2E * zv));
        __nv_bfloat16 hi, lo; split_bf16(val, hi, lo);
        const size_t ob = row * (3 * DINNER);
        y2[ob + d]              = hi;
        y2[ob + DINNER + d]     = lo;
        y2[ob + 2 * DINNER + d] = hi;
    }
}

// ---------------- head: out = h2 @ W3 + b3 (N=6) ----------------
__global__ void head_kernel(const float* __restrict__ h2,
                            const float* __restrict__ W3,
                            const float* __restrict__ b3,
                            float* __restrict__ out)
{
    __shared__ float sW[256 * 6];
    const int tid = threadIdx.x;
    for (int i = tid; i < 256 * 6; i += 256) sW[i] = W3[i];
    __syncthreads();

    const int warp = tid >> 5, lane = tid & 31;
    const int row  = blockIdx.x * 8 + warp;
    const float* hrow = h2 + (size_t)row * 256;

    float acc[6] = {0.f, 0.f, 0.f, 0.f, 0.f, 0.f};
    #pragma unroll
    for (int kk = 0; kk < 8; kk++) {
        const int k = kk * 32 + lane;
        const float v = hrow[k];
        #pragma unroll
        for (int j = 0; j < 6; j++) acc[j] = fmaf(v, sW[k * 6 + j], acc[j]);
    }
    #pragma unroll
    for (int j = 0; j < 6; j++) {
        #pragma unroll
        for (int o = 16; o > 0; o >>= 1)
            acc[j] += __shfl_xor_sync(0xffffffffu, acc[j], o);
    }
    if (lane == 0) {
        #pragma unroll
        for (int j = 0; j < 6; j++)
            out[(size_t)row * 6 + j] = acc[j] + b3[j];
    }
}

// ---------------- launch ----------------
extern "C" void kernel_launch(void* const* d_in, const int* in_sizes, int n_in,
                              void* d_out, int out_size)
{
    const float* spatial  = (const float*)d_in[0];
    const float* temporal = (const float*)d_in[1];
    const float* W_in     = (const float*)d_in[2];
    const float* conv_w   = (const float*)d_in[3];
    const float* conv_b   = (const float*)d_in[4];
    const float* W_x      = (const float*)d_in[5];
    const float* W_dt     = (const float*)d_in[6];
    const float* b_dt     = (const float*)d_in[7];
    const float* A_log    = (const float*)d_in[8];
    const float* D_skip   = (const float*)d_in[9];
    const float* W_out    = (const float*)d_in[10];
    const float* W1       = (const float*)d_in[11];
    const float* b1       = (const float*)d_in[12];
    const float* W2       = (const float*)d_in[13];
    const float* b2       = (const float*)d_in[14];
    const float* W3       = (const float*)d_in[15];
    const float* b3       = (const float*)d_in[16];
    float* out = (float*)d_out;

    float *pxz, *pxc, *pproj, *pdt, *ph2;
    __nv_bfloat16 *pAx, *pBwin, *pAxc, *pBwx, *pAdt, *pBwdt, *pAy, *pBwout,
                  *pAf, *pBw1, *pAh1, *pBw2;
    cudaGetSymbolAddress((void**)&pxz,   g_xz);
    cudaGetSymbolAddress((void**)&pxc,   g_xc);
    cudaGetSymbolAddress((void**)&pproj, g_proj);
    cudaGetSymbolAddress((void**)&pdt,   g_dt);
    cudaGetSymbolAddress((void**)&ph2,   g_h2);
    cudaGetSymbolAddress((void**)&pAx,   g_Ax);
    cudaGetSymbolAddress((void**)&pBwin, g_Bwin);
    cudaGetSymbolAddress((void**)&pAxc,  g_Axc);
    cudaGetSymbolAddress((void**)&pBwx,  g_Bwx);
    cudaGetSymbolAddress((void**)&pAdt,  g_Adt);
    cudaGetSymbolAddress((void**)&pBwdt, g_Bwdt);
    cudaGetSymbolAddress((void**)&pAy,   g_Ay);
    cudaGetSymbolAddress((void**)&pBwout,g_Bwout);
    cudaGetSymbolAddress((void**)&pAf,   g_Af);
    cudaGetSymbolAddress((void**)&pBw1,  g_Bw1);
    cudaGetSymbolAddress((void**)&pAh1,  g_Ah1);
    cudaGetSymbolAddress((void**)&pBw2,  g_Bw2);

    const int SMEM_B128 = 3 * (128 + 128) * 128 + 1024;   // 99328
    const int SMEM_B64  = 3 * (64  + 128) * 128 + 1024;   // 74752
    cudaFuncSetAttribute(tgbig_k<64,  0, false>, cudaFuncAttributeMaxDynamicSharedMemorySize, SMEM_B64);
    cudaFuncSetAttribute(tgbig_k<128, 2, false>, cudaFuncAttributeMaxDynamicSharedMemorySize, SMEM_B128);
    cudaFuncSetAttribute(tgbig_k<128, 0, true>,  cudaFuncAttributeMaxDynamicSharedMemorySize, SMEM_B128);
    cudaFuncSetAttribute(tgsm_k<64, true,  0, false>, cudaFuncAttributeMaxDynamicSharedMemorySize, SMEM_B64);
    cudaFuncSetAttribute(tgsm_k<64, false, 1, true>,  cudaFuncAttributeMaxDynamicSharedMemorySize, SMEM_B64);
    cudaFuncSetAttribute(tgsm_k<64, false, 1, false>, cudaFuncAttributeMaxDynamicSharedMemorySize, SMEM_B64);

    // 0) concat + split3
    concat_split_kernel<<<(NTOK * DMODEL + 255) / 256, 256>>>(spatial, temporal, pAx);
    // 1) W_in split
    wt_split_kernel<<<dim3(2 * DINNER / 32, DMODEL / 32), dim3(32, 8)>>>(W_in, pBwin, DMODEL, 2 * DINNER);
    // 2) W_x split (96 rows; rows 96..127 of g_Bwx remain zero)
    wt_split_kernel<<<dim3(PROJW / 32, DINNER / 32), dim3(32, 8)>>>(W_x, pBwx, DINNER, PROJW);
    // 3) G1: xz = X @ W_in   M=4096, N=4096, K''=3072 — BM=64 grid 2048 (wave-quant free)
    tgbig_k<64, 0, false><<<dim3(4096 / 128, NTOK / 64), 128, SMEM_B64>>>(
        pAx, pBwin, nullptr, pxz, nullptr, NTOK, 4096, 3072);
    // 4) conv + silu (fp32 + split3)
    conv_silu_kernel<<<dim3(DINNER / 256, BSZ), 256>>>(pxz, conv_w, conv_b, pxc, pAxc);
    // 5) zero proj
    zero_kernel<<<(NTOK * PROJW + 255) / 256, 256>>>(pproj, NTOK * PROJW);
    // 6) Gx: proj = xc @ W_x  (split-K x4, atomic fp32, Nout=96)
    tgsm_k<64, true, 0, false><<<dim3(1, NTOK / 64, 4), 256, SMEM_B64>>>(
        pAxc, pBwx, nullptr, pproj, nullptr, NTOK, PROJW, 3 * DINNER, 3 * DINNER / 4);
    // 7) W_dt split
    wt_split_kernel<<<dim3(DINNER / 32, DTRANK / 32), dim3(32, 8)>>>(W_dt, pBwdt, DTRANK, DINNER);
    // 8) dt_raw split3
    dtraw_split_kernel<<<(NTOK * DTRANK + 255) / 256, 256>>>(pproj, pAdt);
    // 9) G3: dt = softplus(dt_raw @ W_dt + b_dt)  N=2048, K''=192
    tgbig_k<128, 2, false><<<dim3(DINNER / 128, NTOK / 128), 128, SMEM_B128>>>(
        pAdt, pBwdt, b_dt, pdt, nullptr, NTOK, DINNER, 192);
    // 10) scan -> y'' split3
    scan_kernel<<<dim3(DINNER / 512, BSZ), 512>>>(pproj, pdt, pxc, pxz, A_log, D_skip, pAy);
    // 11) W_out split
    wt_split_kernel<<<dim3(DMODEL / 32, DINNER / 32), dim3(32, 8)>>>(W_out, pBwout, DINNER, DMODEL);
    // 12) G4: f'' = split3(y @ W_out)  N=1024, K''=6144  (grid 256 = single wave)
    tgbig_k<128, 0, true><<<dim3(DMODEL / 128, NTOK / 128), 128, SMEM_B128>>>(
        pAy, pBwout, nullptr, nullptr, pAf, NTOK, DMODEL, 6144);
    // 13) W1 split
    wt_split_kernel<<<dim3(512 / 32, DMODEL / 32), dim3(32, 8)>>>(W1, pBw1, DMODEL, 512);
    // 14) G5: h1'' = split3(relu(f @ W1 + b1))  N=512, K''=3072  (BM=64)
    tgsm_k<64, false, 1, true><<<dim3(512 / 128, NTOK / 64), 256, SMEM_B64>>>(
        pAf, pBw1, b1, nullptr, pAh1, NTOK, 512, 3072, 0);
    // 15) W2 split
    wt_split_kernel<<<dim3(256 / 32, 512 / 32), dim3(32, 8)>>>(W2, pBw2, 512, 256);
    // 16) G6: h2 = relu(h1 @ W2 + b2)  N=256, K''=1536  (BM=64)
    tgsm_k<64, false, 1, false><<<dim3(256 / 128, NTOK / 64), 256, SMEM_B64>>>(
        pAh1, pBw2, b2, ph2, nullptr, NTOK, 256, 1536, 0);
    // 17) head
    head_kernel<<<NTOK / 8, 256>>>(ph2, W3, b3, out);
}

// round 10
// speedup vs baseline: 1.3096x; 1.3061x over previous
#include <cuda_runtime.h>
#include <cuda_fp16.h>
#include <math.h>
#include <stdint.h>

// ---------------- problem dims ----------------
#define BSZ     64
#define TSEQ    64
#define EDIM    512
#define DMODEL  1024
#define DINNER  2048
#define NTOK    (BSZ*TSEQ)       // 4096
#define DSTATE  16
#define DTRANK  64
#define PROJW   96

// ---------------- scratch (device globals, zero-initialized at load) ----------------
__device__ float g_xz  [NTOK * 2 * DINNER];
__device__ float g_xc  [NTOK * DINNER];
__device__ float g_proj[NTOK * PROJW];
__device__ float g_dt  [NTOK * DINNER];
__device__ float g_h2  [NTOK * 256];
// fp16 split-2: A'' = [Ah|Al] (Mx2K), B'' = [Bh|Bh] (Nx2K).
// (Ah+Al)=A exact to 22 bits; product = A*Bh, error = A*Bl ~ 2^-12 rel.
__device__ __half g_Ax   [NTOK * 2 * DMODEL];
__device__ __half g_Bwin [2 * DINNER * 2 * DMODEL];
__device__ __half g_Axc  [NTOK * 2 * DINNER];
__device__ __half g_Bwx  [128 * 2 * DINNER];          // rows 96..127 stay 0
__device__ __half g_Adt  [NTOK * 2 * DTRANK];
__device__ __half g_Bwdt [DINNER * 2 * DTRANK];
__device__ __half g_Ay   [NTOK * 2 * DINNER];
__device__ __half g_Bwout[DMODEL * 2 * DINNER];
__device__ __half g_Af   [NTOK * 2 * DMODEL];
__device__ __half g_Bw1  [512 * 2 * DMODEL];
__device__ __half g_Ah1  [NTOK * 2 * 512];
__device__ __half g_Bw2  [256 * 2 * 512];

// ---------------- MUFU transcendentals ----------------
__device__ __forceinline__ float ex2f(float x) { float y; asm("ex2.approx.f32 %0, %1;" : "=f"(y) : "f"(x)); return y; }
__device__ __forceinline__ float lg2f(float x) { float y; asm("lg2.approx.f32 %0, %1;" : "=f"(y) : "f"(x)); return y; }
__device__ __forceinline__ float rcpf(float x) { float y; asm("rcp.approx.f32 %0, %1;" : "=f"(y) : "f"(x)); return y; }
#define LOG2E 1.4426950408889634f
#define LN2   0.6931471805599453f

__device__ __forceinline__ float softplus_f(float x) {
    if (x > 15.0f) return x;
    return LN2 * lg2f(1.0f + ex2f(LOG2E * x));
}
__device__ __forceinline__ float silu_f(float x) {
    return x * rcpf(1.0f + ex2f(-LOG2E * x));
}

// ---------------- PTX helpers (portable sm_80+ subset) ----------------
__device__ __forceinline__ uint32_t smem_u32(const void* p) {
    uint32_t a;
    asm("{ .reg .u64 t; cvta.to.shared.u64 t, %1; cvt.u32.u64 %0, t; }" : "=r"(a) : "l"(p));
    return a;
}
#define SWZ(off) ((off) ^ (((off) >> 3) & 0x70))

#define CP16(dst, src) asm volatile("cp.async.cg.shared.global [%0], [%1], 16;\n" :: "r"(dst), "l"(src) : "memory")
#define CP_COMMIT()    asm volatile("cp.async.commit_group;\n" ::: "memory")
#define CP_WAIT(n)     asm volatile("cp.async.wait_group %0;\n" :: "n"(n) : "memory")

#define LDSM_X4(r0, r1, r2, r3, addr) \
    asm volatile("ldmatrix.sync.aligned.m8n8.x4.shared.b16 {%0,%1,%2,%3}, [%4];" \
        : "=r"(r0), "=r"(r1), "=r"(r2), "=r"(r3) : "r"(addr))

#define MMA_F16(c0, c1, c2, c3, a0, a1, a2, a3, b0, b1) \
    asm volatile("mma.sync.aligned.m16n8k16.row.col.f32.f16.f16.f32 " \
        "{%0,%1,%2,%3}, {%4,%5,%6,%7}, {%8,%9}, {%0,%1,%2,%3};" \
        : "+f"(c0), "+f"(c1), "+f"(c2), "+f"(c3) \
        : "r"(a0), "r"(a1), "r"(a2), "r"(a3), "r"(b0), "r"(b1))

__device__ __forceinline__ void split_f16(float v, __half& hi, __half& lo) {
    hi = __float2half_rn(v);
    lo = __float2half_rn(v - __half2float(hi));
}

// ======================================================================
// BIG GEMM: BMT in {64,128}, BN=128, BK=64, 128 threads (4 warps, 2m x 2n),
// warp tile (BMT/2)x64, 3-stage cp.async (S=2 supported), 2 CTAs/SM.
// C(MxN) = A''(MxK2) . B''(NxK2)^T, fp16 inputs, fp32 accumulate.
// ACT: 0 none, 2 softplus. SPLIT2: write fp16 [hi|lo] width-2N to Cs.
// ======================================================================
template<int BMT, int ACT, bool SPLIT2>
__global__ void __launch_bounds__(128, 2) tgbig_k(
    const __half* __restrict__ A,
    const __half* __restrict__ B,
    const float* __restrict__ bias,
    float* __restrict__ Cout,
    __half* __restrict__ Cs,
    int M, int N, int K2)
{
    constexpr int MT    = BMT / 32;
    constexpr int STAGE = (BMT + 128) * 128;
    extern __shared__ char dsm[];
    const uint32_t base = (smem_u32(dsm) + 1023u) & ~1023u;

    const int tid  = threadIdx.x;
    const int wid  = tid >> 5;
    const int lane = tid & 31;
    const int bm   = blockIdx.y * BMT;
    const int bn   = blockIdx.x * 128;

    const int wm = wid & 1;
    const int wn = wid >> 1;

    const uint32_t aRow  = (uint32_t)(wm * (BMT / 2) + (lane & 15));
    const uint32_t aKsel = (uint32_t)(((lane >> 4) & 1) * 16);
    const uint32_t bRow  = (uint32_t)(wn * 64 + (lane & 7) + ((lane >> 4) & 1) * 8);
    const uint32_t bKsel = (uint32_t)(((lane >> 3) & 1) * 16);

    float c[MT][8][4];
    #pragma unroll
    for (int mt = 0; mt < MT; mt++)
        #pragma unroll
        for (int nt = 0; nt < 8; nt++)
            #pragma unroll
            for (int r = 0; r < 4; r++) c[mt][nt][r] = 0.0f;

    const int S = K2 / 64;            // S >= 2

    auto load_stage = [&](uint32_t abase, int k0) {
        const uint32_t bbase = abase + BMT * 128;
        #pragma unroll
        for (int i = 0; i < (BMT * 8) / 128; i++) {
            int cc = tid + i * 128;
            int row = cc >> 3, ch = cc & 7;
            uint32_t dst = abase + SWZ((uint32_t)(row * 128 + ch * 16));
            CP16(dst, A + (size_t)(bm + row) * K2 + k0 + ch * 8);
        }
        #pragma unroll
        for (int i = 0; i < 8; i++) {
            int cc = tid + i * 128;
            int row = cc >> 3, ch = cc & 7;
            uint32_t dst = bbase + SWZ((uint32_t)(row * 128 + ch * 16));
            CP16(dst, B + (size_t)(bn + row) * K2 + k0 + ch * 8);
        }
        CP_COMMIT();
    };

    load_stage(base,         0);
    load_stage(base + STAGE, 64);
    if (S > 2) load_stage(base + 2 * STAGE, 128);

    for (int s = 0; s < S; s++) {
        if (s + 3 <= S)      { CP_WAIT(2); }
        else if (s + 2 == S) { CP_WAIT(1); }
        else                 { CP_WAIT(0); }
        __syncthreads();

        const int buf = s % 3;
        const uint32_t ab = base + (uint32_t)buf * STAGE;
        const uint32_t bb = ab + BMT * 128;

        #pragma unroll
        for (int ks = 0; ks < 4; ks++) {
            uint32_t a[MT][4];
            #pragma unroll
            for (int mt = 0; mt < MT; mt++) {
                uint32_t addr = ab + SWZ((aRow + mt * 16) * 128 + (uint32_t)ks * 32 + aKsel);
                LDSM_X4(a[mt][0], a[mt][1], a[mt][2], a[mt][3], addr);
            }
            #pragma unroll
            for (int ntp = 0; ntp < 4; ntp++) {
                uint32_t b0, b1, b2, b3;
                uint32_t addr = bb + SWZ((bRow + ntp * 16) * 128 + (uint32_t)ks * 32 + bKsel);
                LDSM_X4(b0, b1, b2, b3, addr);
                #pragma unroll
                for (int mt = 0; mt < MT; mt++) {
                    MMA_F16(c[mt][2 * ntp][0], c[mt][2 * ntp][1],
                            c[mt][2 * ntp][2], c[mt][2 * ntp][3],
                            a[mt][0], a[mt][1], a[mt][2], a[mt][3], b0, b1);
                    MMA_F16(c[mt][2 * ntp + 1][0], c[mt][2 * ntp + 1][1],
                            c[mt][2 * ntp + 1][2], c[mt][2 * ntp + 1][3],
                            a[mt][0], a[mt][1], a[mt][2], a[mt][3], b2, b3);
                }
            }
        }

        __syncthreads();
        if (s + 3 < S)
            load_stage(base + (uint32_t)buf * STAGE, (s + 3) * 64);
    }

    // epilogue
    const int g    = lane >> 2;
    const int tcol = (lane & 3) * 2;
    #pragma unroll
    for (int mt = 0; mt < MT; mt++) {
        #pragma unroll
        for (int half = 0; half < 2; half++) {
            const int row = bm + wm * (BMT / 2) + mt * 16 + half * 8 + g;
            #pragma unroll
            for (int nt = 0; nt < 8; nt++) {
                const int col = bn + wn * 64 + nt * 8 + tcol;
                float v0 = c[mt][nt][half * 2 + 0];
                float v1 = c[mt][nt][half * 2 + 1];
                if (bias) { v0 += __ldg(&bias[col]); v1 += __ldg(&bias[col + 1]); }
                if (ACT == 2) { v0 = softplus_f(v0); v1 = softplus_f(v1); }
                if (SPLIT2) {
                    __half h0, l0, h1, l1;
                    split_f16(v0, h0, l0);
                    split_f16(v1, h1, l1);
                    __half* rp = Cs + (size_t)row * 2 * N;
                    *(__half2*)(rp + col)     = __halves2half2(h0, h1);
                    *(__half2*)(rp + N + col) = __halves2half2(l0, l1);
                } else {
                    *(float2*)(Cout + (size_t)row * N + col) = make_float2(v0, v1);
                }
            }
        }
    }
}

// ======================================================================
// SMALL GEMM: BM=64, BN=128 tile, 256 threads, 3-stage (S=2 supported).
// ======================================================================
template<int BM_, bool SPLITK, int ACT, bool SPLIT2>
__global__ void __launch_bounds__(256, 2) tgsm_k(
    const __half* __restrict__ A,
    const __half* __restrict__ B,
    const float* __restrict__ bias,
    float* __restrict__ Cout,
    __half* __restrict__ Cs,
    int M, int Nout, int K2, int kchunk)
{
    constexpr int NWM = BM_ / 32;
    constexpr int NWN = 8 / NWM;
    constexpr int WNW = 128 / NWN;
    constexpr int NT  = WNW / 8;
    constexpr int STAGE = (BM_ + 128) * 128;
    extern __shared__ char dsm[];
    const uint32_t base = (smem_u32(dsm) + 1023u) & ~1023u;

    const int tid  = threadIdx.x;
    const int wid  = tid >> 5;
    const int lane = tid & 31;
    const int bm   = blockIdx.y * BM_;
    const int bn   = blockIdx.x * 128;

    const int kbeg = SPLITK ? blockIdx.z * kchunk : 0;
    const int S    = (SPLITK ? kchunk : K2) / 64;

    const int wm = wid % NWM;
    const int wn = wid / NWM;

    const uint32_t aRow  = (uint32_t)(wm * 32 + (lane & 15));
    const uint32_t aKsel = (uint32_t)(((lane >> 4) & 1) * 16);
    const uint32_t bRow  = (uint32_t)(wn * WNW + (lane & 7) + ((lane >> 4) & 1) * 8);
    const uint32_t bKsel = (uint32_t)(((lane >> 3) & 1) * 16);

    float c[2][NT][4];
    #pragma unroll
    for (int mt = 0; mt < 2; mt++)
        #pragma unroll
        for (int nt = 0; nt < NT; nt++)
            #pragma unroll
            for (int r = 0; r < 4; r++) c[mt][nt][r] = 0.0f;

    auto load_stage = [&](uint32_t abase, int k0) {
        const uint32_t bbase = abase + BM_ * 128;
        #pragma unroll
        for (int i = 0; i < (BM_ * 8) / 256; i++) {
            int cc = tid + i * 256;
            int row = cc >> 3, ch = cc & 7;
            uint32_t dst = abase + SWZ((uint32_t)(row * 128 + ch * 16));
            CP16(dst, A + (size_t)(bm + row) * K2 + k0 + ch * 8);
        }
        #pragma unroll
        for (int i = 0; i < 4; i++) {
            int cc = tid + i * 256;
            int row = cc >> 3, ch = cc & 7;
            uint32_t dst = bbase + SWZ((uint32_t)(row * 128 + ch * 16));
            CP16(dst, B + (size_t)(bn + row) * K2 + k0 + ch * 8);
        }
        CP_COMMIT();
    };

    load_stage(base,         kbeg);
    load_stage(base + STAGE, kbeg + 64);
    if (S > 2) load_stage(base + 2 * STAGE, kbeg + 128);

    for (int s = 0; s < S; s++) {
        if (s + 3 <= S)      { CP_WAIT(2); }
        else if (s + 2 == S) { CP_WAIT(1); }
        else                 { CP_WAIT(0); }
        __syncthreads();

        const int buf = s % 3;
        const uint32_t ab = base + (uint32_t)buf * STAGE;
        const uint32_t bb = ab + BM_ * 128;

        #pragma unroll
        for (int ks = 0; ks < 4; ks++) {
            uint32_t a[2][4], b[NT / 2][4];
            #pragma unroll
            for (int mt = 0; mt < 2; mt++) {
                uint32_t addr = ab + SWZ((aRow + mt * 16) * 128 + (uint32_t)ks * 32 + aKsel);
                LDSM_X4(a[mt][0], a[mt][1], a[mt][2], a[mt][3], addr);
            }
            #pragma unroll
            for (int ntp = 0; ntp < NT / 2; ntp++) {
                uint32_t addr = bb + SWZ((bRow + ntp * 16) * 128 + (uint32_t)ks * 32 + bKsel);
                LDSM_X4(b[ntp][0], b[ntp][1], b[ntp][2], b[ntp][3], addr);
            }
            #pragma unroll
            for (int mt = 0; mt < 2; mt++)
                #pragma unroll
                for (int nt = 0; nt < NT; nt++) {
                    const int ntp = nt >> 1, hi = nt & 1;
                    MMA_F16(c[mt][nt][0], c[mt][nt][1], c[mt][nt][2], c[mt][nt][3],
                            a[mt][0], a[mt][1], a[mt][2], a[mt][3],
                            b[ntp][hi * 2], b[ntp][hi * 2 + 1]);
                }
        }

        __syncthreads();
        if (s + 3 < S)
            load_stage(base + (uint32_t)buf * STAGE, kbeg + (s + 3) * 64);
    }

    const int g    = lane >> 2;
    const int tcol = (lane & 3) * 2;
    #pragma unroll
    for (int mt = 0; mt < 2; mt++) {
        #pragma unroll
        for (int half = 0; half < 2; half++) {
            const int row = bm + wm * 32 + mt * 16 + half * 8 + g;
            #pragma unroll
            for (int nt = 0; nt < NT; nt++) {
                const int col = bn + wn * WNW + nt * 8 + tcol;
                if (col >= Nout) continue;
                float v0 = c[mt][nt][half * 2 + 0];
                float v1 = c[mt][nt][half * 2 + 1];
                if (SPLITK) {
                    atomicAdd(&Cout[(size_t)row * Nout + col], v0);
                    if (col + 1 < Nout)
                        atomicAdd(&Cout[(size_t)row * Nout + col + 1], v1);
                } else {
                    if (bias) { v0 += __ldg(&bias[col]); v1 += __ldg(&bias[col + 1]); }
                    if (ACT == 1) { v0 = fmaxf(v0, 0.0f); v1 = fmaxf(v1, 0.0f); }
                    if (SPLIT2) {
                        __half h0, l0, h1, l1;
                        split_f16(v0, h0, l0);
                        split_f16(v1, h1, l1);
                        __half* rp = Cs + (size_t)row * 2 * Nout;
                        *(__half2*)(rp + col)        = __halves2half2(h0, h1);
                        *(__half2*)(rp + Nout + col) = __halves2half2(l0, l1);
                    } else {
                        *(float2*)(Cout + (size_t)row * Nout + col) = make_float2(v0, v1);
                    }
                }
            }
        }
    }
}

// ---------------- concat + split2 ----------------
__global__ void concat_split_kernel(const float* __restrict__ sp,
                                    const float* __restrict__ te,
                                    __half* __restrict__ ax) {
    int i = blockIdx.x * 256 + threadIdx.x;
    if (i < NTOK * DMODEL) {
        int row = i >> 10, c = i & 1023;
        float v = (c < EDIM) ? sp[(size_t)row * EDIM + c]
                             : te[(size_t)row * EDIM + (c - EDIM)];
        __half hi, lo; split_f16(v, hi, lo);
        size_t b = (size_t)row * (2 * DMODEL);
        ax[b + c]          = hi;
        ax[b + DMODEL + c] = lo;
    }
}

// ---------------- weight transpose + dup: W(KxN) -> B''(N x 2K) [Bh|Bh] ----------------
__global__ void wt_split_kernel(const float* __restrict__ W,
                                __half* __restrict__ out,
                                int K, int N) {
    __shared__ float s[32][33];
    const int tx = threadIdx.x, ty = threadIdx.y;
    const int n0 = blockIdx.x * 32, k0 = blockIdx.y * 32;
    #pragma unroll
    for (int i = 0; i < 4; i++)
        s[ty + 8 * i][tx] = W[(size_t)(k0 + ty + 8 * i) * N + n0 + tx];
    __syncthreads();
    #pragma unroll
    for (int i = 0; i < 4; i++) {
        int n = n0 + ty + 8 * i;
        float v = s[tx][ty + 8 * i];
        __half hi = __float2half_rn(v);
        size_t b = (size_t)n * (2 * K) + k0 + tx;
        out[b]     = hi;
        out[b + K] = hi;
    }
}

// ---------------- dt_raw split2 ----------------
__global__ void dtraw_split_kernel(const float* __restrict__ proj,
                                   __half* __restrict__ out) {
    int i = blockIdx.x * 256 + threadIdx.x;
    if (i < NTOK * DTRANK) {
        int r = i >> 6, c = i & 63;
        float v = proj[(size_t)r * PROJW + c];
        __half hi, lo; split_f16(v, hi, lo);
        size_t b = (size_t)r * (2 * DTRANK);
        out[b + c]      = hi;
        out[b + 64 + c] = lo;
    }
}

__global__ void zero_kernel(float* __restrict__ p, int n) {
    int i = blockIdx.x * 256 + threadIdx.x;
    if (i < n) p[i] = 0.0f;
}

// ---------------- causal depthwise conv1d (K=4) + silu; writes fp32 + split2 ----------------
__global__ void conv_silu_kernel(const float* __restrict__ xz,
                                 const float* __restrict__ cw,
                                 const float* __restrict__ cb,
                                 float* __restrict__ xc,
                                 __half* __restrict__ xc2)
{
    const int d = blockIdx.x * 256 + threadIdx.x;
    const int b = blockIdx.y;
    if (d >= DINNER) return;
    const float w0 = cw[d * 4 + 0], w1 = cw[d * 4 + 1];
    const float w2 = cw[d * 4 + 2], w3 = cw[d * 4 + 3];
    const float bias = cb[d];
    const float* src = xz + (size_t)b * TSEQ * (2 * DINNER) + d;
    float x0 = 0.f, x1 = 0.f, x2 = 0.f;
    const size_t rbase = (size_t)b * TSEQ;
    for (int t = 0; t < TSEQ; t++) {
        float x3 = src[(size_t)t * (2 * DINNER)];
        float v  = fmaf(w3, x3, fmaf(w2, x2, fmaf(w1, x1, w0 * x0))) + bias;
        float s  = silu_f(v);
        const size_t row = rbase + t;
        xc[row * DINNER + d] = s;
        __half hi, lo; split_f16(s, hi, lo);
        const size_t ob = row * (2 * DINNER);
        xc2[ob + d]          = hi;
        xc2[ob + DINNER + d] = lo;
        x0 = x1; x1 = x2; x2 = x3;
    }
}

// ---------------- selective scan + skip + gate; writes split2 y'' ----------------
__global__ void __launch_bounds__(512) scan_kernel(
    const float* __restrict__ proj,
    const float* __restrict__ dt,
    const float* __restrict__ xc,
    const float* __restrict__ xz,
    const float* __restrict__ A_log,
    const float* __restrict__ D_skip,
    __half* __restrict__ y2)
{
    const int b = blockIdx.y;
    const int d = blockIdx.x * 512 + threadIdx.x;

    __shared__ float sBC[TSEQ][32];
    for (int i = threadIdx.x; i < TSEQ * 32; i += 512) {
        int t = i >> 5, c = i & 31;
        sBC[t][c] = proj[((size_t)(b * TSEQ + t)) * PROJW + DTRANK + c];
    }
    __syncthreads();

    float A2[DSTATE];
    #pragma unroll
    for (int n = 0; n < DSTATE; n++)
        A2[n] = -ex2f(A_log[(size_t)d * DSTATE + n] * LOG2E) * LOG2E;
    const float Dv = D_skip[d];

    float h[DSTATE];
    #pragma unroll
    for (int n = 0; n < DSTATE; n++) h[n] = 0.0f;

    const size_t rbase = (size_t)b * TSEQ;
    for (int t = 0; t < TSEQ; t++) {
        const size_t row = rbase + t;
        const float dtv = dt[row * DINNER + d];
        const float xv  = xc[row * DINNER + d];
        const float zv  = xz[row * (2 * DINNER) + DINNER + d];
        const float dtx = dtv * xv;
        float yv = 0.0f;
        #pragma unroll
        for (int n = 0; n < DSTATE; n++) {
            const float dA = ex2f(dtv * A2[n]);
            h[n] = fmaf(dA, h[n], dtx * sBC[t][n]);
            yv   = fmaf(h[n], sBC[t][16 + n], yv);
        }
        yv = fmaf(xv, Dv, yv);
        const float val = yv * zv * rcpf(1.0f + ex2f(-LOG2E * zv));
        __half hi, lo; split_f16(val, hi, lo);
        const size_t ob = row * (2 * DINNER);
        y2[ob + d]          = hi;
        y2[ob + DINNER + d] = lo;
    }
}

// ---------------- head: out = h2 @ W3 + b3 (N=6) ----------------
__global__ void head_kernel(const float* __restrict__ h2,
                            const float* __restrict__ W3,
                            const float* __restrict__ b3,
                            float* __restrict__ out)
{
    __shared__ float sW[256 * 6];
    const int tid = threadIdx.x;
    for (int i = tid; i < 256 * 6; i += 256) sW[i] = W3[i];
    __syncthreads();

    const int warp = tid >> 5, lane = tid & 31;
    const int row  = blockIdx.x * 8 + warp;
    const float* hrow = h2 + (size_t)row * 256;

    float acc[6] = {0.f, 0.f, 0.f, 0.f, 0.f, 0.f};
    #pragma unroll
    for (int kk = 0; kk < 8; kk++) {
        const int k = kk * 32 + lane;
        const float v = hrow[k];
        #pragma unroll
        for (int j = 0; j < 6; j++) acc[j] = fmaf(v, sW[k * 6 + j], acc[j]);
    }
    #pragma unroll
    for (int j = 0; j < 6; j++) {
        #pragma unroll
        for (int o = 16; o > 0; o >>= 1)
            acc[j] += __shfl_xor_sync(0xffffffffu, acc[j], o);
    }
    if (lane == 0) {
        #pragma unroll
        for (int j = 0; j < 6; j++)
            out[(size_t)row * 6 + j] = acc[j] + b3[j];
    }
}

// ---------------- launch ----------------
extern "C" void kernel_launch(void* const* d_in, const int* in_sizes, int n_in,
                              void* d_out, int out_size)
{
    const float* spatial  = (const float*)d_in[0];
    const float* temporal = (const float*)d_in[1];
    const float* W_in     = (const float*)d_in[2];
    const float* conv_w   = (const float*)d_in[3];
    const float* conv_b   = (const float*)d_in[4];
    const float* W_x      = (const float*)d_in[5];
    const float* W_dt     = (const float*)d_in[6];
    const float* b_dt     = (const float*)d_in[7];
    const float* A_log    = (const float*)d_in[8];
    const float* D_skip   = (const float*)d_in[9];
    const float* W_out    = (const float*)d_in[10];
    const float* W1       = (const float*)d_in[11];
    const float* b1       = (const float*)d_in[12];
    const float* W2       = (const float*)d_in[13];
    const float* b2       = (const float*)d_in[14];
    const float* W3       = (const float*)d_in[15];
    const float* b3       = (const float*)d_in[16];
    float* out = (float*)d_out;

    float *pxz, *pxc, *pproj, *pdt, *ph2;
    __half *pAx, *pBwin, *pAxc, *pBwx, *pAdt, *pBwdt, *pAy, *pBwout,
           *pAf, *pBw1, *pAh1, *pBw2;
    cudaGetSymbolAddress((void**)&pxz,   g_xz);
    cudaGetSymbolAddress((void**)&pxc,   g_xc);
    cudaGetSymbolAddress((void**)&pproj, g_proj);
    cudaGetSymbolAddress((void**)&pdt,   g_dt);
    cudaGetSymbolAddress((void**)&ph2,   g_h2);
    cudaGetSymbolAddress((void**)&pAx,   g_Ax);
    cudaGetSymbolAddress((void**)&pBwin, g_Bwin);
    cudaGetSymbolAddress((void**)&pAxc,  g_Axc);
    cudaGetSymbolAddress((void**)&pBwx,  g_Bwx);
    cudaGetSymbolAddress((void**)&pAdt,  g_Adt);
    cudaGetSymbolAddress((void**)&pBwdt, g_Bwdt);
    cudaGetSymbolAddress((void**)&pAy,   g_Ay);
    cudaGetSymbolAddress((void**)&pBwout,g_Bwout);
    cudaGetSymbolAddress((void**)&pAf,   g_Af);
    cudaGetSymbolAddress((void**)&pBw1,  g_Bw1);
    cudaGetSymbolAddress((void**)&pAh1,  g_Ah1);
    cudaGetSymbolAddress((void**)&pBw2,  g_Bw2);

    const int SMEM_B128 = 3 * (128 + 128) * 128 + 1024;   // 99328
    const int SMEM_B64  = 3 * (64  + 128) * 128 + 1024;   // 74752
    cudaFuncSetAttribute(tgbig_k<64,  0, false>, cudaFuncAttributeMaxDynamicSharedMemorySize, SMEM_B64);
    cudaFuncSetAttribute(tgbig_k<128, 2, false>, cudaFuncAttributeMaxDynamicSharedMemorySize, SMEM_B128);
    cudaFuncSetAttribute(tgbig_k<128, 0, true>,  cudaFuncAttributeMaxDynamicSharedMemorySize, SMEM_B128);
    cudaFuncSetAttribute(tgsm_k<64, true,  0, false>, cudaFuncAttributeMaxDynamicSharedMemorySize, SMEM_B64);
    cudaFuncSetAttribute(tgsm_k<64, false, 1, true>,  cudaFuncAttributeMaxDynamicSharedMemorySize, SMEM_B64);
    cudaFuncSetAttribute(tgsm_k<64, false, 1, false>, cudaFuncAttributeMaxDynamicSharedMemorySize, SMEM_B64);

    // 0) concat + split2
    concat_split_kernel<<<(NTOK * DMODEL + 255) / 256, 256>>>(spatial, temporal, pAx);
    // 1) W_in dup
    wt_split_kernel<<<dim3(2 * DINNER / 32, DMODEL / 32), dim3(32, 8)>>>(W_in, pBwin, DMODEL, 2 * DINNER);
    // 2) W_x dup (96 rows; rows 96..127 of g_Bwx remain zero)
    wt_split_kernel<<<dim3(PROJW / 32, DINNER / 32), dim3(32, 8)>>>(W_x, pBwx, DINNER, PROJW);
    // 3) G1: xz = X @ W_in   M=4096, N=4096, K''=2048 — BM=64 grid 2048
    tgbig_k<64, 0, false><<<dim3(4096 / 128, NTOK / 64), 128, SMEM_B64>>>(
        pAx, pBwin, nullptr, pxz, nullptr, NTOK, 4096, 2 * DMODEL);
    // 4) conv + silu (fp32 + split2)
    conv_silu_kernel<<<dim3(DINNER / 256, BSZ), 256>>>(pxz, conv_w, conv_b, pxc, pAxc);
    // 5) zero proj
    zero_kernel<<<(NTOK * PROJW + 255) / 256, 256>>>(pproj, NTOK * PROJW);
    // 6) Gx: proj = xc @ W_x  (split-K x4, atomic fp32, Nout=96, K''=4096)
    tgsm_k<64, true, 0, false><<<dim3(1, NTOK / 64, 4), 256, SMEM_B64>>>(
        pAxc, pBwx, nullptr, pproj, nullptr, NTOK, PROJW, 2 * DINNER, 2 * DINNER / 4);
    // 7) W_dt dup
    wt_split_kernel<<<dim3(DINNER / 32, DTRANK / 32), dim3(32, 8)>>>(W_dt, pBwdt, DTRANK, DINNER);
    // 8) dt_raw split2
    dtraw_split_kernel<<<(NTOK * DTRANK + 255) / 256, 256>>>(pproj, pAdt);
    // 9) G3: dt = softplus(dt_raw @ W_dt + b_dt)  N=2048, K''=128 (S=2)
    tgbig_k<128, 2, false><<<dim3(DINNER / 128, NTOK / 128), 128, SMEM_B128>>>(
        pAdt, pBwdt, b_dt, pdt, nullptr, NTOK, DINNER, 2 * DTRANK);
    // 10) scan -> y'' split2
    scan_kernel<<<dim3(DINNER / 512, BSZ), 512>>>(pproj, pdt, pxc, pxz, A_log, D_skip, pAy);
    // 11) W_out dup
    wt_split_kernel<<<dim3(DMODEL / 32, DINNER / 32), dim3(32, 8)>>>(W_out, pBwout, DINNER, DMODEL);
    // 12) G4: f'' = split2(y @ W_out)  N=1024, K''=4096
    tgbig_k<128, 0, true><<<dim3(DMODEL / 128, NTOK / 128), 128, SMEM_B128>>>(
        pAy, pBwout, nullptr, nullptr, pAf, NTOK, DMODEL, 2 * DINNER);
    // 13) W1 dup
    wt_split_kernel<<<dim3(512 / 32, DMODEL / 32), dim3(32, 8)>>>(W1, pBw1, DMODEL, 512);
    // 14) G5: h1'' = split2(relu(f @ W1 + b1))  N=512, K''=2048  (BM=64)
    tgsm_k<64, false, 1, true><<<dim3(512 / 128, NTOK / 64), 256, SMEM_B64>>>(
        pAf, pBw1, b1, nullptr, pAh1, NTOK, 512, 2 * DMODEL, 0);
    // 15) W2 dup
    wt_split_kernel<<<dim3(256 / 32, 512 / 32), dim3(32, 8)>>>(W2, pBw2, 512, 256);
    // 16) G6: h2 = relu(h1 @ W2 + b2)  N=256, K''=1024  (BM=64)
    tgsm_k<64, false, 1, false><<<dim3(256 / 128, NTOK / 64), 256, SMEM_B64>>>(
        pAh1, pBw2, b2, ph2, nullptr, NTOK, 256, 2 * 512, 0);
    // 17) head
    head_kernel<<<NTOK / 8, 256>>>(ph2, W3, b3, out);
}

// round 11
// speedup vs baseline: 1.3603x; 1.0387x over previous
#include <cuda_runtime.h>
#include <cuda_fp16.h>
#include <math.h>
#include <stdint.h>

// ---------------- problem dims ----------------
#define BSZ     64
#define TSEQ    64
#define EDIM    512
#define DMODEL  1024
#define DINNER  2048
#define NTOK    (BSZ*TSEQ)       // 4096
#define DSTATE  16
#define DTRANK  64
#define PROJW   96

// ---------------- scratch (device globals, zero-initialized at load) ----------------
__device__ float g_xz  [NTOK * 2 * DINNER];
__device__ float g_proj[NTOK * PROJW];
__device__ float g_dt  [NTOK * DINNER];
__device__ float g_h2  [NTOK * 256];
// fp16 split-2: A'' = [Ah|Al] (Mx2K), B'' = [Bh|Bh] (Nx2K).
__device__ __half g_Ax   [NTOK * 2 * DMODEL];
__device__ __half g_Bwin [2 * DINNER * 2 * DMODEL];
__device__ __half g_Axc  [NTOK * 2 * DINNER];
__device__ __half g_Bwx  [128 * 2 * DINNER];          // rows 96..127 stay 0
__device__ __half g_Adt  [NTOK * 2 * DTRANK];
__device__ __half g_Bwdt [DINNER * 2 * DTRANK];
__device__ __half g_Ay   [NTOK * 2 * DINNER];
__device__ __half g_Bwout[DMODEL * 2 * DINNER];
__device__ __half g_Af   [NTOK * 2 * DMODEL];
__device__ __half g_Bw1  [512 * 2 * DMODEL];
__device__ __half g_Ah1  [NTOK * 2 * 512];
__device__ __half g_Bw2  [256 * 2 * 512];

// ---------------- MUFU transcendentals ----------------
__device__ __forceinline__ float ex2f(float x) { float y; asm("ex2.approx.f32 %0, %1;" : "=f"(y) : "f"(x)); return y; }
__device__ __forceinline__ float lg2f(float x) { float y; asm("lg2.approx.f32 %0, %1;" : "=f"(y) : "f"(x)); return y; }
__device__ __forceinline__ float rcpf(float x) { float y; asm("rcp.approx.f32 %0, %1;" : "=f"(y) : "f"(x)); return y; }
#define LOG2E 1.4426950408889634f
#define LN2   0.6931471805599453f

__device__ __forceinline__ float softplus_f(float x) {
    if (x > 15.0f) return x;
    return LN2 * lg2f(1.0f + ex2f(LOG2E * x));
}
__device__ __forceinline__ float silu_f(float x) {
    return x * rcpf(1.0f + ex2f(-LOG2E * x));
}

// ---------------- PTX helpers (portable sm_80+ subset) ----------------
__device__ __forceinline__ uint32_t smem_u32(const void* p) {
    uint32_t a;
    asm("{ .reg .u64 t; cvta.to.shared.u64 t, %1; cvt.u32.u64 %0, t; }" : "=r"(a) : "l"(p));
    return a;
}
#define SWZ(off) ((off) ^ (((off) >> 3) & 0x70))

#define CP16(dst, src) asm volatile("cp.async.cg.shared.global [%0], [%1], 16;\n" :: "r"(dst), "l"(src) : "memory")
#define CP_COMMIT()    asm volatile("cp.async.commit_group;\n" ::: "memory")
#define CP_WAIT(n)     asm volatile("cp.async.wait_group %0;\n" :: "n"(n) : "memory")

#define LDSM_X4(r0, r1, r2, r3, addr) \
    asm volatile("ldmatrix.sync.aligned.m8n8.x4.shared.b16 {%0,%1,%2,%3}, [%4];" \
        : "=r"(r0), "=r"(r1), "=r"(r2), "=r"(r3) : "r"(addr))

#define MMA_F16(c0, c1, c2, c3, a0, a1, a2, a3, b0, b1) \
    asm volatile("mma.sync.aligned.m16n8k16.row.col.f32.f16.f16.f32 " \
        "{%0,%1,%2,%3}, {%4,%5,%6,%7}, {%8,%9}, {%0,%1,%2,%3};" \
        : "+f"(c0), "+f"(c1), "+f"(c2), "+f"(c3) \
        : "r"(a0), "r"(a1), "r"(a2), "r"(a3), "r"(b0), "r"(b1))

__device__ __forceinline__ void split_f16(float v, __half& hi, __half& lo) {
    hi = __float2half_rn(v);
    lo = __float2half_rn(v - __half2float(hi));
}

// ======================================================================
// BIG GEMM: BMT in {64,128}, BN=128, BK=64, 128 threads (4 warps, 2m x 2n),
// warp tile (BMT/2)x64, 3-stage cp.async (S=2 supported).
// BMT=64 -> 3 CTAs/SM (regs capped 168, smem 74.75KB); BMT=128 -> 2 CTAs/SM.
// ======================================================================
template<int BMT, int ACT, bool SPLIT2>
__global__ void __launch_bounds__(128, (BMT == 64) ? 3 : 2) tgbig_k(
    const __half* __restrict__ A,
    const __half* __restrict__ B,
    const float* __restrict__ bias,
    float* __restrict__ Cout,
    __half* __restrict__ Cs,
    int M, int N, int K2)
{
    constexpr int MT    = BMT / 32;
    constexpr int STAGE = (BMT + 128) * 128;
    extern __shared__ char dsm[];
    const uint32_t base = (smem_u32(dsm) + 1023u) & ~1023u;

    const int tid  = threadIdx.x;
    const int wid  = tid >> 5;
    const int lane = tid & 31;
    const int bm   = blockIdx.y * BMT;
    const int bn   = blockIdx.x * 128;

    const int wm = wid & 1;
    const int wn = wid >> 1;

    const uint32_t aRow  = (uint32_t)(wm * (BMT / 2) + (lane & 15));
    const uint32_t aKsel = (uint32_t)(((lane >> 4) & 1) * 16);
    const uint32_t bRow  = (uint32_t)(wn * 64 + (lane & 7) + ((lane >> 4) & 1) * 8);
    const uint32_t bKsel = (uint32_t)(((lane >> 3) & 1) * 16);

    float c[MT][8][4];
    #pragma unroll
    for (int mt = 0; mt < MT; mt++)
        #pragma unroll
        for (int nt = 0; nt < 8; nt++)
            #pragma unroll
            for (int r = 0; r < 4; r++) c[mt][nt][r] = 0.0f;

    const int S = K2 / 64;            // S >= 2

    auto load_stage = [&](uint32_t abase, int k0) {
        const uint32_t bbase = abase + BMT * 128;
        #pragma unroll
        for (int i = 0; i < (BMT * 8) / 128; i++) {
            int cc = tid + i * 128;
            int row = cc >> 3, ch = cc & 7;
            uint32_t dst = abase + SWZ((uint32_t)(row * 128 + ch * 16));
            CP16(dst, A + (size_t)(bm + row) * K2 + k0 + ch * 8);
        }
        #pragma unroll
        for (int i = 0; i < 8; i++) {
            int cc = tid + i * 128;
            int row = cc >> 3, ch = cc & 7;
            uint32_t dst = bbase + SWZ((uint32_t)(row * 128 + ch * 16));
            CP16(dst, B + (size_t)(bn + row) * K2 + k0 + ch * 8);
        }
        CP_COMMIT();
    };

    load_stage(base,         0);
    load_stage(base + STAGE, 64);
    if (S > 2) load_stage(base + 2 * STAGE, 128);

    for (int s = 0; s < S; s++) {
        if (s + 3 <= S)      { CP_WAIT(2); }
        else if (s + 2 == S) { CP_WAIT(1); }
        else                 { CP_WAIT(0); }
        __syncthreads();

        const int buf = s % 3;
        const uint32_t ab = base + (uint32_t)buf * STAGE;
        const uint32_t bb = ab + BMT * 128;

        #pragma unroll
        for (int ks = 0; ks < 4; ks++) {
            uint32_t a[MT][4];
            #pragma unroll
            for (int mt = 0; mt < MT; mt++) {
                uint32_t addr = ab + SWZ((aRow + mt * 16) * 128 + (uint32_t)ks * 32 + aKsel);
                LDSM_X4(a[mt][0], a[mt][1], a[mt][2], a[mt][3], addr);
            }
            #pragma unroll
            for (int ntp = 0; ntp < 4; ntp++) {
                uint32_t b0, b1, b2, b3;
                uint32_t addr = bb + SWZ((bRow + ntp * 16) * 128 + (uint32_t)ks * 32 + bKsel);
                LDSM_X4(b0, b1, b2, b3, addr);
                #pragma unroll
                for (int mt = 0; mt < MT; mt++) {
                    MMA_F16(c[mt][2 * ntp][0], c[mt][2 * ntp][1],
                            c[mt][2 * ntp][2], c[mt][2 * ntp][3],
                            a[mt][0], a[mt][1], a[mt][2], a[mt][3], b0, b1);
                    MMA_F16(c[mt][2 * ntp + 1][0], c[mt][2 * ntp + 1][1],
                            c[mt][2 * ntp + 1][2], c[mt][2 * ntp + 1][3],
                            a[mt][0], a[mt][1], a[mt][2], a[mt][3], b2, b3);
                }
            }
        }

        __syncthreads();
        if (s + 3 < S)
            load_stage(base + (uint32_t)buf * STAGE, (s + 3) * 64);
    }

    // epilogue
    const int g    = lane >> 2;
    const int tcol = (lane & 3) * 2;
    #pragma unroll
    for (int mt = 0; mt < MT; mt++) {
        #pragma unroll
        for (int half = 0; half < 2; half++) {
            const int row = bm + wm * (BMT / 2) + mt * 16 + half * 8 + g;
            #pragma unroll
            for (int nt = 0; nt < 8; nt++) {
                const int col = bn + wn * 64 + nt * 8 + tcol;
                float v0 = c[mt][nt][half * 2 + 0];
                float v1 = c[mt][nt][half * 2 + 1];
                if (bias) { v0 += __ldg(&bias[col]); v1 += __ldg(&bias[col + 1]); }
                if (ACT == 2) { v0 = softplus_f(v0); v1 = softplus_f(v1); }
                if (SPLIT2) {
                    __half h0, l0, h1, l1;
                    split_f16(v0, h0, l0);
                    split_f16(v1, h1, l1);
                    __half* rp = Cs + (size_t)row * 2 * N;
                    *(__half2*)(rp + col)     = __halves2half2(h0, h1);
                    *(__half2*)(rp + N + col) = __halves2half2(l0, l1);
                } else {
                    *(float2*)(Cout + (size_t)row * N + col) = make_float2(v0, v1);
                }
            }
        }
    }
}

// ======================================================================
// SMALL GEMM: BM=64, BN=128 tile, 256 threads, 3-stage (S=2 supported).
// ======================================================================
template<int BM_, bool SPLITK, int ACT, bool SPLIT2>
__global__ void __launch_bounds__(256, 2) tgsm_k(
    const __half* __restrict__ A,
    const __half* __restrict__ B,
    const float* __restrict__ bias,
    float* __restrict__ Cout,
    __half* __restrict__ Cs,
    int M, int Nout, int K2, int kchunk)
{
    constexpr int NWM = BM_ / 32;
    constexpr int NWN = 8 / NWM;
    constexpr int WNW = 128 / NWN;
    constexpr int NT  = WNW / 8;
    constexpr int STAGE = (BM_ + 128) * 128;
    extern __shared__ char dsm[];
    const uint32_t base = (smem_u32(dsm) + 1023u) & ~1023u;

    const int tid  = threadIdx.x;
    const int wid  = tid >> 5;
    const int lane = tid & 31;
    const int bm   = blockIdx.y * BM_;
    const int bn   = blockIdx.x * 128;

    const int kbeg = SPLITK ? blockIdx.z * kchunk : 0;
    const int S    = (SPLITK ? kchunk : K2) / 64;

    const int wm = wid % NWM;
    const int wn = wid / NWM;

    const uint32_t aRow  = (uint32_t)(wm * 32 + (lane & 15));
    const uint32_t aKsel = (uint32_t)(((lane >> 4) & 1) * 16);
    const uint32_t bRow  = (uint32_t)(wn * WNW + (lane & 7) + ((lane >> 4) & 1) * 8);
    const uint32_t bKsel = (uint32_t)(((lane >> 3) & 1) * 16);

    float c[2][NT][4];
    #pragma unroll
    for (int mt = 0; mt < 2; mt++)
        #pragma unroll
        for (int nt = 0; nt < NT; nt++)
            #pragma unroll
            for (int r = 0; r < 4; r++) c[mt][nt][r] = 0.0f;

    auto load_stage = [&](uint32_t abase, int k0) {
        const uint32_t bbase = abase + BM_ * 128;
        #pragma unroll
        for (int i = 0; i < (BM_ * 8) / 256; i++) {
            int cc = tid + i * 256;
            int row = cc >> 3, ch = cc & 7;
            uint32_t dst = abase + SWZ((uint32_t)(row * 128 + ch * 16));
            CP16(dst, A + (size_t)(bm + row) * K2 + k0 + ch * 8);
        }
        #pragma unroll
        for (int i = 0; i < 4; i++) {
            int cc = tid + i * 256;
            int row = cc >> 3, ch = cc & 7;
            uint32_t dst = bbase + SWZ((uint32_t)(row * 128 + ch * 16));
            CP16(dst, B + (size_t)(bn + row) * K2 + k0 + ch * 8);
        }
        CP_COMMIT();
    };

    load_stage(base,         kbeg);
    load_stage(base + STAGE, kbeg + 64);
    if (S > 2) load_stage(base + 2 * STAGE, kbeg + 128);

    for (int s = 0; s < S; s++) {
        if (s + 3 <= S)      { CP_WAIT(2); }
        else if (s + 2 == S) { CP_WAIT(1); }
        else                 { CP_WAIT(0); }
        __syncthreads();

        const int buf = s % 3;
        const uint32_t ab = base + (uint32_t)buf * STAGE;
        const uint32_t bb = ab + BM_ * 128;

        #pragma unroll
        for (int ks = 0; ks < 4; ks++) {
            uint32_t a[2][4], b[NT / 2][4];
            #pragma unroll
            for (int mt = 0; mt < 2; mt++) {
                uint32_t addr = ab + SWZ((aRow + mt * 16) * 128 + (uint32_t)ks * 32 + aKsel);
                LDSM_X4(a[mt][0], a[mt][1], a[mt][2], a[mt][3], addr);
            }
            #pragma unroll
            for (int ntp = 0; ntp < NT / 2; ntp++) {
                uint32_t addr = bb + SWZ((bRow + ntp * 16) * 128 + (uint32_t)ks * 32 + bKsel);
                LDSM_X4(b[ntp][0], b[ntp][1], b[ntp][2], b[ntp][3], addr);
            }
            #pragma unroll
            for (int mt = 0; mt < 2; mt++)
                #pragma unroll
                for (int nt = 0; nt < NT; nt++) {
                    const int ntp = nt >> 1, hi = nt & 1;
                    MMA_F16(c[mt][nt][0], c[mt][nt][1], c[mt][nt][2], c[mt][nt][3],
                            a[mt][0], a[mt][1], a[mt][2], a[mt][3],
                            b[ntp][hi * 2], b[ntp][hi * 2 + 1]);
                }
        }

        __syncthreads();
        if (s + 3 < S)
            load_stage(base + (uint32_t)buf * STAGE, kbeg + (s + 3) * 64);
    }

    const int g    = lane >> 2;
    const int tcol = (lane & 3) * 2;
    #pragma unroll
    for (int mt = 0; mt < 2; mt++) {
        #pragma unroll
        for (int half = 0; half < 2; half++) {
            const int row = bm + wm * 32 + mt * 16 + half * 8 + g;
            #pragma unroll
            for (int nt = 0; nt < NT; nt++) {
                const int col = bn + wn * WNW + nt * 8 + tcol;
                if (col >= Nout) continue;
                float v0 = c[mt][nt][half * 2 + 0];
                float v1 = c[mt][nt][half * 2 + 1];
                if (SPLITK) {
                    atomicAdd(&Cout[(size_t)row * Nout + col], v0);
                    if (col + 1 < Nout)
                        atomicAdd(&Cout[(size_t)row * Nout + col + 1], v1);
                } else {
                    if (bias) { v0 += __ldg(&bias[col]); v1 += __ldg(&bias[col + 1]); }
                    if (ACT == 1) { v0 = fmaxf(v0, 0.0f); v1 = fmaxf(v1, 0.0f); }
                    if (SPLIT2) {
                        __half h0, l0, h1, l1;
                        split_f16(v0, h0, l0);
                        split_f16(v1, h1, l1);
                        __half* rp = Cs + (size_t)row * 2 * Nout;
                        *(__half2*)(rp + col)        = __halves2half2(h0, h1);
                        *(__half2*)(rp + Nout + col) = __halves2half2(l0, l1);
                    } else {
                        *(float2*)(Cout + (size_t)row * Nout + col) = make_float2(v0, v1);
                    }
                }
            }
        }
    }
}

// ---------------- concat + split2 ----------------
__global__ void concat_split_kernel(const float* __restrict__ sp,
                                    const float* __restrict__ te,
                                    __half* __restrict__ ax) {
    int i = blockIdx.x * 256 + threadIdx.x;
    if (i < NTOK * DMODEL) {
        int row = i >> 10, c = i & 1023;
        float v = (c < EDIM) ? sp[(size_t)row * EDIM + c]
                             : te[(size_t)row * EDIM + (c - EDIM)];
        __half hi, lo; split_f16(v, hi, lo);
        size_t b = (size_t)row * (2 * DMODEL);
        ax[b + c]          = hi;
        ax[b + DMODEL + c] = lo;
    }
}

// ---------------- batched weight transpose+dup: 6 jobs in one launch ----------------
// W(KxN) -> out(N x 2K) [Bh|Bh]; one 32x32 tile per block.
struct WtJobs {
    const float* W[6];
    __half*      out[6];
    int          K[6];
    int          N[6];
    int          off[7];   // cumulative tile offsets
};

__global__ void wt_split_all(WtJobs j) {
    __shared__ float s[32][33];
    const int b = blockIdx.x;
    int job = 0;
    #pragma unroll
    for (int q = 0; q < 5; q++) if (b >= j.off[q + 1]) job = q + 1;
    const float* W = j.W[job];
    __half* out    = j.out[job];
    const int K = j.K[job], N = j.N[job];
    const int rel = b - j.off[job];
    const int tilesN = N >> 5;
    const int n0 = (rel % tilesN) * 32;
    const int k0 = (rel / tilesN) * 32;

    const int tx = threadIdx.x, ty = threadIdx.y;
    #pragma unroll
    for (int i = 0; i < 4; i++)
        s[ty + 8 * i][tx] = W[(size_t)(k0 + ty + 8 * i) * N + n0 + tx];
    __syncthreads();
    #pragma unroll
    for (int i = 0; i < 4; i++) {
        int n = n0 + ty + 8 * i;
        float v = s[tx][ty + 8 * i];
        __half hi = __float2half_rn(v);
        size_t bo = (size_t)n * (2 * K) + k0 + tx;
        out[bo]     = hi;
        out[bo + K] = hi;
    }
}

// ---------------- dt_raw split2 ----------------
__global__ void dtraw_split_kernel(const float* __restrict__ proj,
                                   __half* __restrict__ out) {
    int i = blockIdx.x * 256 + threadIdx.x;
    if (i < NTOK * DTRANK) {
        int r = i >> 6, c = i & 63;
        float v = proj[(size_t)r * PROJW + c];
        __half hi, lo; split_f16(v, hi, lo);
        size_t b = (size_t)r * (2 * DTRANK);
        out[b + c]      = hi;
        out[b + 64 + c] = lo;
    }
}

__global__ void zero_kernel(float* __restrict__ p, int n) {
    int i = blockIdx.x * 256 + threadIdx.x;
    if (i < n) p[i] = 0.0f;
}

// ---------------- causal depthwise conv1d (K=4) + silu; writes split2 only ----------------
__global__ void conv_silu_kernel(const float* __restrict__ xz,
                                 const float* __restrict__ cw,
                                 const float* __restrict__ cb,
                                 __half* __restrict__ xc2)
{
    const int d = blockIdx.x * 256 + threadIdx.x;
    const int b = blockIdx.y;
    if (d >= DINNER) return;
    const float w0 = cw[d * 4 + 0], w1 = cw[d * 4 + 1];
    const float w2 = cw[d * 4 + 2], w3 = cw[d * 4 + 3];
    const float bias = cb[d];
    const float* src = xz + (size_t)b * TSEQ * (2 * DINNER) + d;
    float x0 = 0.f, x1 = 0.f, x2 = 0.f;
    const size_t rbase = (size_t)b * TSEQ;
    for (int t = 0; t < TSEQ; t++) {
        float x3 = src[(size_t)t * (2 * DINNER)];
        float v  = fmaf(w3, x3, fmaf(w2, x2, fmaf(w1, x1, w0 * x0))) + bias;
        float s  = silu_f(v);
        const size_t row = rbase + t;
        __half hi, lo; split_f16(s, hi, lo);
        const size_t ob = row * (2 * DINNER);
        xc2[ob + d]          = hi;
        xc2[ob + DINNER + d] = lo;
        x0 = x1; x1 = x2; x2 = x3;
    }
}

// ---------------- selective scan + skip + gate; reads xc2 (hi+lo), writes split2 y'' ----------------
__global__ void __launch_bounds__(512) scan_kernel(
    const float* __restrict__ proj,
    const float* __restrict__ dt,
    const __half* __restrict__ xc2,
    const float* __restrict__ xz,
    const float* __restrict__ A_log,
    const float* __restrict__ D_skip,
    __half* __restrict__ y2)
{
    const int b = blockIdx.y;
    const int d = blockIdx.x * 512 + threadIdx.x;

    __shared__ float sBC[TSEQ][32];
    for (int i = threadIdx.x; i < TSEQ * 32; i += 512) {
        int t = i >> 5, c = i & 31;
        sBC[t][c] = proj[((size_t)(b * TSEQ + t)) * PROJW + DTRANK + c];
    }
    __syncthreads();

    float A2[DSTATE];
    #pragma unroll
    for (int n = 0; n < DSTATE; n++)
        A2[n] = -ex2f(A_log[(size_t)d * DSTATE + n] * LOG2E) * LOG2E;
    const float Dv = D_skip[d];

    float h[DSTATE];
    #pragma unroll
    for (int n = 0; n < DSTATE; n++) h[n] = 0.0f;

    const size_t rbase = (size_t)b * TSEQ;
    for (int t = 0; t < TSEQ; t++) {
        const size_t row = rbase + t;
        const float dtv = dt[row * DINNER + d];
        const size_t xb = row * (2 * DINNER);
        const float xv  = __half2float(xc2[xb + d]) + __half2float(xc2[xb + DINNER + d]);
        const float zv  = xz[row * (2 * DINNER) + DINNER + d];
        const float dtx = dtv * xv;
        float yv = 0.0f;
        #pragma unroll
        for (int n = 0; n < DSTATE; n++) {
            const float dA = ex2f(dtv * A2[n]);
            h[n] = fmaf(dA, h[n], dtx * sBC[t][n]);
            yv   = fmaf(h[n], sBC[t][16 + n], yv);
        }
        yv = fmaf(xv, Dv, yv);
        const float val = yv * zv * rcpf(1.0f + ex2f(-LOG2E * zv));
        __half hi, lo; split_f16(val, hi, lo);
        const size_t ob = row * (2 * DINNER);
        y2[ob + d]          = hi;
        y2[ob + DINNER + d] = lo;
    }
}

// ---------------- head: out = h2 @ W3 + b3 (N=6) ----------------
__global__ void head_kernel(const float* __restrict__ h2,
                            const float* __restrict__ W3,
                            const float* __restrict__ b3,
                            float* __restrict__ out)
{
    __shared__ float sW[256 * 6];
    const int tid = threadIdx.x;
    for (int i = tid; i < 256 * 6; i += 256) sW[i] = W3[i];
    __syncthreads();

    const int warp = tid >> 5, lane = tid & 31;
    const int row  = blockIdx.x * 8 + warp;
    const float* hrow = h2 + (size_t)row * 256;

    float acc[6] = {0.f, 0.f, 0.f, 0.f, 0.f, 0.f};
    #pragma unroll
    for (int kk = 0; kk < 8; kk++) {
        const int k = kk * 32 + lane;
        const float v = hrow[k];
        #pragma unroll
        for (int j = 0; j < 6; j++) acc[j] = fmaf(v, sW[k * 6 + j], acc[j]);
    }
    #pragma unroll
    for (int j = 0; j < 6; j++) {
        #pragma unroll
        for (int o = 16; o > 0; o >>= 1)
            acc[j] += __shfl_xor_sync(0xffffffffu, acc[j], o);
    }
    if (lane == 0) {
        #pragma unroll
        for (int j = 0; j < 6; j++)
            out[(size_t)row * 6 + j] = acc[j] + b3[j];
    }
}

// ---------------- launch ----------------
extern "C" void kernel_launch(void* const* d_in, const int* in_sizes, int n_in,
                              void* d_out, int out_size)
{
    const float* spatial  = (const float*)d_in[0];
    const float* temporal = (const float*)d_in[1];
    const float* W_in     = (const float*)d_in[2];
    const float* conv_w   = (const float*)d_in[3];
    const float* conv_b   = (const float*)d_in[4];
    const float* W_x      = (const float*)d_in[5];
    const float* W_dt     = (const float*)d_in[6];
    const float* b_dt     = (const float*)d_in[7];
    const float* A_log    = (const float*)d_in[8];
    const float* D_skip   = (const float*)d_in[9];
    const float* W_out    = (const float*)d_in[10];
    const float* W1       = (const float*)d_in[11];
    const float* b1       = (const float*)d_in[12];
    const float* W2       = (const float*)d_in[13];
    const float* b2       = (const float*)d_in[14];
    const float* W3       = (const float*)d_in[15];
    const float* b3       = (const float*)d_in[16];
    float* out = (float*)d_out;

    float *pxz, *pproj, *pdt, *ph2;
    __half *pAx, *pBwin, *pAxc, *pBwx, *pAdt, *pBwdt, *pAy, *pBwout,
           *pAf, *pBw1, *pAh1, *pBw2;
    cudaGetSymbolAddress((void**)&pxz,   g_xz);
    cudaGetSymbolAddress((void**)&pproj, g_proj);
    cudaGetSymbolAddress((void**)&pdt,   g_dt);
    cudaGetSymbolAddress((void**)&ph2,   g_h2);
    cudaGetSymbolAddress((void**)&pAx,   g_Ax);
    cudaGetSymbolAddress((void**)&pBwin, g_Bwin);
    cudaGetSymbolAddress((void**)&pAxc,  g_Axc);
    cudaGetSymbolAddress((void**)&pBwx,  g_Bwx);
    cudaGetSymbolAddress((void**)&pAdt,  g_Adt);
    cudaGetSymbolAddress((void**)&pBwdt, g_Bwdt);
    cudaGetSymbolAddress((void**)&pAy,   g_Ay);
    cudaGetSymbolAddress((void**)&pBwout,g_Bwout);
    cudaGetSymbolAddress((void**)&pAf,   g_Af);
    cudaGetSymbolAddress((void**)&pBw1,  g_Bw1);
    cudaGetSymbolAddress((void**)&pAh1,  g_Ah1);
    cudaGetSymbolAddress((void**)&pBw2,  g_Bw2);

    const int SMEM_B128 = 3 * (128 + 128) * 128 + 1024;   // 99328
    const int SMEM_B64  = 3 * (64  + 128) * 128 + 1024;   // 74752
    cudaFuncSetAttribute(tgbig_k<64,  0, false>, cudaFuncAttributeMaxDynamicSharedMemorySize, SMEM_B64);
    cudaFuncSetAttribute(tgbig_k<128, 2, false>, cudaFuncAttributeMaxDynamicSharedMemorySize, SMEM_B128);
    cudaFuncSetAttribute(tgbig_k<128, 0, true>,  cudaFuncAttributeMaxDynamicSharedMemorySize, SMEM_B128);
    cudaFuncSetAttribute(tgsm_k<64, true,  0, false>, cudaFuncAttributeMaxDynamicSharedMemorySize, SMEM_B64);
    cudaFuncSetAttribute(tgsm_k<64, false, 1, true>,  cudaFuncAttributeMaxDynamicSharedMemorySize, SMEM_B64);
    cudaFuncSetAttribute(tgsm_k<64, false, 1, false>, cudaFuncAttributeMaxDynamicSharedMemorySize, SMEM_B64);

    // weight-dup job table (6 jobs, tile counts = (N/32)*(K/32))
    WtJobs wj;
    const float* Ws[6]  = { W_in, W_x, W_dt, W_out, W1, W2 };
    __half* Os[6]       = { pBwin, pBwx, pBwdt, pBwout, pBw1, pBw2 };
    const int Ks[6]     = { DMODEL, DINNER, DTRANK, DINNER, DMODEL, 512 };
    const int Ns[6]     = { 2 * DINNER, PROJW, DINNER, DMODEL, 512, 256 };
    int acc = 0;
    for (int q = 0; q < 6; q++) {
        wj.W[q] = Ws[q]; wj.out[q] = Os[q]; wj.K[q] = Ks[q]; wj.N[q] = Ns[q];
        wj.off[q] = acc;
        acc += (Ns[q] / 32) * (Ks[q] / 32);
    }
    wj.off[6] = acc;

    // 0) concat + split2
    concat_split_kernel<<<(NTOK * DMODEL + 255) / 256, 256>>>(spatial, temporal, pAx);
    // 1) all weight dups in one launch
    wt_split_all<<<acc, dim3(32, 8)>>>(wj);
    // 2) G1: xz = X @ W_in   M=4096, N=4096, K''=2048 — BM=64, 3 CTAs/SM
    tgbig_k<64, 0, false><<<dim3(4096 / 128, NTOK / 64), 128, SMEM_B64>>>(
        pAx, pBwin, nullptr, pxz, nullptr, NTOK, 4096, 2 * DMODEL);
    // 3) conv + silu (split2 only)
    conv_silu_kernel<<<dim3(DINNER / 256, BSZ), 256>>>(pxz, conv_w, conv_b, pAxc);
    // 4) zero proj
    zero_kernel<<<(NTOK * PROJW + 255) / 256, 256>>>(pproj, NTOK * PROJW);
    // 5) Gx: proj = xc @ W_x  (split-K x4, atomic fp32, Nout=96, K''=4096)
    tgsm_k<64, true, 0, false><<<dim3(1, NTOK / 64, 4), 256, SMEM_B64>>>(
        pAxc, pBwx, nullptr, pproj, nullptr, NTOK, PROJW, 2 * DINNER, 2 * DINNER / 4);
    // 6) dt_raw split2
    dtraw_split_kernel<<<(NTOK * DTRANK + 255) / 256, 256>>>(pproj, pAdt);
    // 7) G3: dt = softplus(dt_raw @ W_dt + b_dt)  N=2048, K''=128 (S=2)
    tgbig_k<128, 2, false><<<dim3(DINNER / 128, NTOK / 128), 128, SMEM_B128>>>(
        pAdt, pBwdt, b_dt, pdt, nullptr, NTOK, DINNER, 2 * DTRANK);
    // 8) scan -> y'' split2
    scan_kernel<<<dim3(DINNER / 512, BSZ), 512>>>(pproj, pdt, pAxc, pxz, A_log, D_skip, pAy);
    // 9) G4: f'' = split2(y @ W_out)  N=1024, K''=4096
    tgbig_k<128, 0, true><<<dim3(DMODEL / 128, NTOK / 128), 128, SMEM_B128>>>(
        pAy, pBwout, nullptr, nullptr, pAf, NTOK, DMODEL, 2 * DINNER);
    // 10) G5: h1'' = split2(relu(f @ W1 + b1))  N=512, K''=2048  (BM=64)
    tgsm_k<64, false, 1, true><<<dim3(512 / 128, NTOK / 64), 256, SMEM_B64>>>(
        pAf, pBw1, b1, nullptr, pAh1, NTOK, 512, 2 * DMODEL, 0);
    // 11) G6: h2 = relu(h1 @ W2 + b2)  N=256, K''=1024  (BM=64)
    tgsm_k<64, false, 1, false><<<dim3(256 / 128, NTOK / 64), 256, SMEM_B64>>>(
        pAh1, pBw2, b2, ph2, nullptr, NTOK, 256, 2 * 512, 0);
    // 12) head
    head_kernel<<<NTOK / 8, 256>>>(ph2, W3, b3, out);
}

// round 12
// speedup vs baseline: 1.4095x; 1.0362x over previous
#include <cuda_runtime.h>
#include <cuda_fp16.h>
#include <math.h>
#include <stdint.h>

// ---------------- problem dims ----------------
#define BSZ     64
#define TSEQ    64
#define EDIM    512
#define DMODEL  1024
#define DINNER  2048
#define NTOK    (BSZ*TSEQ)       // 4096
#define DSTATE  16
#define DTRANK  64
#define PROJW   96

// ---------------- scratch (device globals, zero-initialized at load) ----------------
__device__ float g_z   [NTOK * DINNER];     // gate z (fp32)
__device__ float g_proj[NTOK * PROJW];
__device__ float g_dt  [NTOK * DINNER];
__device__ float g_h2  [NTOK * 256];
// fp16 split-2: A'' = [Ah|Al] (Mx2K), B'' = [Bh|Bh] (Nx2K).
__device__ __half g_Ax   [NTOK * 2 * DMODEL];
__device__ __half g_Bwin [2 * DINNER * 2 * DMODEL];
__device__ __half g_Axc  [NTOK * 2 * DINNER];
__device__ __half g_Bwx  [128 * 2 * DINNER];          // rows 96..127 stay 0
__device__ __half g_Adt  [NTOK * 2 * DTRANK];
__device__ __half g_Bwdt [DINNER * 2 * DTRANK];
__device__ __half g_Ay   [NTOK * 2 * DINNER];
__device__ __half g_Bwout[DMODEL * 2 * DINNER];
__device__ __half g_Af   [NTOK * 2 * DMODEL];
__device__ __half g_Bw1  [512 * 2 * DMODEL];
__device__ __half g_Ah1  [NTOK * 2 * 512];
__device__ __half g_Bw2  [256 * 2 * 512];

// ---------------- MUFU transcendentals ----------------
__device__ __forceinline__ float ex2f(float x) { float y; asm("ex2.approx.f32 %0, %1;" : "=f"(y) : "f"(x)); return y; }
__device__ __forceinline__ float lg2f(float x) { float y; asm("lg2.approx.f32 %0, %1;" : "=f"(y) : "f"(x)); return y; }
__device__ __forceinline__ float rcpf(float x) { float y; asm("rcp.approx.f32 %0, %1;" : "=f"(y) : "f"(x)); return y; }
#define LOG2E 1.4426950408889634f
#define LN2   0.6931471805599453f

__device__ __forceinline__ float softplus_f(float x) {
    if (x > 15.0f) return x;
    return LN2 * lg2f(1.0f + ex2f(LOG2E * x));
}
__device__ __forceinline__ float silu_f(float x) {
    return x * rcpf(1.0f + ex2f(-LOG2E * x));
}

// ---------------- PTX helpers (portable sm_80+ subset) ----------------
__device__ __forceinline__ uint32_t smem_u32(const void* p) {
    uint32_t a;
    asm("{ .reg .u64 t; cvta.to.shared.u64 t, %1; cvt.u32.u64 %0, t; }" : "=r"(a) : "l"(p));
    return a;
}
#define SWZ(off) ((off) ^ (((off) >> 3) & 0x70))

#define CP16(dst, src) asm volatile("cp.async.cg.shared.global [%0], [%1], 16;\n" :: "r"(dst), "l"(src) : "memory")
#define CP_COMMIT()    asm volatile("cp.async.commit_group;\n" ::: "memory")
#define CP_WAIT(n)     asm volatile("cp.async.wait_group %0;\n" :: "n"(n) : "memory")

#define LDSM_X4(r0, r1, r2, r3, addr) \
    asm volatile("ldmatrix.sync.aligned.m8n8.x4.shared.b16 {%0,%1,%2,%3}, [%4];" \
        : "=r"(r0), "=r"(r1), "=r"(r2), "=r"(r3) : "r"(addr))

#define MMA_F16(c0, c1, c2, c3, a0, a1, a2, a3, b0, b1) \
    asm volatile("mma.sync.aligned.m16n8k16.row.col.f32.f16.f16.f32 " \
        "{%0,%1,%2,%3}, {%4,%5,%6,%7}, {%8,%9}, {%0,%1,%2,%3};" \
        : "+f"(c0), "+f"(c1), "+f"(c2), "+f"(c3) \
        : "r"(a0), "r"(a1), "r"(a2), "r"(a3), "r"(b0), "r"(b1))

__device__ __forceinline__ void split_f16(float v, __half& hi, __half& lo) {
    hi = __float2half_rn(v);
    lo = __float2half_rn(v - __half2float(hi));
}

// ======================================================================
// BIG GEMM: BMT in {64,128}, BN=128, BK=64, 128 threads (4 warps, 2m x 2n),
// warp tile (BMT/2)x64, 3-stage cp.async (S=2 supported).
// MODE 0: fp32 out (+bias/act). MODE 1: split2 fp16 [hi|lo] out.
// MODE 2 (BMT=64 only, G1 conv-fuse): xi tiles (bn<DINNER) -> causal
//   depthwise conv(K=4)+silu+split2 into Cs (tile = one batch's full T=64);
//   z tiles (bn>=DINNER) -> fp32 into Cout (compact DINNER-stride).
// ======================================================================
template<int BMT, int ACT, int MODE>
__global__ void __launch_bounds__(128, (BMT == 64) ? 3 : 2) tgbig_k(
    const __half* __restrict__ A,
    const __half* __restrict__ B,
    const float* __restrict__ bias,
    float* __restrict__ Cout,
    __half* __restrict__ Cs,
    int M, int N, int K2,
    const float* __restrict__ cw, const float* __restrict__ cb)
{
    constexpr int MT    = BMT / 32;
    constexpr int STAGE = (BMT + 128) * 128;
    extern __shared__ char dsm[];
    const uint32_t base = (smem_u32(dsm) + 1023u) & ~1023u;
    const uint32_t pad  = base - smem_u32(dsm);

    const int tid  = threadIdx.x;
    const int wid  = tid >> 5;
    const int lane = tid & 31;
    const int bm   = blockIdx.y * BMT;
    const int bn   = blockIdx.x * 128;

    const int wm = wid & 1;
    const int wn = wid >> 1;

    const uint32_t aRow  = (uint32_t)(wm * (BMT / 2) + (lane & 15));
    const uint32_t aKsel = (uint32_t)(((lane >> 4) & 1) * 16);
    const uint32_t bRow  = (uint32_t)(wn * 64 + (lane & 7) + ((lane >> 4) & 1) * 8);
    const uint32_t bKsel = (uint32_t)(((lane >> 3) & 1) * 16);

    float c[MT][8][4];
    #pragma unroll
    for (int mt = 0; mt < MT; mt++)
        #pragma unroll
        for (int nt = 0; nt < 8; nt++)
            #pragma unroll
            for (int r = 0; r < 4; r++) c[mt][nt][r] = 0.0f;

    const int S = K2 / 64;            // S >= 2

    auto load_stage = [&](uint32_t abase, int k0) {
        const uint32_t bbase = abase + BMT * 128;
        #pragma unroll
        for (int i = 0; i < (BMT * 8) / 128; i++) {
            int cc = tid + i * 128;
            int row = cc >> 3, ch = cc & 7;
            uint32_t dst = abase + SWZ((uint32_t)(row * 128 + ch * 16));
            CP16(dst, A + (size_t)(bm + row) * K2 + k0 + ch * 8);
        }
        #pragma unroll
        for (int i = 0; i < 8; i++) {
            int cc = tid + i * 128;
            int row = cc >> 3, ch = cc & 7;
            uint32_t dst = bbase + SWZ((uint32_t)(row * 128 + ch * 16));
            CP16(dst, B + (size_t)(bn + row) * K2 + k0 + ch * 8);
        }
        CP_COMMIT();
    };

    load_stage(base,         0);
    load_stage(base + STAGE, 64);
    if (S > 2) load_stage(base + 2 * STAGE, 128);

    for (int s = 0; s < S; s++) {
        if (s + 3 <= S)      { CP_WAIT(2); }
        else if (s + 2 == S) { CP_WAIT(1); }
        else                 { CP_WAIT(0); }
        __syncthreads();

        const int buf = s % 3;
        const uint32_t ab = base + (uint32_t)buf * STAGE;
        const uint32_t bb = ab + BMT * 128;

        #pragma unroll
        for (int ks = 0; ks < 4; ks++) {
            uint32_t a[MT][4];
            #pragma unroll
            for (int mt = 0; mt < MT; mt++) {
                uint32_t addr = ab + SWZ((aRow + mt * 16) * 128 + (uint32_t)ks * 32 + aKsel);
                LDSM_X4(a[mt][0], a[mt][1], a[mt][2], a[mt][3], addr);
            }
            #pragma unroll
            for (int ntp = 0; ntp < 4; ntp++) {
                uint32_t b0, b1, b2, b3;
                uint32_t addr = bb + SWZ((bRow + ntp * 16) * 128 + (uint32_t)ks * 32 + bKsel);
                LDSM_X4(b0, b1, b2, b3, addr);
                #pragma unroll
                for (int mt = 0; mt < MT; mt++) {
                    MMA_F16(c[mt][2 * ntp][0], c[mt][2 * ntp][1],
                            c[mt][2 * ntp][2], c[mt][2 * ntp][3],
                            a[mt][0], a[mt][1], a[mt][2], a[mt][3], b0, b1);
                    MMA_F16(c[mt][2 * ntp + 1][0], c[mt][2 * ntp + 1][1],
                            c[mt][2 * ntp + 1][2], c[mt][2 * ntp + 1][3],
                            a[mt][0], a[mt][1], a[mt][2], a[mt][3], b2, b3);
                }
            }
        }

        __syncthreads();
        if (s + 3 < S)
            load_stage(base + (uint32_t)buf * STAGE, (s + 3) * 64);
    }

    // epilogue
    const int g    = lane >> 2;
    const int tcol = (lane & 3) * 2;

    if (MODE == 2) {
        const bool is_xi = (bn < DINNER);
        if (is_xi) {
            // stage accumulators to smem as [t(64)][ch(128)] fp32
            float* sc = (float*)(dsm + pad);
            #pragma unroll
            for (int mt = 0; mt < MT; mt++)
                #pragma unroll
                for (int half = 0; half < 2; half++) {
                    const int rl = wm * (BMT / 2) + mt * 16 + half * 8 + g;
                    #pragma unroll
                    for (int nt = 0; nt < 8; nt++) {
                        const int cl = wn * 64 + nt * 8 + tcol;
                        *(float2*)&sc[rl * 128 + cl] =
                            make_float2(c[mt][nt][half * 2], c[mt][nt][half * 2 + 1]);
                    }
                }
            __syncthreads();
            // per-channel causal conv + silu + split2 (tile = one full batch)
            const int d  = bn + tid;           // 128 threads, one channel each
            const float w0 = cw[d * 4 + 0], w1 = cw[d * 4 + 1];
            const float w2 = cw[d * 4 + 2], w3 = cw[d * 4 + 3];
            const float cbias = cb[d];
            float x0 = 0.f, x1 = 0.f, x2 = 0.f;
            for (int t = 0; t < TSEQ; t++) {
                const float x3 = sc[t * 128 + tid];
                const float v  = fmaf(w3, x3, fmaf(w2, x2, fmaf(w1, x1, w0 * x0))) + cbias;
                const float sv = silu_f(v);
                __half hi, lo; split_f16(sv, hi, lo);
                const size_t ob = (size_t)(bm + t) * (2 * DINNER);
                Cs[ob + d]          = hi;
                Cs[ob + DINNER + d] = lo;
                x0 = x1; x1 = x2; x2 = x3;
            }
        } else {
            // z tile -> compact fp32 (ldc = DINNER)
            const int zc = bn - DINNER;
            #pragma unroll
            for (int mt = 0; mt < MT; mt++)
                #pragma unroll
                for (int half = 0; half < 2; half++) {
                    const int row = bm + wm * (BMT / 2) + mt * 16 + half * 8 + g;
                    #pragma unroll
                    for (int nt = 0; nt < 8; nt++) {
                        const int col = zc + wn * 64 + nt * 8 + tcol;
                        *(float2*)(Cout + (size_t)row * DINNER + col) =
                            make_float2(c[mt][nt][half * 2], c[mt][nt][half * 2 + 1]);
                    }
                }
        }
        return;
    }

    #pragma unroll
    for (int mt = 0; mt < MT; mt++) {
        #pragma unroll
        for (int half = 0; half < 2; half++) {
            const int row = bm + wm * (BMT / 2) + mt * 16 + half * 8 + g;
            #pragma unroll
            for (int nt = 0; nt < 8; nt++) {
                const int col = bn + wn * 64 + nt * 8 + tcol;
                float v0 = c[mt][nt][half * 2 + 0];
                float v1 = c[mt][nt][half * 2 + 1];
                if (bias) { v0 += __ldg(&bias[col]); v1 += __ldg(&bias[col + 1]); }
                if (ACT == 2) { v0 = softplus_f(v0); v1 = softplus_f(v1); }
                if (MODE == 1) {
                    __half h0, l0, h1, l1;
                    split_f16(v0, h0, l0);
                    split_f16(v1, h1, l1);
                    __half* rp = Cs + (size_t)row * 2 * N;
                    *(__half2*)(rp + col)     = __halves2half2(h0, h1);
                    *(__half2*)(rp + N + col) = __halves2half2(l0, l1);
                } else {
                    *(float2*)(Cout + (size_t)row * N + col) = make_float2(v0, v1);
                }
            }
        }
    }
}

// ======================================================================
// SMALL GEMM: BM=64, BN=128 tile, 256 threads, 3-stage (S=2 supported).
// ======================================================================
template<int BM_, bool SPLITK, int ACT, bool SPLIT2>
__global__ void __launch_bounds__(256, 2) tgsm_k(
    const __half* __restrict__ A,
    const __half* __restrict__ B,
    const float* __restrict__ bias,
    float* __restrict__ Cout,
    __half* __restrict__ Cs,
    int M, int Nout, int K2, int kchunk)
{
    constexpr int NWM = BM_ / 32;
    constexpr int NWN = 8 / NWM;
    constexpr int WNW = 128 / NWN;
    constexpr int NT  = WNW / 8;
    constexpr int STAGE = (BM_ + 128) * 128;
    extern __shared__ char dsm[];
    const uint32_t base = (smem_u32(dsm) + 1023u) & ~1023u;

    const int tid  = threadIdx.x;
    const int wid  = tid >> 5;
    const int lane = tid & 31;
    const int bm   = blockIdx.y * BM_;
    const int bn   = blockIdx.x * 128;

    const int kbeg = SPLITK ? blockIdx.z * kchunk : 0;
    const int S    = (SPLITK ? kchunk : K2) / 64;

    const int wm = wid % NWM;
    const int wn = wid / NWM;

    const uint32_t aRow  = (uint32_t)(wm * 32 + (lane & 15));
    const uint32_t aKsel = (uint32_t)(((lane >> 4) & 1) * 16);
    const uint32_t bRow  = (uint32_t)(wn * WNW + (lane & 7) + ((lane >> 4) & 1) * 8);
    const uint32_t bKsel = (uint32_t)(((lane >> 3) & 1) * 16);

    float c[2][NT][4];
    #pragma unroll
    for (int mt = 0; mt < 2; mt++)
        #pragma unroll
        for (int nt = 0; nt < NT; nt++)
            #pragma unroll
            for (int r = 0; r < 4; r++) c[mt][nt][r] = 0.0f;

    auto load_stage = [&](uint32_t abase, int k0) {
        const uint32_t bbase = abase + BM_ * 128;
        #pragma unroll
        for (int i = 0; i < (BM_ * 8) / 256; i++) {
            int cc = tid + i * 256;
            int row = cc >> 3, ch = cc & 7;
            uint32_t dst = abase + SWZ((uint32_t)(row * 128 + ch * 16));
            CP16(dst, A + (size_t)(bm + row) * K2 + k0 + ch * 8);
        }
        #pragma unroll
        for (int i = 0; i < 4; i++) {
            int cc = tid + i * 256;
            int row = cc >> 3, ch = cc & 7;
            uint32_t dst = bbase + SWZ((uint32_t)(row * 128 + ch * 16));
            CP16(dst, B + (size_t)(bn + row) * K2 + k0 + ch * 8);
        }
        CP_COMMIT();
    };

    load_stage(base,         kbeg);
    load_stage(base + STAGE, kbeg + 64);
    if (S > 2) load_stage(base + 2 * STAGE, kbeg + 128);

    for (int s = 0; s < S; s++) {
        if (s + 3 <= S)      { CP_WAIT(2); }
        else if (s + 2 == S) { CP_WAIT(1); }
        else                 { CP_WAIT(0); }
        __syncthreads();

        const int buf = s % 3;
        const uint32_t ab = base + (uint32_t)buf * STAGE;
        const uint32_t bb = ab + BM_ * 128;

        #pragma unroll
        for (int ks = 0; ks < 4; ks++) {
            uint32_t a[2][4], b[NT / 2][4];
            #pragma unroll
            for (int mt = 0; mt < 2; mt++) {
                uint32_t addr = ab + SWZ((aRow + mt * 16) * 128 + (uint32_t)ks * 32 + aKsel);
                LDSM_X4(a[mt][0], a[mt][1], a[mt][2], a[mt][3], addr);
            }
            #pragma unroll
            for (int ntp = 0; ntp < NT / 2; ntp++) {
                uint32_t addr = bb + SWZ((bRow + ntp * 16) * 128 + (uint32_t)ks * 32 + bKsel);
                LDSM_X4(b[ntp][0], b[ntp][1], b[ntp][2], b[ntp][3], addr);
            }
            #pragma unroll
            for (int mt = 0; mt < 2; mt++)
                #pragma unroll
                for (int nt = 0; nt < NT; nt++) {
                    const int ntp = nt >> 1, hi = nt & 1;
                    MMA_F16(c[mt][nt][0], c[mt][nt][1], c[mt][nt][2], c[mt][nt][3],
                            a[mt][0], a[mt][1], a[mt][2], a[mt][3],
                            b[ntp][hi * 2], b[ntp][hi * 2 + 1]);
                }
        }

        __syncthreads();
        if (s + 3 < S)
            load_stage(base + (uint32_t)buf * STAGE, kbeg + (s + 3) * 64);
    }

    const int g    = lane >> 2;
    const int tcol = (lane & 3) * 2;
    #pragma unroll
    for (int mt = 0; mt < 2; mt++) {
        #pragma unroll
        for (int half = 0; half < 2; half++) {
            const int row = bm + wm * 32 + mt * 16 + half * 8 + g;
            #pragma unroll
            for (int nt = 0; nt < NT; nt++) {
                const int col = bn + wn * WNW + nt * 8 + tcol;
                if (col >= Nout) continue;
                float v0 = c[mt][nt][half * 2 + 0];
                float v1 = c[mt][nt][half * 2 + 1];
                if (SPLITK) {
                    atomicAdd(&Cout[(size_t)row * Nout + col], v0);
                    if (col + 1 < Nout)
                        atomicAdd(&Cout[(size_t)row * Nout + col + 1], v1);
                } else {
                    if (bias) { v0 += __ldg(&bias[col]); v1 += __ldg(&bias[col + 1]); }
                    if (ACT == 1) { v0 = fmaxf(v0, 0.0f); v1 = fmaxf(v1, 0.0f); }
                    if (SPLIT2) {
                        __half h0, l0, h1, l1;
                        split_f16(v0, h0, l0);
                        split_f16(v1, h1, l1);
                        __half* rp = Cs + (size_t)row * 2 * Nout;
                        *(__half2*)(rp + col)        = __halves2half2(h0, h1);
                        *(__half2*)(rp + Nout + col) = __halves2half2(l0, l1);
                    } else {
                        *(float2*)(Cout + (size_t)row * Nout + col) = make_float2(v0, v1);
                    }
                }
            }
        }
    }
}

// ---------------- concat + split2 ----------------
__global__ void concat_split_kernel(const float* __restrict__ sp,
                                    const float* __restrict__ te,
                                    __half* __restrict__ ax) {
    int i = blockIdx.x * 256 + threadIdx.x;
    if (i < NTOK * DMODEL) {
        int row = i >> 10, c = i & 1023;
        float v = (c < EDIM) ? sp[(size_t)row * EDIM + c]
                             : te[(size_t)row * EDIM + (c - EDIM)];
        __half hi, lo; split_f16(v, hi, lo);
        size_t b = (size_t)row * (2 * DMODEL);
        ax[b + c]          = hi;
        ax[b + DMODEL + c] = lo;
    }
}

// ---------------- batched weight transpose+dup: 6 jobs in one launch ----------------
struct WtJobs {
    const float* W[6];
    __half*      out[6];
    int          K[6];
    int          N[6];
    int          off[7];
};

__global__ void wt_split_all(WtJobs j) {
    __shared__ float s[32][33];
    const int b = blockIdx.x;
    int job = 0;
    #pragma unroll
    for (int q = 0; q < 5; q++) if (b >= j.off[q + 1]) job = q + 1;
    const float* W = j.W[job];
    __half* out    = j.out[job];
    const int K = j.K[job], N = j.N[job];
    const int rel = b - j.off[job];
    const int tilesN = N >> 5;
    const int n0 = (rel % tilesN) * 32;
    const int k0 = (rel / tilesN) * 32;

    const int tx = threadIdx.x, ty = threadIdx.y;
    #pragma unroll
    for (int i = 0; i < 4; i++)
        s[ty + 8 * i][tx] = W[(size_t)(k0 + ty + 8 * i) * N + n0 + tx];
    __syncthreads();
    #pragma unroll
    for (int i = 0; i < 4; i++) {
        int n = n0 + ty + 8 * i;
        float v = s[tx][ty + 8 * i];
        __half hi = __float2half_rn(v);
        size_t bo = (size_t)n * (2 * K) + k0 + tx;
        out[bo]     = hi;
        out[bo + K] = hi;
    }
}

// ---------------- dt_raw split2 ----------------
__global__ void dtraw_split_kernel(const float* __restrict__ proj,
                                   __half* __restrict__ out) {
    int i = blockIdx.x * 256 + threadIdx.x;
    if (i < NTOK * DTRANK) {
        int r = i >> 6, c = i & 63;
        float v = proj[(size_t)r * PROJW + c];
        __half hi, lo; split_f16(v, hi, lo);
        size_t b = (size_t)r * (2 * DTRANK);
        out[b + c]      = hi;
        out[b + 64 + c] = lo;
    }
}

__global__ void zero_kernel(float* __restrict__ p, int n) {
    int i = blockIdx.x * 256 + threadIdx.x;
    if (i < n) p[i] = 0.0f;
}

// ---------------- selective scan + skip + gate; reads xc2 (hi+lo) + z; writes split2 y'' ----------------
__global__ void __launch_bounds__(512) scan_kernel(
    const float* __restrict__ proj,
    const float* __restrict__ dt,
    const __half* __restrict__ xc2,
    const float* __restrict__ z,
    const float* __restrict__ A_log,
    const float* __restrict__ D_skip,
    __half* __restrict__ y2)
{
    const int b = blockIdx.y;
    const int d = blockIdx.x * 512 + threadIdx.x;

    __shared__ float sBC[TSEQ][32];
    for (int i = threadIdx.x; i < TSEQ * 32; i += 512) {
        int t = i >> 5, c = i & 31;
        sBC[t][c] = proj[((size_t)(b * TSEQ + t)) * PROJW + DTRANK + c];
    }
    __syncthreads();

    float A2[DSTATE];
    #pragma unroll
    for (int n = 0; n < DSTATE; n++)
        A2[n] = -ex2f(A_log[(size_t)d * DSTATE + n] * LOG2E) * LOG2E;
    const float Dv = D_skip[d];

    float h[DSTATE];
    #pragma unroll
    for (int n = 0; n < DSTATE; n++) h[n] = 0.0f;

    const size_t rbase = (size_t)b * TSEQ;
    for (int t = 0; t < TSEQ; t++) {
        const size_t row = rbase + t;
        const float dtv = dt[row * DINNER + d];
        const size_t xb = row * (2 * DINNER);
        const float xv  = __half2float(xc2[xb + d]) + __half2float(xc2[xb + DINNER + d]);
        const float zv  = z[row * DINNER + d];
        const float dtx = dtv * xv;
        float yv = 0.0f;
        #pragma unroll
        for (int n = 0; n < DSTATE; n++) {
            const float dA = ex2f(dtv * A2[n]);
            h[n] = fmaf(dA, h[n], dtx * sBC[t][n]);
            yv   = fmaf(h[n], sBC[t][16 + n], yv);
        }
        yv = fmaf(xv, Dv, yv);
        const float val = yv * zv * rcpf(1.0f + ex2f(-LOG2E * zv));
        __half hi, lo; split_f16(val, hi, lo);
        const size_t ob = row * (2 * DINNER);
        y2[ob + d]          = hi;
        y2[ob + DINNER + d] = lo;
    }
}

// ---------------- head: out = h2 @ W3 + b3 (N=6) ----------------
__global__ void head_kernel(const float* __restrict__ h2,
                            const float* __restrict__ W3,
                            const float* __restrict__ b3,
                            float* __restrict__ out)
{
    __shared__ float sW[256 * 6];
    const int tid = threadIdx.x;
    for (int i = tid; i < 256 * 6; i += 256) sW[i] = W3[i];
    __syncthreads();

    const int warp = tid >> 5, lane = tid & 31;
    const int row  = blockIdx.x * 8 + warp;
    const float* hrow = h2 + (size_t)row * 256;

    float acc[6] = {0.f, 0.f, 0.f, 0.f, 0.f, 0.f};
    #pragma unroll
    for (int kk = 0; kk < 8; kk++) {
        const int k = kk * 32 + lane;
        const float v = hrow[k];
        #pragma unroll
        for (int j = 0; j < 6; j++) acc[j] = fmaf(v, sW[k * 6 + j], acc[j]);
    }
    #pragma unroll
    for (int j = 0; j < 6; j++) {
        #pragma unroll
        for (int o = 16; o > 0; o >>= 1)
            acc[j] += __shfl_xor_sync(0xffffffffu, acc[j], o);
    }
    if (lane == 0) {
        #pragma unroll
        for (int j = 0; j < 6; j++)
            out[(size_t)row * 6 + j] = acc[j] + b3[j];
    }
}

// ---------------- launch ----------------
extern "C" void kernel_launch(void* const* d_in, const int* in_sizes, int n_in,
                              void* d_out, int out_size)
{
    const float* spatial  = (const float*)d_in[0];
    const float* temporal = (const float*)d_in[1];
    const float* W_in     = (const float*)d_in[2];
    const float* conv_w   = (const float*)d_in[3];
    const float* conv_b   = (const float*)d_in[4];
    const float* W_x      = (const float*)d_in[5];
    const float* W_dt     = (const float*)d_in[6];
    const float* b_dt     = (const float*)d_in[7];
    const float* A_log    = (const float*)d_in[8];
    const float* D_skip   = (const float*)d_in[9];
    const float* W_out    = (const float*)d_in[10];
    const float* W1       = (const float*)d_in[11];
    const float* b1       = (const float*)d_in[12];
    const float* W2       = (const float*)d_in[13];
    const float* b2       = (const float*)d_in[14];
    const float* W3       = (const float*)d_in[15];
    const float* b3       = (const float*)d_in[16];
    float* out = (float*)d_out;

    float *pz, *pproj, *pdt, *ph2;
    __half *pAx, *pBwin, *pAxc, *pBwx, *pAdt, *pBwdt, *pAy, *pBwout,
           *pAf, *pBw1, *pAh1, *pBw2;
    cudaGetSymbolAddress((void**)&pz,    g_z);
    cudaGetSymbolAddress((void**)&pproj, g_proj);
    cudaGetSymbolAddress((void**)&pdt,   g_dt);
    cudaGetSymbolAddress((void**)&ph2,   g_h2);
    cudaGetSymbolAddress((void**)&pAx,   g_Ax);
    cudaGetSymbolAddress((void**)&pBwin, g_Bwin);
    cudaGetSymbolAddress((void**)&pAxc,  g_Axc);
    cudaGetSymbolAddress((void**)&pBwx,  g_Bwx);
    cudaGetSymbolAddress((void**)&pAdt,  g_Adt);
    cudaGetSymbolAddress((void**)&pBwdt, g_Bwdt);
    cudaGetSymbolAddress((void**)&pAy,   g_Ay);
    cudaGetSymbolAddress((void**)&pBwout,g_Bwout);
    cudaGetSymbolAddress((void**)&pAf,   g_Af);
    cudaGetSymbolAddress((void**)&pBw1,  g_Bw1);
    cudaGetSymbolAddress((void**)&pAh1,  g_Ah1);
    cudaGetSymbolAddress((void**)&pBw2,  g_Bw2);

    const int SMEM_B128 = 3 * (128 + 128) * 128 + 1024;   // 99328
    const int SMEM_B64  = 3 * (64  + 128) * 128 + 1024;   // 74752
    cudaFuncSetAttribute(tgbig_k<64,  0, 2>, cudaFuncAttributeMaxDynamicSharedMemorySize, SMEM_B64);
    cudaFuncSetAttribute(tgbig_k<128, 2, 0>, cudaFuncAttributeMaxDynamicSharedMemorySize, SMEM_B128);
    cudaFuncSetAttribute(tgbig_k<128, 0, 1>, cudaFuncAttributeMaxDynamicSharedMemorySize, SMEM_B128);
    cudaFuncSetAttribute(tgsm_k<64, true,  0, false>, cudaFuncAttributeMaxDynamicSharedMemorySize, SMEM_B64);
    cudaFuncSetAttribute(tgsm_k<64, false, 1, true>,  cudaFuncAttributeMaxDynamicSharedMemorySize, SMEM_B64);
    cudaFuncSetAttribute(tgsm_k<64, false, 1, false>, cudaFuncAttributeMaxDynamicSharedMemorySize, SMEM_B64);

    // weight-dup job table
    WtJobs wj;
    const float* Ws[6]  = { W_in, W_x, W_dt, W_out, W1, W2 };
    __half* Os[6]       = { pBwin, pBwx, pBwdt, pBwout, pBw1, pBw2 };
    const int Ks[6]     = { DMODEL, DINNER, DTRANK, DINNER, DMODEL, 512 };
    const int Ns[6]     = { 2 * DINNER, PROJW, DINNER, DMODEL, 512, 256 };
    int acc = 0;
    for (int q = 0; q < 6; q++) {
        wj.W[q] = Ws[q]; wj.out[q] = Os[q]; wj.K[q] = Ks[q]; wj.N[q] = Ns[q];
        wj.off[q] = acc;
        acc += (Ns[q] / 32) * (Ks[q] / 32);
    }
    wj.off[6] = acc;

    // 0) concat + split2
    concat_split_kernel<<<(NTOK * DMODEL + 255) / 256, 256>>>(spatial, temporal, pAx);
    // 1) all weight dups in one launch
    wt_split_all<<<acc, dim3(32, 8)>>>(wj);
    // 2) G1 (conv-fused): xi tiles -> conv+silu+split2 into xc2; z tiles -> g_z fp32
    tgbig_k<64, 0, 2><<<dim3(4096 / 128, NTOK / 64), 128, SMEM_B64>>>(
        pAx, pBwin, nullptr, pz, pAxc, NTOK, 4096, 2 * DMODEL, conv_w, conv_b);
    // 3) zero proj
    zero_kernel<<<(NTOK * PROJW + 255) / 256, 256>>>(pproj, NTOK * PROJW);
    // 4) Gx: proj = xc @ W_x  (split-K x4, atomic fp32, Nout=96)
    tgsm_k<64, true, 0, false><<<dim3(1, NTOK / 64, 4), 256, SMEM_B64>>>(
        pAxc, pBwx, nullptr, pproj, nullptr, NTOK, PROJW, 2 * DINNER, 2 * DINNER / 4);
    // 5) dt_raw split2
    dtraw_split_kernel<<<(NTOK * DTRANK + 255) / 256, 256>>>(pproj, pAdt);
    // 6) G3: dt = softplus(dt_raw @ W_dt + b_dt)  N=2048, K''=128 (S=2)
    tgbig_k<128, 2, 0><<<dim3(DINNER / 128, NTOK / 128), 128, SMEM_B128>>>(
        pAdt, pBwdt, b_dt, pdt, nullptr, NTOK, DINNER, 2 * DTRANK, nullptr, nullptr);
    // 7) scan -> y'' split2
    scan_kernel<<<dim3(DINNER / 512, BSZ), 512>>>(pproj, pdt, pAxc, pz, A_log, D_skip, pAy);
    // 8) G4: f'' = split2(y @ W_out)  N=1024, K''=4096
    tgbig_k<128, 0, 1><<<dim3(DMODEL / 128, NTOK / 128), 128, SMEM_B128>>>(
        pAy, pBwout, nullptr, nullptr, pAf, NTOK, DMODEL, 2 * DINNER, nullptr, nullptr);
    // 9) G5: h1'' = split2(relu(f @ W1 + b1))  N=512, K''=2048  (BM=64)
    tgsm_k<64, false, 1, true><<<dim3(512 / 128, NTOK / 64), 256, SMEM_B64>>>(
        pAf, pBw1, b1, nullptr, pAh1, NTOK, 512, 2 * DMODEL, 0);
    // 10) G6: h2 = relu(h1 @ W2 + b2)  N=256, K''=1024  (BM=64)
    tgsm_k<64, false, 1, false><<<dim3(256 / 128, NTOK / 64), 256, SMEM_B64>>>(
        pAh1, pBw2, b2, ph2, nullptr, NTOK, 256, 2 * 512, 0);
    // 11) head
    head_kernel<<<NTOK / 8, 256>>>(ph2, W3, b3, out);
}

// round 13
// speedup vs baseline: 1.4181x; 1.0060x over previous
#include <cuda_runtime.h>
#include <cuda_fp16.h>
#include <math.h>
#include <stdint.h>

// ---------------- problem dims ----------------
#define BSZ     64
#define TSEQ    64
#define EDIM    512
#define DMODEL  1024
#define DINNER  2048
#define NTOK    (BSZ*TSEQ)       // 4096
#define DSTATE  16
#define DTRANK  64
#define PROJW   96

// ---------------- scratch (device globals, zero-initialized at load) ----------------
__device__ float g_z    [NTOK * DINNER];     // gate z (fp32)
__device__ float g_proj [NTOK * PROJW];
__device__ float g_projp[4 * NTOK * PROJW];  // split-K partials (plain stores)
__device__ float g_dt   [NTOK * DINNER];
__device__ float g_h2   [NTOK * 256];
// fp16 split-2: A'' = [Ah|Al] (Mx2K), B'' = [Bh|Bh] (Nx2K).
__device__ __half g_Ax   [NTOK * 2 * DMODEL];
__device__ __half g_Bwin [2 * DINNER * 2 * DMODEL];
__device__ __half g_Axc  [NTOK * 2 * DINNER];
__device__ __half g_Bwx  [128 * 2 * DINNER];          // rows 96..127 stay 0
__device__ __half g_Adt  [NTOK * 2 * DTRANK];
__device__ __half g_Bwdt [DINNER * 2 * DTRANK];
__device__ __half g_Ay   [NTOK * 2 * DINNER];
__device__ __half g_Bwout[DMODEL * 2 * DINNER];
__device__ __half g_Af   [NTOK * 2 * DMODEL];
__device__ __half g_Bw1  [512 * 2 * DMODEL];
__device__ __half g_Ah1  [NTOK * 2 * 512];
__device__ __half g_Bw2  [256 * 2 * 512];

// ---------------- MUFU transcendentals ----------------
__device__ __forceinline__ float ex2f(float x) { float y; asm("ex2.approx.f32 %0, %1;" : "=f"(y) : "f"(x)); return y; }
__device__ __forceinline__ float lg2f(float x) { float y; asm("lg2.approx.f32 %0, %1;" : "=f"(y) : "f"(x)); return y; }
__device__ __forceinline__ float rcpf(float x) { float y; asm("rcp.approx.f32 %0, %1;" : "=f"(y) : "f"(x)); return y; }
#define LOG2E 1.4426950408889634f
#define LN2   0.6931471805599453f

__device__ __forceinline__ float softplus_f(float x) {
    if (x > 15.0f) return x;
    return LN2 * lg2f(1.0f + ex2f(LOG2E * x));
}
__device__ __forceinline__ float silu_f(float x) {
    return x * rcpf(1.0f + ex2f(-LOG2E * x));
}

// ---------------- PTX helpers (portable sm_80+ subset) ----------------
__device__ __forceinline__ uint32_t smem_u32(const void* p) {
    uint32_t a;
    asm("{ .reg .u64 t; cvta.to.shared.u64 t, %1; cvt.u32.u64 %0, t; }" : "=r"(a) : "l"(p));
    return a;
}
#define SWZ(off) ((off) ^ (((off) >> 3) & 0x70))

#define CP16(dst, src) asm volatile("cp.async.cg.shared.global [%0], [%1], 16;\n" :: "r"(dst), "l"(src) : "memory")
#define CP_COMMIT()    asm volatile("cp.async.commit_group;\n" ::: "memory")
#define CP_WAIT(n)     asm volatile("cp.async.wait_group %0;\n" :: "n"(n) : "memory")

#define LDSM_X4(r0, r1, r2, r3, addr) \
    asm volatile("ldmatrix.sync.aligned.m8n8.x4.shared.b16 {%0,%1,%2,%3}, [%4];" \
        : "=r"(r0), "=r"(r1), "=r"(r2), "=r"(r3) : "r"(addr))

#define MMA_F16(c0, c1, c2, c3, a0, a1, a2, a3, b0, b1) \
    asm volatile("mma.sync.aligned.m16n8k16.row.col.f32.f16.f16.f32 " \
        "{%0,%1,%2,%3}, {%4,%5,%6,%7}, {%8,%9}, {%0,%1,%2,%3};" \
        : "+f"(c0), "+f"(c1), "+f"(c2), "+f"(c3) \
        : "r"(a0), "r"(a1), "r"(a2), "r"(a3), "r"(b0), "r"(b1))

__device__ __forceinline__ void split_f16(float v, __half& hi, __half& lo) {
    hi = __float2half_rn(v);
    lo = __float2half_rn(v - __half2float(hi));
}

// ======================================================================
// BIG GEMM: BMT in {64,128}, BN=128, BK=64, 128 threads (4 warps, 2m x 2n),
// warp tile (BMT/2)x64, 3-stage cp.async (S=2 supported).
// MODE 0: fp32 out (+bias/act). MODE 1: split2 fp16 [hi|lo] out.
// MODE 2 (BMT=64 only, G1 conv-fuse): xi tiles (bn<DINNER) -> causal
//   depthwise conv(K=4)+silu+split2 into Cs; z tiles -> fp32 Cout (ldc=DINNER).
// ======================================================================
template<int BMT, int ACT, int MODE>
__global__ void __launch_bounds__(128, (BMT == 64) ? 3 : 2) tgbig_k(
    const __half* __restrict__ A,
    const __half* __restrict__ B,
    const float* __restrict__ bias,
    float* __restrict__ Cout,
    __half* __restrict__ Cs,
    int M, int N, int K2,
    const float* __restrict__ cw, const float* __restrict__ cb)
{
    constexpr int MT    = BMT / 32;
    constexpr int STAGE = (BMT + 128) * 128;
    extern __shared__ char dsm[];
    const uint32_t base = (smem_u32(dsm) + 1023u) & ~1023u;
    const uint32_t pad  = base - smem_u32(dsm);

    const int tid  = threadIdx.x;
    const int wid  = tid >> 5;
    const int lane = tid & 31;
    const int bm   = blockIdx.y * BMT;
    const int bn   = blockIdx.x * 128;

    const int wm = wid & 1;
    const int wn = wid >> 1;

    const uint32_t aRow  = (uint32_t)(wm * (BMT / 2) + (lane & 15));
    const uint32_t aKsel = (uint32_t)(((lane >> 4) & 1) * 16);
    const uint32_t bRow  = (uint32_t)(wn * 64 + (lane & 7) + ((lane >> 4) & 1) * 8);
    const uint32_t bKsel = (uint32_t)(((lane >> 3) & 1) * 16);

    float c[MT][8][4];
    #pragma unroll
    for (int mt = 0; mt < MT; mt++)
        #pragma unroll
        for (int nt = 0; nt < 8; nt++)
            #pragma unroll
            for (int r = 0; r < 4; r++) c[mt][nt][r] = 0.0f;

    const int S = K2 / 64;            // S >= 2

    auto load_stage = [&](uint32_t abase, int k0) {
        const uint32_t bbase = abase + BMT * 128;
        #pragma unroll
        for (int i = 0; i < (BMT * 8) / 128; i++) {
            int cc = tid + i * 128;
            int row = cc >> 3, ch = cc & 7;
            uint32_t dst = abase + SWZ((uint32_t)(row * 128 + ch * 16));
            CP16(dst, A + (size_t)(bm + row) * K2 + k0 + ch * 8);
        }
        #pragma unroll
        for (int i = 0; i < 8; i++) {
            int cc = tid + i * 128;
            int row = cc >> 3, ch = cc & 7;
            uint32_t dst = bbase + SWZ((uint32_t)(row * 128 + ch * 16));
            CP16(dst, B + (size_t)(bn + row) * K2 + k0 + ch * 8);
        }
        CP_COMMIT();
    };

    load_stage(base,         0);
    load_stage(base + STAGE, 64);
    if (S > 2) load_stage(base + 2 * STAGE, 128);

    for (int s = 0; s < S; s++) {
        if (s + 3 <= S)      { CP_WAIT(2); }
        else if (s + 2 == S) { CP_WAIT(1); }
        else                 { CP_WAIT(0); }
        __syncthreads();

        const int buf = s % 3;
        const uint32_t ab = base + (uint32_t)buf * STAGE;
        const uint32_t bb = ab + BMT * 128;

        #pragma unroll
        for (int ks = 0; ks < 4; ks++) {
            uint32_t a[MT][4];
            #pragma unroll
            for (int mt = 0; mt < MT; mt++) {
                uint32_t addr = ab + SWZ((aRow + mt * 16) * 128 + (uint32_t)ks * 32 + aKsel);
                LDSM_X4(a[mt][0], a[mt][1], a[mt][2], a[mt][3], addr);
            }
            #pragma unroll
            for (int ntp = 0; ntp < 4; ntp++) {
                uint32_t b0, b1, b2, b3;
                uint32_t addr = bb + SWZ((bRow + ntp * 16) * 128 + (uint32_t)ks * 32 + bKsel);
                LDSM_X4(b0, b1, b2, b3, addr);
                #pragma unroll
                for (int mt = 0; mt < MT; mt++) {
                    MMA_F16(c[mt][2 * ntp][0], c[mt][2 * ntp][1],
                            c[mt][2 * ntp][2], c[mt][2 * ntp][3],
                            a[mt][0], a[mt][1], a[mt][2], a[mt][3], b0, b1);
                    MMA_F16(c[mt][2 * ntp + 1][0], c[mt][2 * ntp + 1][1],
                            c[mt][2 * ntp + 1][2], c[mt][2 * ntp + 1][3],
                            a[mt][0], a[mt][1], a[mt][2], a[mt][3], b2, b3);
                }
            }
        }

        __syncthreads();
        if (s + 3 < S)
            load_stage(base + (uint32_t)buf * STAGE, (s + 3) * 64);
    }

    // epilogue
    const int g    = lane >> 2;
    const int tcol = (lane & 3) * 2;

    if (MODE == 2) {
        const bool is_xi = (bn < DINNER);
        if (is_xi) {
            float* sc = (float*)(dsm + pad);
            #pragma unroll
            for (int mt = 0; mt < MT; mt++)
                #pragma unroll
                for (int half = 0; half < 2; half++) {
                    const int rl = wm * (BMT / 2) + mt * 16 + half * 8 + g;
                    #pragma unroll
                    for (int nt = 0; nt < 8; nt++) {
                        const int cl = wn * 64 + nt * 8 + tcol;
                        *(float2*)&sc[rl * 128 + cl] =
                            make_float2(c[mt][nt][half * 2], c[mt][nt][half * 2 + 1]);
                    }
                }
            __syncthreads();
            const int d  = bn + tid;
            const float w0 = cw[d * 4 + 0], w1 = cw[d * 4 + 1];
            const float w2 = cw[d * 4 + 2], w3 = cw[d * 4 + 3];
            const float cbias = cb[d];
            float x0 = 0.f, x1 = 0.f, x2 = 0.f;
            for (int t = 0; t < TSEQ; t++) {
                const float x3 = sc[t * 128 + tid];
                const float v  = fmaf(w3, x3, fmaf(w2, x2, fmaf(w1, x1, w0 * x0))) + cbias;
                const float sv = silu_f(v);
                __half hi, lo; split_f16(sv, hi, lo);
                const size_t ob = (size_t)(bm + t) * (2 * DINNER);
                Cs[ob + d]          = hi;
                Cs[ob + DINNER + d] = lo;
                x0 = x1; x1 = x2; x2 = x3;
            }
        } else {
            const int zc = bn - DINNER;
            #pragma unroll
            for (int mt = 0; mt < MT; mt++)
                #pragma unroll
                for (int half = 0; half < 2; half++) {
                    const int row = bm + wm * (BMT / 2) + mt * 16 + half * 8 + g;
                    #pragma unroll
                    for (int nt = 0; nt < 8; nt++) {
                        const int col = zc + wn * 64 + nt * 8 + tcol;
                        *(float2*)(Cout + (size_t)row * DINNER + col) =
                            make_float2(c[mt][nt][half * 2], c[mt][nt][half * 2 + 1]);
                    }
                }
        }
        return;
    }

    #pragma unroll
    for (int mt = 0; mt < MT; mt++) {
        #pragma unroll
        for (int half = 0; half < 2; half++) {
            const int row = bm + wm * (BMT / 2) + mt * 16 + half * 8 + g;
            #pragma unroll
            for (int nt = 0; nt < 8; nt++) {
                const int col = bn + wn * 64 + nt * 8 + tcol;
                float v0 = c[mt][nt][half * 2 + 0];
                float v1 = c[mt][nt][half * 2 + 1];
                if (bias) { v0 += __ldg(&bias[col]); v1 += __ldg(&bias[col + 1]); }
                if (ACT == 2) { v0 = softplus_f(v0); v1 = softplus_f(v1); }
                if (MODE == 1) {
                    __half h0, l0, h1, l1;
                    split_f16(v0, h0, l0);
                    split_f16(v1, h1, l1);
                    __half* rp = Cs + (size_t)row * 2 * N;
                    *(__half2*)(rp + col)     = __halves2half2(h0, h1);
                    *(__half2*)(rp + N + col) = __halves2half2(l0, l1);
                } else {
                    *(float2*)(Cout + (size_t)row * N + col) = make_float2(v0, v1);
                }
            }
        }
    }
}

// ======================================================================
// SMALL GEMM: BM=64, BN=128 tile, 256 threads, 3-stage (S=2 supported).
// SPLITK: plain stores to partial buffer z-slice (Cout + z*M*Nout).
// ======================================================================
template<int BM_, bool SPLITK, int ACT, bool SPLIT2>
__global__ void __launch_bounds__(256, 2) tgsm_k(
    const __half* __restrict__ A,
    const __half* __restrict__ B,
    const float* __restrict__ bias,
    float* __restrict__ Cout,
    __half* __restrict__ Cs,
    int M, int Nout, int K2, int kchunk)
{
    constexpr int NWM = BM_ / 32;
    constexpr int NWN = 8 / NWM;
    constexpr int WNW = 128 / NWN;
    constexpr int NT  = WNW / 8;
    constexpr int STAGE = (BM_ + 128) * 128;
    extern __shared__ char dsm[];
    const uint32_t base = (smem_u32(dsm) + 1023u) & ~1023u;

    const int tid  = threadIdx.x;
    const int wid  = tid >> 5;
    const int lane = tid & 31;
    const int bm   = blockIdx.y * BM_;
    const int bn   = blockIdx.x * 128;

    const int kbeg = SPLITK ? blockIdx.z * kchunk : 0;
    const int S    = (SPLITK ? kchunk : K2) / 64;

    float* Cpart = SPLITK ? (Cout + (size_t)blockIdx.z * M * Nout) : Cout;

    const int wm = wid % NWM;
    const int wn = wid / NWM;

    const uint32_t aRow  = (uint32_t)(wm * 32 + (lane & 15));
    const uint32_t aKsel = (uint32_t)(((lane >> 4) & 1) * 16);
    const uint32_t bRow  = (uint32_t)(wn * WNW + (lane & 7) + ((lane >> 4) & 1) * 8);
    const uint32_t bKsel = (uint32_t)(((lane >> 3) & 1) * 16);

    float c[2][NT][4];
    #pragma unroll
    for (int mt = 0; mt < 2; mt++)
        #pragma unroll
        for (int nt = 0; nt < NT; nt++)
            #pragma unroll
            for (int r = 0; r < 4; r++) c[mt][nt][r] = 0.0f;

    auto load_stage = [&](uint32_t abase, int k0) {
        const uint32_t bbase = abase + BM_ * 128;
        #pragma unroll
        for (int i = 0; i < (BM_ * 8) / 256; i++) {
            int cc = tid + i * 256;
            int row = cc >> 3, ch = cc & 7;
            uint32_t dst = abase + SWZ((uint32_t)(row * 128 + ch * 16));
            CP16(dst, A + (size_t)(bm + row) * K2 + k0 + ch * 8);
        }
        #pragma unroll
        for (int i = 0; i < 4; i++) {
            int cc = tid + i * 256;
            int row = cc >> 3, ch = cc & 7;
            uint32_t dst = bbase + SWZ((uint32_t)(row * 128 + ch * 16));
            CP16(dst, B + (size_t)(bn + row) * K2 + k0 + ch * 8);
        }
        CP_COMMIT();
    };

    load_stage(base,         kbeg);
    load_stage(base + STAGE, kbeg + 64);
    if (S > 2) load_stage(base + 2 * STAGE, kbeg + 128);

    for (int s = 0; s < S; s++) {
        if (s + 3 <= S)      { CP_WAIT(2); }
        else if (s + 2 == S) { CP_WAIT(1); }
        else                 { CP_WAIT(0); }
        __syncthreads();

        const int buf = s % 3;
        const uint32_t ab = base + (uint32_t)buf * STAGE;
        const uint32_t bb = ab + BM_ * 128;

        #pragma unroll
        for (int ks = 0; ks < 4; ks++) {
            uint32_t a[2][4], b[NT / 2][4];
            #pragma unroll
            for (int mt = 0; mt < 2; mt++) {
                uint32_t addr = ab + SWZ((aRow + mt * 16) * 128 + (uint32_t)ks * 32 + aKsel);
                LDSM_X4(a[mt][0], a[mt][1], a[mt][2], a[mt][3], addr);
            }
            #pragma unroll
            for (int ntp = 0; ntp < NT / 2; ntp++) {
                uint32_t addr = bb + SWZ((bRow + ntp * 16) * 128 + (uint32_t)ks * 32 + bKsel);
                LDSM_X4(b[ntp][0], b[ntp][1], b[ntp][2], b[ntp][3], addr);
            }
            #pragma unroll
            for (int mt = 0; mt < 2; mt++)
                #pragma unroll
                for (int nt = 0; nt < NT; nt++) {
                    const int ntp = nt >> 1, hi = nt & 1;
                    MMA_F16(c[mt][nt][0], c[mt][nt][1], c[mt][nt][2], c[mt][nt][3],
                            a[mt][0], a[mt][1], a[mt][2], a[mt][3],
                            b[ntp][hi * 2], b[ntp][hi * 2 + 1]);
                }
        }

        __syncthreads();
        if (s + 3 < S)
            load_stage(base + (uint32_t)buf * STAGE, kbeg + (s + 3) * 64);
    }

    const int g    = lane >> 2;
    const int tcol = (lane & 3) * 2;
    #pragma unroll
    for (int mt = 0; mt < 2; mt++) {
        #pragma unroll
        for (int half = 0; half < 2; half++) {
            const int row = bm + wm * 32 + mt * 16 + half * 8 + g;
            #pragma unroll
            for (int nt = 0; nt < NT; nt++) {
                const int col = bn + wn * WNW + nt * 8 + tcol;
                if (col >= Nout) continue;
                float v0 = c[mt][nt][half * 2 + 0];
                float v1 = c[mt][nt][half * 2 + 1];
                if (SPLITK) {
                    if (col + 1 < Nout) {
                        *(float2*)(Cpart + (size_t)row * Nout + col) = make_float2(v0, v1);
                    } else {
                        Cpart[(size_t)row * Nout + col] = v0;
                    }
                } else {
                    if (bias) { v0 += __ldg(&bias[col]); v1 += __ldg(&bias[col + 1]); }
                    if (ACT == 1) { v0 = fmaxf(v0, 0.0f); v1 = fmaxf(v1, 0.0f); }
                    if (SPLIT2) {
                        __half h0, l0, h1, l1;
                        split_f16(v0, h0, l0);
                        split_f16(v1, h1, l1);
                        __half* rp = Cs + (size_t)row * 2 * Nout;
                        *(__half2*)(rp + col)        = __halves2half2(h0, h1);
                        *(__half2*)(rp + Nout + col) = __halves2half2(l0, l1);
                    } else {
                        *(float2*)(Cout + (size_t)row * Nout + col) = make_float2(v0, v1);
                    }
                }
            }
        }
    }
}

// ---------------- concat + split2 ----------------
__global__ void concat_split_kernel(const float* __restrict__ sp,
                                    const float* __restrict__ te,
                                    __half* __restrict__ ax) {
    int i = blockIdx.x * 256 + threadIdx.x;
    if (i < NTOK * DMODEL) {
        int row = i >> 10, c = i & 1023;
        float v = (c < EDIM) ? sp[(size_t)row * EDIM + c]
                             : te[(size_t)row * EDIM + (c - EDIM)];
        __half hi, lo; split_f16(v, hi, lo);
        size_t b = (size_t)row * (2 * DMODEL);
        ax[b + c]          = hi;
        ax[b + DMODEL + c] = lo;
    }
}

// ---------------- batched weight transpose+dup: 6 jobs in one launch ----------------
struct WtJobs {
    const float* W[6];
    __half*      out[6];
    int          K[6];
    int          N[6];
    int          off[7];
};

__global__ void wt_split_all(WtJobs j) {
    __shared__ float s[32][33];
    const int b = blockIdx.x;
    int job = 0;
    #pragma unroll
    for (int q = 0; q < 5; q++) if (b >= j.off[q + 1]) job = q + 1;
    const float* W = j.W[job];
    __half* out    = j.out[job];
    const int K = j.K[job], N = j.N[job];
    const int rel = b - j.off[job];
    const int tilesN = N >> 5;
    const int n0 = (rel % tilesN) * 32;
    const int k0 = (rel / tilesN) * 32;

    const int tx = threadIdx.x, ty = threadIdx.y;
    #pragma unroll
    for (int i = 0; i < 4; i++)
        s[ty + 8 * i][tx] = W[(size_t)(k0 + ty + 8 * i) * N + n0 + tx];
    __syncthreads();
    #pragma unroll
    for (int i = 0; i < 4; i++) {
        int n = n0 + ty + 8 * i;
        float v = s[tx][ty + 8 * i];
        __half hi = __float2half_rn(v);
        size_t bo = (size_t)n * (2 * K) + k0 + tx;
        out[bo]     = hi;
        out[bo + K] = hi;
    }
}

// ---------------- reduce partials -> proj fp32 + dt_raw split2 ----------------
__global__ void reduce_dtraw_kernel(const float* __restrict__ projp,
                                    float* __restrict__ proj,
                                    __half* __restrict__ adt) {
    int i = blockIdx.x * 256 + threadIdx.x;
    if (i < NTOK * PROJW) {
        float v = projp[i] + projp[i + NTOK * PROJW]
                + projp[i + 2 * NTOK * PROJW] + projp[i + 3 * NTOK * PROJW];
        proj[i] = v;
        int r = i / PROJW, c = i - r * PROJW;
        if (c < DTRANK) {
            __half hi, lo; split_f16(v, hi, lo);
            size_t b = (size_t)r * (2 * DTRANK);
            adt[b + c]          = hi;
            adt[b + DTRANK + c] = lo;
        }
    }
}

// ---------------- selective scan + skip + gate ----------------
__global__ void __launch_bounds__(512) scan_kernel(
    const float* __restrict__ proj,
    const float* __restrict__ dt,
    const __half* __restrict__ xc2,
    const float* __restrict__ z,
    const float* __restrict__ A_log,
    const float* __restrict__ D_skip,
    __half* __restrict__ y2)
{
    const int b = blockIdx.y;
    const int d = blockIdx.x * 512 + threadIdx.x;

    __shared__ float sBC[TSEQ][32];
    for (int i = threadIdx.x; i < TSEQ * 32; i += 512) {
        int t = i >> 5, c = i & 31;
        sBC[t][c] = proj[((size_t)(b * TSEQ + t)) * PROJW + DTRANK + c];
    }
    __syncthreads();

    float A2[DSTATE];
    #pragma unroll
    for (int n = 0; n < DSTATE; n++)
        A2[n] = -ex2f(A_log[(size_t)d * DSTATE + n] * LOG2E) * LOG2E;
    const float Dv = D_skip[d];

    float h[DSTATE];
    #pragma unroll
    for (int n = 0; n < DSTATE; n++) h[n] = 0.0f;

    const size_t rbase = (size_t)b * TSEQ;
    for (int t = 0; t < TSEQ; t++) {
        const size_t row = rbase + t;
        const float dtv = dt[row * DINNER + d];
        const size_t xb = row * (2 * DINNER);
        const float xv  = __half2float(xc2[xb + d]) + __half2float(xc2[xb + DINNER + d]);
        const float zv  = z[row * DINNER + d];
        const float dtx = dtv * xv;
        float yv = 0.0f;
        #pragma unroll
        for (int n = 0; n < DSTATE; n++) {
            const float dA = ex2f(dtv * A2[n]);
            h[n] = fmaf(dA, h[n], dtx * sBC[t][n]);
            yv   = fmaf(h[n], sBC[t][16 + n], yv);
        }
        yv = fmaf(xv, Dv, yv);
        const float val = yv * zv * rcpf(1.0f + ex2f(-LOG2E * zv));
        __half hi, lo; split_f16(val, hi, lo);
        const size_t ob = row * (2 * DINNER);
        y2[ob + d]          = hi;
        y2[ob + DINNER + d] = lo;
    }
}

// ---------------- head: out = h2 @ W3 + b3 (N=6) ----------------
__global__ void head_kernel(const float* __restrict__ h2,
                            const float* __restrict__ W3,
                            const float* __restrict__ b3,
                            float* __restrict__ out)
{
    __shared__ float sW[256 * 6];
    const int tid = threadIdx.x;
    for (int i = tid; i < 256 * 6; i += 256) sW[i] = W3[i];
    __syncthreads();

    const int warp = tid >> 5, lane = tid & 31;
    const int row  = blockIdx.x * 8 + warp;
    const float* hrow = h2 + (size_t)row * 256;

    float acc[6] = {0.f, 0.f, 0.f, 0.f, 0.f, 0.f};
    #pragma unroll
    for (int kk = 0; kk < 8; kk++) {
        const int k = kk * 32 + lane;
        const float v = hrow[k];
        #pragma unroll
        for (int j = 0; j < 6; j++) acc[j] = fmaf(v, sW[k * 6 + j], acc[j]);
    }
    #pragma unroll
    for (int j = 0; j < 6; j++) {
        #pragma unroll
        for (int o = 16; o > 0; o >>= 1)
            acc[j] += __shfl_xor_sync(0xffffffffu, acc[j], o);
    }
    if (lane == 0) {
        #pragma unroll
        for (int j = 0; j < 6; j++)
            out[(size_t)row * 6 + j] = acc[j] + b3[j];
    }
}

// ---------------- launch ----------------
extern "C" void kernel_launch(void* const* d_in, const int* in_sizes, int n_in,
                              void* d_out, int out_size)
{
    const float* spatial  = (const float*)d_in[0];
    const float* temporal = (const float*)d_in[1];
    const float* W_in     = (const float*)d_in[2];
    const float* conv_w   = (const float*)d_in[3];
    const float* conv_b   = (const float*)d_in[4];
    const float* W_x      = (const float*)d_in[5];
    const float* W_dt     = (const float*)d_in[6];
    const float* b_dt     = (const float*)d_in[7];
    const float* A_log    = (const float*)d_in[8];
    const float* D_skip   = (const float*)d_in[9];
    const float* W_out    = (const float*)d_in[10];
    const float* W1       = (const float*)d_in[11];
    const float* b1       = (const float*)d_in[12];
    const float* W2       = (const float*)d_in[13];
    const float* b2       = (const float*)d_in[14];
    const float* W3       = (const float*)d_in[15];
    const float* b3       = (const float*)d_in[16];
    float* out = (float*)d_out;

    float *pz, *pproj, *pprojp, *pdt, *ph2;
    __half *pAx, *pBwin, *pAxc, *pBwx, *pAdt, *pBwdt, *pAy, *pBwout,
           *pAf, *pBw1, *pAh1, *pBw2;
    cudaGetSymbolAddress((void**)&pz,     g_z);
    cudaGetSymbolAddress((void**)&pproj,  g_proj);
    cudaGetSymbolAddress((void**)&pprojp, g_projp);
    cudaGetSymbolAddress((void**)&pdt,    g_dt);
    cudaGetSymbolAddress((void**)&ph2,    g_h2);
    cudaGetSymbolAddress((void**)&pAx,    g_Ax);
    cudaGetSymbolAddress((void**)&pBwin,  g_Bwin);
    cudaGetSymbolAddress((void**)&pAxc,   g_Axc);
    cudaGetSymbolAddress((void**)&pBwx,   g_Bwx);
    cudaGetSymbolAddress((void**)&pAdt,   g_Adt);
    cudaGetSymbolAddress((void**)&pBwdt,  g_Bwdt);
    cudaGetSymbolAddress((void**)&pAy,    g_Ay);
    cudaGetSymbolAddress((void**)&pBwout, g_Bwout);
    cudaGetSymbolAddress((void**)&pAf,    g_Af);
    cudaGetSymbolAddress((void**)&pBw1,   g_Bw1);
    cudaGetSymbolAddress((void**)&pAh1,   g_Ah1);
    cudaGetSymbolAddress((void**)&pBw2,   g_Bw2);

    const int SMEM_B128 = 3 * (128 + 128) * 128 + 1024;   // 99328
    const int SMEM_B64  = 3 * (64  + 128) * 128 + 1024;   // 74752
    cudaFuncSetAttribute(tgbig_k<64,  0, 2>, cudaFuncAttributeMaxDynamicSharedMemorySize, SMEM_B64);
    cudaFuncSetAttribute(tgbig_k<128, 2, 0>, cudaFuncAttributeMaxDynamicSharedMemorySize, SMEM_B128);
    cudaFuncSetAttribute(tgbig_k<128, 0, 1>, cudaFuncAttributeMaxDynamicSharedMemorySize, SMEM_B128);
    cudaFuncSetAttribute(tgsm_k<64, true,  0, false>, cudaFuncAttributeMaxDynamicSharedMemorySize, SMEM_B64);
    cudaFuncSetAttribute(tgsm_k<64, false, 1, true>,  cudaFuncAttributeMaxDynamicSharedMemorySize, SMEM_B64);
    cudaFuncSetAttribute(tgsm_k<64, false, 1, false>, cudaFuncAttributeMaxDynamicSharedMemorySize, SMEM_B64);

    // weight-dup job table
    WtJobs wj;
    const float* Ws[6]  = { W_in, W_x, W_dt, W_out, W1, W2 };
    __half* Os[6]       = { pBwin, pBwx, pBwdt, pBwout, pBw1, pBw2 };
    const int Ks[6]     = { DMODEL, DINNER, DTRANK, DINNER, DMODEL, 512 };
    const int Ns[6]     = { 2 * DINNER, PROJW, DINNER, DMODEL, 512, 256 };
    int acc = 0;
    for (int q = 0; q < 6; q++) {
        wj.W[q] = Ws[q]; wj.out[q] = Os[q]; wj.K[q] = Ks[q]; wj.N[q] = Ns[q];
        wj.off[q] = acc;
        acc += (Ns[q] / 32) * (Ks[q] / 32);
    }
    wj.off[6] = acc;

    // 0) concat + split2
    concat_split_kernel<<<(NTOK * DMODEL + 255) / 256, 256>>>(spatial, temporal, pAx);
    // 1) all weight dups in one launch
    wt_split_all<<<acc, dim3(32, 8)>>>(wj);
    // 2) G1 (conv-fused): xi tiles -> conv+silu+split2 into xc2; z tiles -> g_z fp32
    tgbig_k<64, 0, 2><<<dim3(4096 / 128, NTOK / 64), 128, SMEM_B64>>>(
        pAx, pBwin, nullptr, pz, pAxc, NTOK, 4096, 2 * DMODEL, conv_w, conv_b);
    // 3) Gx: proj partials (split-K x4, plain stores, Nout=96)
    tgsm_k<64, true, 0, false><<<dim3(1, NTOK / 64, 4), 256, SMEM_B64>>>(
        pAxc, pBwx, nullptr, pprojp, nullptr, NTOK, PROJW, 2 * DINNER, 2 * DINNER / 4);
    // 4) reduce partials -> proj + dt_raw split2
    reduce_dtraw_kernel<<<(NTOK * PROJW + 255) / 256, 256>>>(pprojp, pproj, pAdt);
    // 5) G3: dt = softplus(dt_raw @ W_dt + b_dt)  N=2048, K''=128 (S=2)
    tgbig_k<128, 2, 0><<<dim3(DINNER / 128, NTOK / 128), 128, SMEM_B128>>>(
        pAdt, pBwdt, b_dt, pdt, nullptr, NTOK, DINNER, 2 * DTRANK, nullptr, nullptr);
    // 6) scan -> y'' split2
    scan_kernel<<<dim3(DINNER / 512, BSZ), 512>>>(pproj, pdt, pAxc, pz, A_log, D_skip, pAy);
    // 7) G4: f'' = split2(y @ W_out)  N=1024, K''=4096
    tgbig_k<128, 0, 1><<<dim3(DMODEL / 128, NTOK / 128), 128, SMEM_B128>>>(
        pAy, pBwout, nullptr, nullptr, pAf, NTOK, DMODEL, 2 * DINNER, nullptr, nullptr);
    // 8) G5: h1'' = split2(relu(f @ W1 + b1))  N=512, K''=2048  (BM=64)
    tgsm_k<64, false, 1, true><<<dim3(512 / 128, NTOK / 64), 256, SMEM_B64>>>(
        pAf, pBw1, b1, nullptr, pAh1, NTOK, 512, 2 * DMODEL, 0);
    // 9) G6: h2 = relu(h1 @ W2 + b2)  N=256, K''=1024  (BM=64)
    tgsm_k<64, false, 1, false><<<dim3(256 / 128, NTOK / 64), 256, SMEM_B64>>>(
        pAh1, pBw2, b2, ph2, nullptr, NTOK, 256, 2 * 512, 0);
    // 10) head
    head_kernel<<<NTOK / 8, 256>>>(ph2, W3, b3, out);
}

// round 14
// speedup vs baseline: 1.4428x; 1.0175x over previous
#include <cuda_runtime.h>
#include <cuda_fp16.h>
#include <math.h>
#include <stdint.h>

// ---------------- problem dims ----------------
#define BSZ     64
#define TSEQ    64
#define EDIM    512
#define DMODEL  1024
#define DINNER  2048
#define NTOK    (BSZ*TSEQ)       // 4096
#define DSTATE  16
#define DTRANK  64
#define PROJW   96

// ---------------- scratch (device globals, zero-initialized at load) ----------------
__device__ float g_proj [NTOK * PROJW];
__device__ float g_projp[4 * NTOK * PROJW];  // split-K partials
__device__ float g_h2   [NTOK * 256];
__device__ __half g_z2  [NTOK * DINNER];     // gate z (fp16)
__device__ __half g_dt2 [NTOK * DINNER];     // softplus dt (fp16)
// fp16 split-2: A'' = [Ah|Al] (Mx2K), B'' = [Bh|Bh] (Nx2K).
__device__ __half g_Ax   [NTOK * 2 * DMODEL];
__device__ __half g_Bwin [2 * DINNER * 2 * DMODEL];
__device__ __half g_Axc  [NTOK * 2 * DINNER];
__device__ __half g_Bwx  [128 * 2 * DINNER];          // rows 96..127 stay 0
__device__ __half g_Adt  [NTOK * 2 * DTRANK];
__device__ __half g_Bwdt [DINNER * 2 * DTRANK];
__device__ __half g_Ay   [NTOK * 2 * DINNER];
__device__ __half g_Bwout[DMODEL * 2 * DINNER];
__device__ __half g_Af   [NTOK * 2 * DMODEL];
__device__ __half g_Bw1  [512 * 2 * DMODEL];
__device__ __half g_Ah1  [NTOK * 2 * 512];
__device__ __half g_Bw2  [256 * 2 * 512];

// ---------------- MUFU transcendentals ----------------
__device__ __forceinline__ float ex2f(float x) { float y; asm("ex2.approx.f32 %0, %1;" : "=f"(y) : "f"(x)); return y; }
__device__ __forceinline__ float lg2f(float x) { float y; asm("lg2.approx.f32 %0, %1;" : "=f"(y) : "f"(x)); return y; }
__device__ __forceinline__ float rcpf(float x) { float y; asm("rcp.approx.f32 %0, %1;" : "=f"(y) : "f"(x)); return y; }
#define LOG2E 1.4426950408889634f
#define LN2   0.6931471805599453f

__device__ __forceinline__ float softplus_f(float x) {
    if (x > 15.0f) return x;
    return LN2 * lg2f(1.0f + ex2f(LOG2E * x));
}
__device__ __forceinline__ float silu_f(float x) {
    return x * rcpf(1.0f + ex2f(-LOG2E * x));
}

// ---------------- PTX helpers (portable sm_80+ subset) ----------------
__device__ __forceinline__ uint32_t smem_u32(const void* p) {
    uint32_t a;
    asm("{ .reg .u64 t; cvta.to.shared.u64 t, %1; cvt.u32.u64 %0, t; }" : "=r"(a) : "l"(p));
    return a;
}
#define SWZ(off) ((off) ^ (((off) >> 3) & 0x70))

#define CP16(dst, src) asm volatile("cp.async.cg.shared.global [%0], [%1], 16;\n" :: "r"(dst), "l"(src) : "memory")
#define CP_COMMIT()    asm volatile("cp.async.commit_group;\n" ::: "memory")
#define CP_WAIT(n)     asm volatile("cp.async.wait_group %0;\n" :: "n"(n) : "memory")

#define LDSM_X4(r0, r1, r2, r3, addr) \
    asm volatile("ldmatrix.sync.aligned.m8n8.x4.shared.b16 {%0,%1,%2,%3}, [%4];" \
        : "=r"(r0), "=r"(r1), "=r"(r2), "=r"(r3) : "r"(addr))

#define MMA_F16(c0, c1, c2, c3, a0, a1, a2, a3, b0, b1) \
    asm volatile("mma.sync.aligned.m16n8k16.row.col.f32.f16.f16.f32 " \
        "{%0,%1,%2,%3}, {%4,%5,%6,%7}, {%8,%9}, {%0,%1,%2,%3};" \
        : "+f"(c0), "+f"(c1), "+f"(c2), "+f"(c3) \
        : "r"(a0), "r"(a1), "r"(a2), "r"(a3), "r"(b0), "r"(b1))

__device__ __forceinline__ void split_f16(float v, __half& hi, __half& lo) {
    hi = __float2half_rn(v);
    lo = __float2half_rn(v - __half2float(hi));
}

// ======================================================================
// BIG GEMM: BMT in {64,128}, BN=128, BK=64, 128 threads (4 warps, 2m x 2n),
// warp tile (BMT/2)x64, 3-stage cp.async (S=2 supported).
// MODE 0: fp32 out (+bias/act). MODE 1: split2 fp16 [hi|lo] out.
// MODE 2 (BMT=64, G1 conv-fuse): xi tiles -> conv+silu+split2 into Cs;
//   z tiles -> single fp16 into Zs (ldc=DINNER).
// MODE 3: bias+ACT then single fp16 out to Cs (ldc=N).
// ======================================================================
template<int BMT, int ACT, int MODE>
__global__ void __launch_bounds__(128, (BMT == 64) ? 3 : 2) tgbig_k(
    const __half* __restrict__ A,
    const __half* __restrict__ B,
    const float* __restrict__ bias,
    float* __restrict__ Cout,
    __half* __restrict__ Cs,
    __half* __restrict__ Zs,
    int M, int N, int K2,
    const float* __restrict__ cw, const float* __restrict__ cb)
{
    constexpr int MT    = BMT / 32;
    constexpr int STAGE = (BMT + 128) * 128;
    extern __shared__ char dsm[];
    const uint32_t base = (smem_u32(dsm) + 1023u) & ~1023u;
    const uint32_t pad  = base - smem_u32(dsm);

    const int tid  = threadIdx.x;
    const int wid  = tid >> 5;
    const int lane = tid & 31;
    const int bm   = blockIdx.y * BMT;
    const int bn   = blockIdx.x * 128;

    const int wm = wid & 1;
    const int wn = wid >> 1;

    const uint32_t aRow  = (uint32_t)(wm * (BMT / 2) + (lane & 15));
    const uint32_t aKsel = (uint32_t)(((lane >> 4) & 1) * 16);
    const uint32_t bRow  = (uint32_t)(wn * 64 + (lane & 7) + ((lane >> 4) & 1) * 8);
    const uint32_t bKsel = (uint32_t)(((lane >> 3) & 1) * 16);

    float c[MT][8][4];
    #pragma unroll
    for (int mt = 0; mt < MT; mt++)
        #pragma unroll
        for (int nt = 0; nt < 8; nt++)
            #pragma unroll
            for (int r = 0; r < 4; r++) c[mt][nt][r] = 0.0f;

    const int S = K2 / 64;            // S >= 2

    auto load_stage = [&](uint32_t abase, int k0) {
        const uint32_t bbase = abase + BMT * 128;
        #pragma unroll
        for (int i = 0; i < (BMT * 8) / 128; i++) {
            int cc = tid + i * 128;
            int row = cc >> 3, ch = cc & 7;
            uint32_t dst = abase + SWZ((uint32_t)(row * 128 + ch * 16));
            CP16(dst, A + (size_t)(bm + row) * K2 + k0 + ch * 8);
        }
        #pragma unroll
        for (int i = 0; i < 8; i++) {
            int cc = tid + i * 128;
            int row = cc >> 3, ch = cc & 7;
            uint32_t dst = bbase + SWZ((uint32_t)(row * 128 + ch * 16));
            CP16(dst, B + (size_t)(bn + row) * K2 + k0 + ch * 8);
        }
        CP_COMMIT();
    };

    load_stage(base,         0);
    load_stage(base + STAGE, 64);
    if (S > 2) load_stage(base + 2 * STAGE, 128);

    for (int s = 0; s < S; s++) {
        if (s + 3 <= S)      { CP_WAIT(2); }
        else if (s + 2 == S) { CP_WAIT(1); }
        else                 { CP_WAIT(0); }
        __syncthreads();

        const int buf = s % 3;
        const uint32_t ab = base + (uint32_t)buf * STAGE;
        const uint32_t bb = ab + BMT * 128;

        #pragma unroll
        for (int ks = 0; ks < 4; ks++) {
            uint32_t a[MT][4];
            #pragma unroll
            for (int mt = 0; mt < MT; mt++) {
                uint32_t addr = ab + SWZ((aRow + mt * 16) * 128 + (uint32_t)ks * 32 + aKsel);
                LDSM_X4(a[mt][0], a[mt][1], a[mt][2], a[mt][3], addr);
            }
            #pragma unroll
            for (int ntp = 0; ntp < 4; ntp++) {
                uint32_t b0, b1, b2, b3;
                uint32_t addr = bb + SWZ((bRow + ntp * 16) * 128 + (uint32_t)ks * 32 + bKsel);
                LDSM_X4(b0, b1, b2, b3, addr);
                #pragma unroll
                for (int mt = 0; mt < MT; mt++) {
                    MMA_F16(c[mt][2 * ntp][0], c[mt][2 * ntp][1],
                            c[mt][2 * ntp][2], c[mt][2 * ntp][3],
                            a[mt][0], a[mt][1], a[mt][2], a[mt][3], b0, b1);
                    MMA_F16(c[mt][2 * ntp + 1][0], c[mt][2 * ntp + 1][1],
                            c[mt][2 * ntp + 1][2], c[mt][2 * ntp + 1][3],
                            a[mt][0], a[mt][1], a[mt][2], a[mt][3], b2, b3);
                }
            }
        }

        __syncthreads();
        if (s + 3 < S)
            load_stage(base + (uint32_t)buf * STAGE, (s + 3) * 64);
    }

    // epilogue
    const int g    = lane >> 2;
    const int tcol = (lane & 3) * 2;

    if (MODE == 2) {
        const bool is_xi = (bn < DINNER);
        if (is_xi) {
            float* sc = (float*)(dsm + pad);
            #pragma unroll
            for (int mt = 0; mt < MT; mt++)
                #pragma unroll
                for (int half = 0; half < 2; half++) {
                    const int rl = wm * (BMT / 2) + mt * 16 + half * 8 + g;
                    #pragma unroll
                    for (int nt = 0; nt < 8; nt++) {
                        const int cl = wn * 64 + nt * 8 + tcol;
                        *(float2*)&sc[rl * 128 + cl] =
                            make_float2(c[mt][nt][half * 2], c[mt][nt][half * 2 + 1]);
                    }
                }
            __syncthreads();
            const int d  = bn + tid;
            const float w0 = cw[d * 4 + 0], w1 = cw[d * 4 + 1];
            const float w2 = cw[d * 4 + 2], w3 = cw[d * 4 + 3];
            const float cbias = cb[d];
            float x0 = 0.f, x1 = 0.f, x2 = 0.f;
            for (int t = 0; t < TSEQ; t++) {
                const float x3 = sc[t * 128 + tid];
                const float v  = fmaf(w3, x3, fmaf(w2, x2, fmaf(w1, x1, w0 * x0))) + cbias;
                const float sv = silu_f(v);
                __half hi, lo; split_f16(sv, hi, lo);
                const size_t ob = (size_t)(bm + t) * (2 * DINNER);
                Cs[ob + d]          = hi;
                Cs[ob + DINNER + d] = lo;
                x0 = x1; x1 = x2; x2 = x3;
            }
        } else {
            const int zc = bn - DINNER;
            #pragma unroll
            for (int mt = 0; mt < MT; mt++)
                #pragma unroll
                for (int half = 0; half < 2; half++) {
                    const int row = bm + wm * (BMT / 2) + mt * 16 + half * 8 + g;
                    #pragma unroll
                    for (int nt = 0; nt < 8; nt++) {
                        const int col = zc + wn * 64 + nt * 8 + tcol;
                        *(__half2*)(Zs + (size_t)row * DINNER + col) =
                            __halves2half2(__float2half_rn(c[mt][nt][half * 2]),
                                           __float2half_rn(c[mt][nt][half * 2 + 1]));
                    }
                }
        }
        return;
    }

    #pragma unroll
    for (int mt = 0; mt < MT; mt++) {
        #pragma unroll
        for (int half = 0; half < 2; half++) {
            const int row = bm + wm * (BMT / 2) + mt * 16 + half * 8 + g;
            #pragma unroll
            for (int nt = 0; nt < 8; nt++) {
                const int col = bn + wn * 64 + nt * 8 + tcol;
                float v0 = c[mt][nt][half * 2 + 0];
                float v1 = c[mt][nt][half * 2 + 1];
                if (bias) { v0 += __ldg(&bias[col]); v1 += __ldg(&bias[col + 1]); }
                if (ACT == 2) { v0 = softplus_f(v0); v1 = softplus_f(v1); }
                if (MODE == 1) {
                    __half h0, l0, h1, l1;
                    split_f16(v0, h0, l0);
                    split_f16(v1, h1, l1);
                    __half* rp = Cs + (size_t)row * 2 * N;
                    *(__half2*)(rp + col)     = __halves2half2(h0, h1);
                    *(__half2*)(rp + N + col) = __halves2half2(l0, l1);
                } else if (MODE == 3) {
                    *(__half2*)(Cs + (size_t)row * N + col) =
                        __halves2half2(__float2half_rn(v0), __float2half_rn(v1));
                } else {
                    *(float2*)(Cout + (size_t)row * N + col) = make_float2(v0, v1);
                }
            }
        }
    }
}

// ======================================================================
// SMALL GEMM: BM=64, BN=128 tile, 256 threads, 3-stage (S=2 supported).
// SPLITK: plain stores to partial buffer z-slice (Cout + z*M*Nout).
// ======================================================================
template<int BM_, bool SPLITK, int ACT, bool SPLIT2>
__global__ void __launch_bounds__(256, 2) tgsm_k(
    const __half* __restrict__ A,
    const __half* __restrict__ B,
    const float* __restrict__ bias,
    float* __restrict__ Cout,
    __half* __restrict__ Cs,
    int M, int Nout, int K2, int kchunk)
{
    constexpr int NWM = BM_ / 32;
    constexpr int NWN = 8 / NWM;
    constexpr int WNW = 128 / NWN;
    constexpr int NT  = WNW / 8;
    constexpr int STAGE = (BM_ + 128) * 128;
    extern __shared__ char dsm[];
    const uint32_t base = (smem_u32(dsm) + 1023u) & ~1023u;

    const int tid  = threadIdx.x;
    const int wid  = tid >> 5;
    const int lane = tid & 31;
    const int bm   = blockIdx.y * BM_;
    const int bn   = blockIdx.x * 128;

    const int kbeg = SPLITK ? blockIdx.z * kchunk : 0;
    const int S    = (SPLITK ? kchunk : K2) / 64;

    float* Cpart = SPLITK ? (Cout + (size_t)blockIdx.z * M * Nout) : Cout;

    const int wm = wid % NWM;
    const int wn = wid / NWM;

    const uint32_t aRow  = (uint32_t)(wm * 32 + (lane & 15));
    const uint32_t aKsel = (uint32_t)(((lane >> 4) & 1) * 16);
    const uint32_t bRow  = (uint32_t)(wn * WNW + (lane & 7) + ((lane >> 4) & 1) * 8);
    const uint32_t bKsel = (uint32_t)(((lane >> 3) & 1) * 16);

    float c[2][NT][4];
    #pragma unroll
    for (int mt = 0; mt < 2; mt++)
        #pragma unroll
        for (int nt = 0; nt < NT; nt++)
            #pragma unroll
            for (int r = 0; r < 4; r++) c[mt][nt][r] = 0.0f;

    auto load_stage = [&](uint32_t abase, int k0) {
        const uint32_t bbase = abase + BM_ * 128;
        #pragma unroll
        for (int i = 0; i < (BM_ * 8) / 256; i++) {
            int cc = tid + i * 256;
            int row = cc >> 3, ch = cc & 7;
            uint32_t dst = abase + SWZ((uint32_t)(row * 128 + ch * 16));
            CP16(dst, A + (size_t)(bm + row) * K2 + k0 + ch * 8);
        }
        #pragma unroll
        for (int i = 0; i < 4; i++) {
            int cc = tid + i * 256;
            int row = cc >> 3, ch = cc & 7;
            uint32_t dst = bbase + SWZ((uint32_t)(row * 128 + ch * 16));
            CP16(dst, B + (size_t)(bn + row) * K2 + k0 + ch * 8);
        }
        CP_COMMIT();
    };

    load_stage(base,         kbeg);
    load_stage(base + STAGE, kbeg + 64);
    if (S > 2) load_stage(base + 2 * STAGE, kbeg + 128);

    for (int s = 0; s < S; s++) {
        if (s + 3 <= S)      { CP_WAIT(2); }
        else if (s + 2 == S) { CP_WAIT(1); }
        else                 { CP_WAIT(0); }
        __syncthreads();

        const int buf = s % 3;
        const uint32_t ab = base + (uint32_t)buf * STAGE;
        const uint32_t bb = ab + BM_ * 128;

        #pragma unroll
        for (int ks = 0; ks < 4; ks++) {
            uint32_t a[2][4], b[NT / 2][4];
            #pragma unroll
            for (int mt = 0; mt < 2; mt++) {
                uint32_t addr = ab + SWZ((aRow + mt * 16) * 128 + (uint32_t)ks * 32 + aKsel);
                LDSM_X4(a[mt][0], a[mt][1], a[mt][2], a[mt][3], addr);
            }
            #pragma unroll
            for (int ntp = 0; ntp < NT / 2; ntp++) {
                uint32_t addr = bb + SWZ((bRow + ntp * 16) * 128 + (uint32_t)ks * 32 + bKsel);
                LDSM_X4(b[ntp][0], b[ntp][1], b[ntp][2], b[ntp][3], addr);
            }
            #pragma unroll
            for (int mt = 0; mt < 2; mt++)
                #pragma unroll
                for (int nt = 0; nt < NT; nt++) {
                    const int ntp = nt >> 1, hi = nt & 1;
                    MMA_F16(c[mt][nt][0], c[mt][nt][1], c[mt][nt][2], c[mt][nt][3],
                            a[mt][0], a[mt][1], a[mt][2], a[mt][3],
                            b[ntp][hi * 2], b[ntp][hi * 2 + 1]);
                }
        }

        __syncthreads();
        if (s + 3 < S)
            load_stage(base + (uint32_t)buf * STAGE, kbeg + (s + 3) * 64);
    }

    const int g    = lane >> 2;
    const int tcol = (lane & 3) * 2;
    #pragma unroll
    for (int mt = 0; mt < 2; mt++) {
        #pragma unroll
        for (int half = 0; half < 2; half++) {
            const int row = bm + wm * 32 + mt * 16 + half * 8 + g;
            #pragma unroll
            for (int nt = 0; nt < NT; nt++) {
                const int col = bn + wn * WNW + nt * 8 + tcol;
                if (col >= Nout) continue;
                float v0 = c[mt][nt][half * 2 + 0];
                float v1 = c[mt][nt][half * 2 + 1];
                if (SPLITK) {
                    if (col + 1 < Nout) {
                        *(float2*)(Cpart + (size_t)row * Nout + col) = make_float2(v0, v1);
                    } else {
                        Cpart[(size_t)row * Nout + col] = v0;
                    }
                } else {
                    if (bias) { v0 += __ldg(&bias[col]); v1 += __ldg(&bias[col + 1]); }
                    if (ACT == 1) { v0 = fmaxf(v0, 0.0f); v1 = fmaxf(v1, 0.0f); }
                    if (SPLIT2) {
                        __half h0, l0, h1, l1;
                        split_f16(v0, h0, l0);
                        split_f16(v1, h1, l1);
                        __half* rp = Cs + (size_t)row * 2 * Nout;
                        *(__half2*)(rp + col)        = __halves2half2(h0, h1);
                        *(__half2*)(rp + Nout + col) = __halves2half2(l0, l1);
                    } else {
                        *(float2*)(Cout + (size_t)row * Nout + col) = make_float2(v0, v1);
                    }
                }
            }
        }
    }
}

// ---------------- concat + split2 ----------------
__global__ void concat_split_kernel(const float* __restrict__ sp,
                                    const float* __restrict__ te,
                                    __half* __restrict__ ax) {
    int i = blockIdx.x * 256 + threadIdx.x;
    if (i < NTOK * DMODEL) {
        int row = i >> 10, c = i & 1023;
        float v = (c < EDIM) ? sp[(size_t)row * EDIM + c]
                             : te[(size_t)row * EDIM + (c - EDIM)];
        __half hi, lo; split_f16(v, hi, lo);
        size_t b = (size_t)row * (2 * DMODEL);
        ax[b + c]          = hi;
        ax[b + DMODEL + c] = lo;
    }
}

// ---------------- batched weight transpose+dup: 6 jobs in one launch ----------------
struct WtJobs {
    const float* W[6];
    __half*      out[6];
    int          K[6];
    int          N[6];
    int          off[7];
};

__global__ void wt_split_all(WtJobs j) {
    __shared__ float s[32][33];
    const int b = blockIdx.x;
    int job = 0;
    #pragma unroll
    for (int q = 0; q < 5; q++) if (b >= j.off[q + 1]) job = q + 1;
    const float* W = j.W[job];
    __half* out    = j.out[job];
    const int K = j.K[job], N = j.N[job];
    const int rel = b - j.off[job];
    const int tilesN = N >> 5;
    const int n0 = (rel % tilesN) * 32;
    const int k0 = (rel / tilesN) * 32;

    const int tx = threadIdx.x, ty = threadIdx.y;
    #pragma unroll
    for (int i = 0; i < 4; i++)
        s[ty + 8 * i][tx] = W[(size_t)(k0 + ty + 8 * i) * N + n0 + tx];
    __syncthreads();
    #pragma unroll
    for (int i = 0; i < 4; i++) {
        int n = n0 + ty + 8 * i;
        float v = s[tx][ty + 8 * i];
        __half hi = __float2half_rn(v);
        size_t bo = (size_t)n * (2 * K) + k0 + tx;
        out[bo]     = hi;
        out[bo + K] = hi;
    }
}

// ---------------- reduce partials -> proj fp32 + dt_raw split2 ----------------
__global__ void reduce_dtraw_kernel(const float* __restrict__ projp,
                                    float* __restrict__ proj,
                                    __half* __restrict__ adt) {
    int i = blockIdx.x * 256 + threadIdx.x;
    if (i < NTOK * PROJW) {
        float v = projp[i] + projp[i + NTOK * PROJW]
                + projp[i + 2 * NTOK * PROJW] + projp[i + 3 * NTOK * PROJW];
        proj[i] = v;
        int r = i / PROJW, c = i - r * PROJW;
        if (c < DTRANK) {
            __half hi, lo; split_f16(v, hi, lo);
            size_t b = (size_t)r * (2 * DTRANK);
            adt[b + c]          = hi;
            adt[b + DTRANK + c] = lo;
        }
    }
}

// ---------------- selective scan + skip + gate (fp16 dt/z inputs) ----------------
__global__ void __launch_bounds__(512) scan_kernel(
    const float* __restrict__ proj,
    const __half* __restrict__ dt2,
    const __half* __restrict__ xc2,
    const __half* __restrict__ z2,
    const float* __restrict__ A_log,
    const float* __restrict__ D_skip,
    __half* __restrict__ y2)
{
    const int b = blockIdx.y;
    const int d = blockIdx.x * 512 + threadIdx.x;

    __shared__ float sBC[TSEQ][32];
    for (int i = threadIdx.x; i < TSEQ * 32; i += 512) {
        int t = i >> 5, c = i & 31;
        sBC[t][c] = proj[((size_t)(b * TSEQ + t)) * PROJW + DTRANK + c];
    }
    __syncthreads();

    float A2[DSTATE];
    #pragma unroll
    for (int n = 0; n < DSTATE; n++)
        A2[n] = -ex2f(A_log[(size_t)d * DSTATE + n] * LOG2E) * LOG2E;
    const float Dv = D_skip[d];

    float h[DSTATE];
    #pragma unroll
    for (int n = 0; n < DSTATE; n++) h[n] = 0.0f;

    const size_t rbase = (size_t)b * TSEQ;
    for (int t = 0; t < TSEQ; t++) {
        const size_t row = rbase + t;
        const float dtv = __half2float(dt2[row * DINNER + d]);
        const size_t xb = row * (2 * DINNER);
        const float xv  = __half2float(xc2[xb + d]) + __half2float(xc2[xb + DINNER + d]);
        const float zv  = __half2float(z2[row * DINNER + d]);
        const float dtx = dtv * xv;
        float yv = 0.0f;
        #pragma unroll
        for (int n = 0; n < DSTATE; n++) {
            const float dA = ex2f(dtv * A2[n]);
            h[n] = fmaf(dA, h[n], dtx * sBC[t][n]);
            yv   = fmaf(h[n], sBC[t][16 + n], yv);
        }
        yv = fmaf(xv, Dv, yv);
        const float val = yv * zv * rcpf(1.0f + ex2f(-LOG2E * zv));
        __half hi, lo; split_f16(val, hi, lo);
        const size_t ob = row * (2 * DINNER);
        y2[ob + d]          = hi;
        y2[ob + DINNER + d] = lo;
    }
}

// ---------------- head: out = h2 @ W3 + b3 (N=6) ----------------
__global__ void head_kernel(const float* __restrict__ h2,
                            const float* __restrict__ W3,
                            const float* __restrict__ b3,
                            float* __restrict__ out)
{
    __shared__ float sW[256 * 6];
    const int tid = threadIdx.x;
    for (int i = tid; i < 256 * 6; i += 256) sW[i] = W3[i];
    __syncthreads();

    const int warp = tid >> 5, lane = tid & 31;
    const int row  = blockIdx.x * 8 + warp;
    const float* hrow = h2 + (size_t)row * 256;

    float acc[6] = {0.f, 0.f, 0.f, 0.f, 0.f, 0.f};
    #pragma unroll
    for (int kk = 0; kk < 8; kk++) {
        const int k = kk * 32 + lane;
        const float v = hrow[k];
        #pragma unroll
        for (int j = 0; j < 6; j++) acc[j] = fmaf(v, sW[k * 6 + j], acc[j]);
    }
    #pragma unroll
    for (int j = 0; j < 6; j++) {
        #pragma unroll
        for (int o = 16; o > 0; o >>= 1)
            acc[j] += __shfl_xor_sync(0xffffffffu, acc[j], o);
    }
    if (lane == 0) {
        #pragma unroll
        for (int j = 0; j < 6; j++)
            out[(size_t)row * 6 + j] = acc[j] + b3[j];
    }
}

// ---------------- launch ----------------
extern "C" void kernel_launch(void* const* d_in, const int* in_sizes, int n_in,
                              void* d_out, int out_size)
{
    const float* spatial  = (const float*)d_in[0];
    const float* temporal = (const float*)d_in[1];
    const float* W_in     = (const float*)d_in[2];
    const float* conv_w   = (const float*)d_in[3];
    const float* conv_b   = (const float*)d_in[4];
    const float* W_x      = (const float*)d_in[5];
    const float* W_dt     = (const float*)d_in[6];
    const float* b_dt     = (const float*)d_in[7];
    const float* A_log    = (const float*)d_in[8];
    const float* D_skip   = (const float*)d_in[9];
    const float* W_out    = (const float*)d_in[10];
    const float* W1       = (const float*)d_in[11];
    const float* b1       = (const float*)d_in[12];
    const float* W2       = (const float*)d_in[13];
    const float* b2       = (const float*)d_in[14];
    const float* W3       = (const float*)d_in[15];
    const float* b3       = (const float*)d_in[16];
    float* out = (float*)d_out;

    float *pproj, *pprojp, *ph2;
    __half *pz2, *pdt2;
    __half *pAx, *pBwin, *pAxc, *pBwx, *pAdt, *pBwdt, *pAy, *pBwout,
           *pAf, *pBw1, *pAh1, *pBw2;
    cudaGetSymbolAddress((void**)&pproj,  g_proj);
    cudaGetSymbolAddress((void**)&pprojp, g_projp);
    cudaGetSymbolAddress((void**)&ph2,    g_h2);
    cudaGetSymbolAddress((void**)&pz2,    g_z2);
    cudaGetSymbolAddress((void**)&pdt2,   g_dt2);
    cudaGetSymbolAddress((void**)&pAx,    g_Ax);
    cudaGetSymbolAddress((void**)&pBwin,  g_Bwin);
    cudaGetSymbolAddress((void**)&pAxc,   g_Axc);
    cudaGetSymbolAddress((void**)&pBwx,   g_Bwx);
    cudaGetSymbolAddress((void**)&pAdt,   g_Adt);
    cudaGetSymbolAddress((void**)&pBwdt,  g_Bwdt);
    cudaGetSymbolAddress((void**)&pAy,    g_Ay);
    cudaGetSymbolAddress((void**)&pBwout, g_Bwout);
    cudaGetSymbolAddress((void**)&pAf,    g_Af);
    cudaGetSymbolAddress((void**)&pBw1,   g_Bw1);
    cudaGetSymbolAddress((void**)&pAh1,   g_Ah1);
    cudaGetSymbolAddress((void**)&pBw2,   g_Bw2);

    const int SMEM_B128 = 3 * (128 + 128) * 128 + 1024;   // 99328
    const int SMEM_B64  = 3 * (64  + 128) * 128 + 1024;   // 74752
    cudaFuncSetAttribute(tgbig_k<64,  0, 2>, cudaFuncAttributeMaxDynamicSharedMemorySize, SMEM_B64);
    cudaFuncSetAttribute(tgbig_k<128, 2, 3>, cudaFuncAttributeMaxDynamicSharedMemorySize, SMEM_B128);
    cudaFuncSetAttribute(tgbig_k<128, 0, 1>, cudaFuncAttributeMaxDynamicSharedMemorySize, SMEM_B128);
    cudaFuncSetAttribute(tgsm_k<64, true,  0, false>, cudaFuncAttributeMaxDynamicSharedMemorySize, SMEM_B64);
    cudaFuncSetAttribute(tgsm_k<64, false, 1, true>,  cudaFuncAttributeMaxDynamicSharedMemorySize, SMEM_B64);
    cudaFuncSetAttribute(tgsm_k<64, false, 1, false>, cudaFuncAttributeMaxDynamicSharedMemorySize, SMEM_B64);

    // weight-dup job table
    WtJobs wj;
    const float* Ws[6]  = { W_in, W_x, W_dt, W_out, W1, W2 };
    __half* Os[6]       = { pBwin, pBwx, pBwdt, pBwout, pBw1, pBw2 };
    const int Ks[6]     = { DMODEL, DINNER, DTRANK, DINNER, DMODEL, 512 };
    const int Ns[6]     = { 2 * DINNER, PROJW, DINNER, DMODEL, 512, 256 };
    int acc = 0;
    for (int q = 0; q < 6; q++) {
        wj.W[q] = Ws[q]; wj.out[q] = Os[q]; wj.K[q] = Ks[q]; wj.N[q] = Ns[q];
        wj.off[q] = acc;
        acc += (Ns[q] / 32) * (Ks[q] / 32);
    }
    wj.off[6] = acc;

    // 0) concat + split2
    concat_split_kernel<<<(NTOK * DMODEL + 255) / 256, 256>>>(spatial, temporal, pAx);
    // 1) all weight dups in one launch
    wt_split_all<<<acc, dim3(32, 8)>>>(wj);
    // 2) G1 (conv-fused): xi tiles -> conv+silu+split2 into xc2; z tiles -> fp16 z2
    tgbig_k<64, 0, 2><<<dim3(4096 / 128, NTOK / 64), 128, SMEM_B64>>>(
        pAx, pBwin, nullptr, nullptr, pAxc, pz2, NTOK, 4096, 2 * DMODEL, conv_w, conv_b);
    // 3) Gx: proj partials (split-K x4, plain stores, Nout=96)
    tgsm_k<64, true, 0, false><<<dim3(1, NTOK / 64, 4), 256, SMEM_B64>>>(
        pAxc, pBwx, nullptr, pprojp, nullptr, NTOK, PROJW, 2 * DINNER, 2 * DINNER / 4);
    // 4) reduce partials -> proj + dt_raw split2
    reduce_dtraw_kernel<<<(NTOK * PROJW + 255) / 256, 256>>>(pprojp, pproj, pAdt);
    // 5) G3: dt = softplus(dt_raw @ W_dt + b_dt) -> fp16 dt2 (MODE 3)
    tgbig_k<128, 2, 3><<<dim3(DINNER / 128, NTOK / 128), 128, SMEM_B128>>>(
        pAdt, pBwdt, b_dt, nullptr, pdt2, nullptr, NTOK, DINNER, 2 * DTRANK, nullptr, nullptr);
    // 6) scan -> y'' split2
    scan_kernel<<<dim3(DINNER / 512, BSZ), 512>>>(pproj, pdt2, pAxc, pz2, A_log, D_skip, pAy);
    // 7) G4: f'' = split2(y @ W_out)  N=1024, K''=4096
    tgbig_k<128, 0, 1><<<dim3(DMODEL / 128, NTOK / 128), 128, SMEM_B128>>>(
        pAy, pBwout, nullptr, nullptr, pAf, nullptr, NTOK, DMODEL, 2 * DINNER, nullptr, nullptr);
    // 8) G5: h1'' = split2(relu(f @ W1 + b1))  N=512, K''=2048  (BM=64)
    tgsm_k<64, false, 1, true><<<dim3(512 / 128, NTOK / 64), 256, SMEM_B64>>>(
        pAf, pBw1, b1, nullptr, pAh1, NTOK, 512, 2 * DMODEL, 0);
    // 9) G6: h2 = relu(h1 @ W2 + b2)  N=256, K''=1024  (BM=64)
    tgsm_k<64, false, 1, false><<<dim3(256 / 128, NTOK / 64), 256, SMEM_B64>>>(
        pAh1, pBw2, b2, ph2, nullptr, NTOK, 256, 2 * 512, 0);
    // 10) head
    head_kernel<<<NTOK / 8, 256>>>(ph2, W3, b3, out);
}

// round 15
// speedup vs baseline: 1.7381x; 1.2046x over previous
#include <cuda_runtime.h>
#include <cuda_fp16.h>
#include <math.h>
#include <stdint.h>

// ---------------- problem dims ----------------
#define BSZ     64
#define TSEQ    64
#define EDIM    512
#define DMODEL  1024
#define DINNER  2048
#define NTOK    (BSZ*TSEQ)       // 4096
#define DSTATE  16
#define DTRANK  64
#define PROJW   96

// ---------------- scratch (device globals, zero-initialized at load) ----------------
__device__ float g_proj [NTOK * PROJW];
__device__ float g_projp[4 * NTOK * PROJW];
__device__ float g_h2   [NTOK * 256];
__device__ __half g_z2  [NTOK * DINNER];     // gate z (fp16)
__device__ __half g_dt2 [NTOK * DINNER];     // softplus dt (fp16)
// activations: single fp16 unless noted
__device__ __half g_Ax   [NTOK * 2 * DMODEL];        // split2 [Ah|Al] (input)
__device__ __half g_Bwin [2 * DINNER * 2 * DMODEL];  // dup [Bh|Bh]
__device__ __half g_Axc  [NTOK * DINNER];            // xc single
__device__ __half g_Bwx  [128 * DINNER];             // single (rows 96..127 = 0)
__device__ __half g_Adt  [NTOK * 2 * DTRANK];        // dt_raw split2
__device__ __half g_Bwdt [DINNER * 2 * DTRANK];      // dup
__device__ __half g_Ay   [NTOK * DINNER];            // y single
__device__ __half g_Bwout[DMODEL * DINNER];          // single
__device__ __half g_Af   [NTOK * DMODEL];            // f single
__device__ __half g_Bw1  [512 * DMODEL];             // single
__device__ __half g_Ah1  [NTOK * 512];               // h1 single
__device__ __half g_Bw2  [256 * 512];                // single

// ---------------- MUFU transcendentals ----------------
__device__ __forceinline__ float ex2f(float x) { float y; asm("ex2.approx.f32 %0, %1;" : "=f"(y) : "f"(x)); return y; }
__device__ __forceinline__ float lg2f(float x) { float y; asm("lg2.approx.f32 %0, %1;" : "=f"(y) : "f"(x)); return y; }
__device__ __forceinline__ float rcpf(float x) { float y; asm("rcp.approx.f32 %0, %1;" : "=f"(y) : "f"(x)); return y; }
#define LOG2E 1.4426950408889634f
#define LN2   0.6931471805599453f

__device__ __forceinline__ float softplus_f(float x) {
    if (x > 15.0f) return x;
    return LN2 * lg2f(1.0f + ex2f(LOG2E * x));
}
__device__ __forceinline__ float silu_f(float x) {
    return x * rcpf(1.0f + ex2f(-LOG2E * x));
}

// ---------------- PTX helpers ----------------
__device__ __forceinline__ uint32_t smem_u32(const void* p) {
    uint32_t a;
    asm("{ .reg .u64 t; cvta.to.shared.u64 t, %1; cvt.u32.u64 %0, t; }" : "=r"(a) : "l"(p));
    return a;
}
#define SWZ(off) ((off) ^ (((off) >> 3) & 0x70))

#define CP16(dst, src) asm volatile("cp.async.cg.shared.global [%0], [%1], 16;\n" :: "r"(dst), "l"(src) : "memory")
#define CP_COMMIT()    asm volatile("cp.async.commit_group;\n" ::: "memory")
#define CP_WAIT(n)     asm volatile("cp.async.wait_group %0;\n" :: "n"(n) : "memory")

#define LDSM_X4(r0, r1, r2, r3, addr) \
    asm volatile("ldmatrix.sync.aligned.m8n8.x4.shared.b16 {%0,%1,%2,%3}, [%4];" \
        : "=r"(r0), "=r"(r1), "=r"(r2), "=r"(r3) : "r"(addr))

#define MMA_F16(c0, c1, c2, c3, a0, a1, a2, a3, b0, b1) \
    asm volatile("mma.sync.aligned.m16n8k16.row.col.f32.f16.f16.f32 " \
        "{%0,%1,%2,%3}, {%4,%5,%6,%7}, {%8,%9}, {%0,%1,%2,%3};" \
        : "+f"(c0), "+f"(c1), "+f"(c2), "+f"(c3) \
        : "r"(a0), "r"(a1), "r"(a2), "r"(a3), "r"(b0), "r"(b1))

__device__ __forceinline__ void split_f16(float v, __half& hi, __half& lo) {
    hi = __float2half_rn(v);
    lo = __float2half_rn(v - __half2float(hi));
}

// ======================================================================
// BIG GEMM: BMT in {64,128}, BN=128, BK=64, 128 threads (4 warps, 2m x 2n),
// warp tile (BMT/2)x64, 3-stage cp.async (S=2 supported).
// MODE 0: fp32 out (+bias/act). MODE 2 (BMT=64, conv-fuse): xi tiles ->
//   conv+silu -> SINGLE fp16 into Cs (ldc=DINNER); z tiles -> fp16 Zs.
// MODE 3: bias+ACT then single fp16 to Cs (ldc=N).
// ======================================================================
template<int BMT, int ACT, int MODE>
__global__ void __launch_bounds__(128, (BMT == 64) ? 3 : 2) tgbig_k(
    const __half* __restrict__ A,
    const __half* __restrict__ B,
    const float* __restrict__ bias,
    float* __restrict__ Cout,
    __half* __restrict__ Cs,
    __half* __restrict__ Zs,
    int M, int N, int K2,
    const float* __restrict__ cw, const float* __restrict__ cb)
{
    constexpr int MT    = BMT / 32;
    constexpr int STAGE = (BMT + 128) * 128;
    extern __shared__ char dsm[];
    const uint32_t base = (smem_u32(dsm) + 1023u) & ~1023u;
    const uint32_t pad  = base - smem_u32(dsm);

    const int tid  = threadIdx.x;
    const int wid  = tid >> 5;
    const int lane = tid & 31;
    const int bm   = blockIdx.y * BMT;
    const int bn   = blockIdx.x * 128;

    const int wm = wid & 1;
    const int wn = wid >> 1;

    const uint32_t aRow  = (uint32_t)(wm * (BMT / 2) + (lane & 15));
    const uint32_t aKsel = (uint32_t)(((lane >> 4) & 1) * 16);
    const uint32_t bRow  = (uint32_t)(wn * 64 + (lane & 7) + ((lane >> 4) & 1) * 8);
    const uint32_t bKsel = (uint32_t)(((lane >> 3) & 1) * 16);

    float c[MT][8][4];
    #pragma unroll
    for (int mt = 0; mt < MT; mt++)
        #pragma unroll
        for (int nt = 0; nt < 8; nt++)
            #pragma unroll
            for (int r = 0; r < 4; r++) c[mt][nt][r] = 0.0f;

    const int S = K2 / 64;            // S >= 2

    auto load_stage = [&](uint32_t abase, int k0) {
        const uint32_t bbase = abase + BMT * 128;
        #pragma unroll
        for (int i = 0; i < (BMT * 8) / 128; i++) {
            int cc = tid + i * 128;
            int row = cc >> 3, ch = cc & 7;
            uint32_t dst = abase + SWZ((uint32_t)(row * 128 + ch * 16));
            CP16(dst, A + (size_t)(bm + row) * K2 + k0 + ch * 8);
        }
        #pragma unroll
        for (int i = 0; i < 8; i++) {
            int cc = tid + i * 128;
            int row = cc >> 3, ch = cc & 7;
            uint32_t dst = bbase + SWZ((uint32_t)(row * 128 + ch * 16));
            CP16(dst, B + (size_t)(bn + row) * K2 + k0 + ch * 8);
        }
        CP_COMMIT();
    };

    load_stage(base,         0);
    load_stage(base + STAGE, 64);
    if (S > 2) load_stage(base + 2 * STAGE, 128);

    for (int s = 0; s < S; s++) {
        if (s + 3 <= S)      { CP_WAIT(2); }
        else if (s + 2 == S) { CP_WAIT(1); }
        else                 { CP_WAIT(0); }
        __syncthreads();

        const int buf = s % 3;
        const uint32_t ab = base + (uint32_t)buf * STAGE;
        const uint32_t bb = ab + BMT * 128;

        #pragma unroll
        for (int ks = 0; ks < 4; ks++) {
            uint32_t a[MT][4];
            #pragma unroll
            for (int mt = 0; mt < MT; mt++) {
                uint32_t addr = ab + SWZ((aRow + mt * 16) * 128 + (uint32_t)ks * 32 + aKsel);
                LDSM_X4(a[mt][0], a[mt][1], a[mt][2], a[mt][3], addr);
            }
            #pragma unroll
            for (int ntp = 0; ntp < 4; ntp++) {
                uint32_t b0, b1, b2, b3;
                uint32_t addr = bb + SWZ((bRow + ntp * 16) * 128 + (uint32_t)ks * 32 + bKsel);
                LDSM_X4(b0, b1, b2, b3, addr);
                #pragma unroll
                for (int mt = 0; mt < MT; mt++) {
                    MMA_F16(c[mt][2 * ntp][0], c[mt][2 * ntp][1],
                            c[mt][2 * ntp][2], c[mt][2 * ntp][3],
                            a[mt][0], a[mt][1], a[mt][2], a[mt][3], b0, b1);
                    MMA_F16(c[mt][2 * ntp + 1][0], c[mt][2 * ntp + 1][1],
                            c[mt][2 * ntp + 1][2], c[mt][2 * ntp + 1][3],
                            a[mt][0], a[mt][1], a[mt][2], a[mt][3], b2, b3);
                }
            }
        }

        __syncthreads();
        if (s + 3 < S)
            load_stage(base + (uint32_t)buf * STAGE, (s + 3) * 64);
    }

    // epilogue
    const int g    = lane >> 2;
    const int tcol = (lane & 3) * 2;

    if (MODE == 2) {
        const bool is_xi = (bn < DINNER);
        if (is_xi) {
            float* sc = (float*)(dsm + pad);
            #pragma unroll
            for (int mt = 0; mt < MT; mt++)
                #pragma unroll
                for (int half = 0; half < 2; half++) {
                    const int rl = wm * (BMT / 2) + mt * 16 + half * 8 + g;
                    #pragma unroll
                    for (int nt = 0; nt < 8; nt++) {
                        const int cl = wn * 64 + nt * 8 + tcol;
                        *(float2*)&sc[rl * 128 + cl] =
                            make_float2(c[mt][nt][half * 2], c[mt][nt][half * 2 + 1]);
                    }
                }
            __syncthreads();
            const int d  = bn + tid;
            const float w0 = cw[d * 4 + 0], w1 = cw[d * 4 + 1];
            const float w2 = cw[d * 4 + 2], w3 = cw[d * 4 + 3];
            const float cbias = cb[d];
            float x0 = 0.f, x1 = 0.f, x2 = 0.f;
            for (int t = 0; t < TSEQ; t++) {
                const float x3 = sc[t * 128 + tid];
                const float v  = fmaf(w3, x3, fmaf(w2, x2, fmaf(w1, x1, w0 * x0))) + cbias;
                Cs[(size_t)(bm + t) * DINNER + d] = __float2half_rn(silu_f(v));
                x0 = x1; x1 = x2; x2 = x3;
            }
        } else {
            const int zc = bn - DINNER;
            #pragma unroll
            for (int mt = 0; mt < MT; mt++)
                #pragma unroll
                for (int half = 0; half < 2; half++) {
                    const int row = bm + wm * (BMT / 2) + mt * 16 + half * 8 + g;
                    #pragma unroll
                    for (int nt = 0; nt < 8; nt++) {
                        const int col = zc + wn * 64 + nt * 8 + tcol;
                        *(__half2*)(Zs + (size_t)row * DINNER + col) =
                            __halves2half2(__float2half_rn(c[mt][nt][half * 2]),
                                           __float2half_rn(c[mt][nt][half * 2 + 1]));
                    }
                }
        }
        return;
    }

    #pragma unroll
    for (int mt = 0; mt < MT; mt++) {
        #pragma unroll
        for (int half = 0; half < 2; half++) {
            const int row = bm + wm * (BMT / 2) + mt * 16 + half * 8 + g;
            #pragma unroll
            for (int nt = 0; nt < 8; nt++) {
                const int col = bn + wn * 64 + nt * 8 + tcol;
                float v0 = c[mt][nt][half * 2 + 0];
                float v1 = c[mt][nt][half * 2 + 1];
                if (bias) { v0 += __ldg(&bias[col]); v1 += __ldg(&bias[col + 1]); }
                if (ACT == 2) { v0 = softplus_f(v0); v1 = softplus_f(v1); }
                if (MODE == 3) {
                    *(__half2*)(Cs + (size_t)row * N + col) =
                        __halves2half2(__float2half_rn(v0), __float2half_rn(v1));
                } else {
                    *(float2*)(Cout + (size_t)row * N + col) = make_float2(v0, v1);
                }
            }
        }
    }
}

// ======================================================================
// SMALL GEMM: BM=64, BN=128 tile, 256 threads, 3-stage (S=2 supported).
// OUT: 0 fp32 (+bias/act), 2 single fp16 (+bias/act).
// SPLITK: plain fp32 stores to partial z-slice.
// ======================================================================
template<int BM_, bool SPLITK, int ACT, int OUT>
__global__ void __launch_bounds__(256, 2) tgsm_k(
    const __half* __restrict__ A,
    const __half* __restrict__ B,
    const float* __restrict__ bias,
    float* __restrict__ Cout,
    __half* __restrict__ Cs,
    int M, int Nout, int K2, int kchunk)
{
    constexpr int NWM = BM_ / 32;
    constexpr int NWN = 8 / NWM;
    constexpr int WNW = 128 / NWN;
    constexpr int NT  = WNW / 8;
    constexpr int STAGE = (BM_ + 128) * 128;
    extern __shared__ char dsm[];
    const uint32_t base = (smem_u32(dsm) + 1023u) & ~1023u;

    const int tid  = threadIdx.x;
    const int wid  = tid >> 5;
    const int lane = tid & 31;
    const int bm   = blockIdx.y * BM_;
    const int bn   = blockIdx.x * 128;

    const int kbeg = SPLITK ? blockIdx.z * kchunk : 0;
    const int S    = (SPLITK ? kchunk : K2) / 64;

    float* Cpart = SPLITK ? (Cout + (size_t)blockIdx.z * M * Nout) : Cout;

    const int wm = wid % NWM;
    const int wn = wid / NWM;

    const uint32_t aRow  = (uint32_t)(wm * 32 + (lane & 15));
    const uint32_t aKsel = (uint32_t)(((lane >> 4) & 1) * 16);
    const uint32_t bRow  = (uint32_t)(wn * WNW + (lane & 7) + ((lane >> 4) & 1) * 8);
    const uint32_t bKsel = (uint32_t)(((lane >> 3) & 1) * 16);

    float c[2][NT][4];
    #pragma unroll
    for (int mt = 0; mt < 2; mt++)
        #pragma unroll
        for (int nt = 0; nt < NT; nt++)
            #pragma unroll
            for (int r = 0; r < 4; r++) c[mt][nt][r] = 0.0f;

    auto load_stage = [&](uint32_t abase, int k0) {
        const uint32_t bbase = abase + BM_ * 128;
        #pragma unroll
        for (int i = 0; i < (BM_ * 8) / 256; i++) {
            int cc = tid + i * 256;
            int row = cc >> 3, ch = cc & 7;
            uint32_t dst = abase + SWZ((uint32_t)(row * 128 + ch * 16));
            CP16(dst, A + (size_t)(bm + row) * K2 + k0 + ch * 8);
        }
        #pragma unroll
        for (int i = 0; i < 4; i++) {
            int cc = tid + i * 256;
            int row = cc >> 3, ch = cc & 7;
            uint32_t dst = bbase + SWZ((uint32_t)(row * 128 + ch * 16));
            CP16(dst, B + (size_t)(bn + row) * K2 + k0 + ch * 8);
        }
        CP_COMMIT();
    };

    load_stage(base,         kbeg);
    load_stage(base + STAGE, kbeg + 64);
    if (S > 2) load_stage(base + 2 * STAGE, kbeg + 128);

    for (int s = 0; s < S; s++) {
        if (s + 3 <= S)      { CP_WAIT(2); }
        else if (s + 2 == S) { CP_WAIT(1); }
        else                 { CP_WAIT(0); }
        __syncthreads();

        const int buf = s % 3;
        const uint32_t ab = base + (uint32_t)buf * STAGE;
        const uint32_t bb = ab + BM_ * 128;

        #pragma unroll
        for (int ks = 0; ks < 4; ks++) {
            uint32_t a[2][4], b[NT / 2][4];
            #pragma unroll
            for (int mt = 0; mt < 2; mt++) {
                uint32_t addr = ab + SWZ((aRow + mt * 16) * 128 + (uint32_t)ks * 32 + aKsel);
                LDSM_X4(a[mt][0], a[mt][1], a[mt][2], a[mt][3], addr);
            }
            #pragma unroll
            for (int ntp = 0; ntp < NT / 2; ntp++) {
                uint32_t addr = bb + SWZ((bRow + ntp * 16) * 128 + (uint32_t)ks * 32 + bKsel);
                LDSM_X4(b[ntp][0], b[ntp][1], b[ntp][2], b[ntp][3], addr);
            }
            #pragma unroll
            for (int mt = 0; mt < 2; mt++)
                #pragma unroll
                for (int nt = 0; nt < NT; nt++) {
                    const int ntp = nt >> 1, hi = nt & 1;
                    MMA_F16(c[mt][nt][0], c[mt][nt][1], c[mt][nt][2], c[mt][nt][3],
                            a[mt][0], a[mt][1], a[mt][2], a[mt][3],
                            b[ntp][hi * 2], b[ntp][hi * 2 + 1]);
                }
        }

        __syncthreads();
        if (s + 3 < S)
            load_stage(base + (uint32_t)buf * STAGE, kbeg + (s + 3) * 64);
    }

    const int g    = lane >> 2;
    const int tcol = (lane & 3) * 2;
    #pragma unroll
    for (int mt = 0; mt < 2; mt++) {
        #pragma unroll
        for (int half = 0; half < 2; half++) {
            const int row = bm + wm * 32 + mt * 16 + half * 8 + g;
            #pragma unroll
            for (int nt = 0; nt < NT; nt++) {
                const int col = bn + wn * WNW + nt * 8 + tcol;
                if (col >= Nout) continue;
                float v0 = c[mt][nt][half * 2 + 0];
                float v1 = c[mt][nt][half * 2 + 1];
                if (SPLITK) {
                    if (col + 1 < Nout) {
                        *(float2*)(Cpart + (size_t)row * Nout + col) = make_float2(v0, v1);
                    } else {
                        Cpart[(size_t)row * Nout + col] = v0;
                    }
                } else {
                    if (bias) { v0 += __ldg(&bias[col]); v1 += __ldg(&bias[col + 1]); }
                    if (ACT == 1) { v0 = fmaxf(v0, 0.0f); v1 = fmaxf(v1, 0.0f); }
                    if (OUT == 2) {
                        *(__half2*)(Cs + (size_t)row * Nout + col) =
                            __halves2half2(__float2half_rn(v0), __float2half_rn(v1));
                    } else {
                        *(float2*)(Cout + (size_t)row * Nout + col) = make_float2(v0, v1);
                    }
                }
            }
        }
    }
}

// ---------------- concat + split2 (input stays split2) ----------------
__global__ void concat_split_kernel(const float* __restrict__ sp,
                                    const float* __restrict__ te,
                                    __half* __restrict__ ax) {
    int i = blockIdx.x * 256 + threadIdx.x;
    if (i < NTOK * DMODEL) {
        int row = i >> 10, c = i & 1023;
        float v = (c < EDIM) ? sp[(size_t)row * EDIM + c]
                             : te[(size_t)row * EDIM + (c - EDIM)];
        __half hi, lo; split_f16(v, hi, lo);
        size_t b = (size_t)row * (2 * DMODEL);
        ax[b + c]          = hi;
        ax[b + DMODEL + c] = lo;
    }
}

// ---------------- batched weight transpose: 6 jobs in one launch ----------------
// W(KxN) -> out(N x (dup?2K:K)); dup writes [Bh|Bh].
struct WtJobs {
    const float* W[6];
    __half*      out[6];
    int          K[6];
    int          N[6];
    int          dup[6];
    int          off[7];
};

__global__ void wt_split_all(WtJobs j) {
    __shared__ float s[32][33];
    const int b = blockIdx.x;
    int job = 0;
    #pragma unroll
    for (int q = 0; q < 5; q++) if (b >= j.off[q + 1]) job = q + 1;
    const float* W = j.W[job];
    __half* out    = j.out[job];
    const int K = j.K[job], N = j.N[job], dup = j.dup[job];
    const int rel = b - j.off[job];
    const int tilesN = N >> 5;
    const int n0 = (rel % tilesN) * 32;
    const int k0 = (rel / tilesN) * 32;
    const int stride = dup ? 2 * K : K;

    const int tx = threadIdx.x, ty = threadIdx.y;
    #pragma unroll
    for (int i = 0; i < 4; i++)
        s[ty + 8 * i][tx] = W[(size_t)(k0 + ty + 8 * i) * N + n0 + tx];
    __syncthreads();
    #pragma unroll
    for (int i = 0; i < 4; i++) {
        int n = n0 + ty + 8 * i;
        float v = s[tx][ty + 8 * i];
        __half hi = __float2half_rn(v);
        size_t bo = (size_t)n * stride + k0 + tx;
        out[bo] = hi;
        if (dup) out[bo + K] = hi;
    }
}

// ---------------- reduce partials -> proj fp32 + dt_raw split2 ----------------
__global__ void reduce_dtraw_kernel(const float* __restrict__ projp,
                                    float* __restrict__ proj,
                                    __half* __restrict__ adt) {
    int i = blockIdx.x * 256 + threadIdx.x;
    if (i < NTOK * PROJW) {
        float v = projp[i] + projp[i + NTOK * PROJW]
                + projp[i + 2 * NTOK * PROJW] + projp[i + 3 * NTOK * PROJW];
        proj[i] = v;
        int r = i / PROJW, c = i - r * PROJW;
        if (c < DTRANK) {
            __half hi, lo; split_f16(v, hi, lo);
            size_t b = (size_t)r * (2 * DTRANK);
            adt[b + c]          = hi;
            adt[b + DTRANK + c] = lo;
        }
    }
}

// ---------------- selective scan (all fp16 activations) ----------------
__global__ void __launch_bounds__(512) scan_kernel(
    const float* __restrict__ proj,
    const __half* __restrict__ dt2,
    const __half* __restrict__ xc2,
    const __half* __restrict__ z2,
    const float* __restrict__ A_log,
    const float* __restrict__ D_skip,
    __half* __restrict__ y2)
{
    const int b = blockIdx.y;
    const int d = blockIdx.x * 512 + threadIdx.x;

    __shared__ float sBC[TSEQ][32];
    for (int i = threadIdx.x; i < TSEQ * 32; i += 512) {
        int t = i >> 5, c = i & 31;
        sBC[t][c] = proj[((size_t)(b * TSEQ + t)) * PROJW + DTRANK + c];
    }
    __syncthreads();

    float A2[DSTATE];
    #pragma unroll
    for (int n = 0; n < DSTATE; n++)
        A2[n] = -ex2f(A_log[(size_t)d * DSTATE + n] * LOG2E) * LOG2E;
    const float Dv = D_skip[d];

    float h[DSTATE];
    #pragma unroll
    for (int n = 0; n < DSTATE; n++) h[n] = 0.0f;

    const size_t rbase = (size_t)b * TSEQ;
    for (int t = 0; t < TSEQ; t++) {
        const size_t row = rbase + t;
        const float dtv = __half2float(dt2[row * DINNER + d]);
        const float xv  = __half2float(xc2[row * DINNER + d]);
        const float zv  = __half2float(z2[row * DINNER + d]);
        const float dtx = dtv * xv;
        float yv = 0.0f;
        #pragma unroll
        for (int n = 0; n < DSTATE; n++) {
            const float dA = ex2f(dtv * A2[n]);
            h[n] = fmaf(dA, h[n], dtx * sBC[t][n]);
            yv   = fmaf(h[n], sBC[t][16 + n], yv);
        }
        yv = fmaf(xv, Dv, yv);
        const float val = yv * zv * rcpf(1.0f + ex2f(-LOG2E * zv));
        y2[row * DINNER + d] = __float2half_rn(val);
    }
}

// ---------------- head: out = h2 @ W3 + b3 (N=6) ----------------
__global__ void head_kernel(const float* __restrict__ h2,
                            const float* __restrict__ W3,
                            const float* __restrict__ b3,
                            float* __restrict__ out)
{
    __shared__ float sW[256 * 6];
    const int tid = threadIdx.x;
    for (int i = tid; i < 256 * 6; i += 256) sW[i] = W3[i];
    __syncthreads();

    const int warp = tid >> 5, lane = tid & 31;
    const int row  = blockIdx.x * 8 + warp;
    const float* hrow = h2 + (size_t)row * 256;

    float acc[6] = {0.f, 0.f, 0.f, 0.f, 0.f, 0.f};
    #pragma unroll
    for (int kk = 0; kk < 8; kk++) {
        const int k = kk * 32 + lane;
        const float v = hrow[k];
        #pragma unroll
        for (int j = 0; j < 6; j++) acc[j] = fmaf(v, sW[k * 6 + j], acc[j]);
    }
    #pragma unroll
    for (int j = 0; j < 6; j++) {
        #pragma unroll
        for (int o = 16; o > 0; o >>= 1)
            acc[j] += __shfl_xor_sync(0xffffffffu, acc[j], o);
    }
    if (lane == 0) {
        #pragma unroll
        for (int j = 0; j < 6; j++)
            out[(size_t)row * 6 + j] = acc[j] + b3[j];
    }
}

// ---------------- launch ----------------
extern "C" void kernel_launch(void* const* d_in, const int* in_sizes, int n_in,
                              void* d_out, int out_size)
{
    const float* spatial  = (const float*)d_in[0];
    const float* temporal = (const float*)d_in[1];
    const float* W_in     = (const float*)d_in[2];
    const float* conv_w   = (const float*)d_in[3];
    const float* conv_b   = (const float*)d_in[4];
    const float* W_x      = (const float*)d_in[5];
    const float* W_dt     = (const float*)d_in[6];
    const float* b_dt     = (const float*)d_in[7];
    const float* A_log    = (const float*)d_in[8];
    const float* D_skip   = (const float*)d_in[9];
    const float* W_out    = (const float*)d_in[10];
    const float* W1       = (const float*)d_in[11];
    const float* b1       = (const float*)d_in[12];
    const float* W2       = (const float*)d_in[13];
    const float* b2       = (const float*)d_in[14];
    const float* W3       = (const float*)d_in[15];
    const float* b3       = (const float*)d_in[16];
    float* out = (float*)d_out;

    float *pproj, *pprojp, *ph2;
    __half *pz2, *pdt2;
    __half *pAx, *pBwin, *pAxc, *pBwx, *pAdt, *pBwdt, *pAy, *pBwout,
           *pAf, *pBw1, *pAh1, *pBw2;
    cudaGetSymbolAddress((void**)&pproj,  g_proj);
    cudaGetSymbolAddress((void**)&pprojp, g_projp);
    cudaGetSymbolAddress((void**)&ph2,    g_h2);
    cudaGetSymbolAddress((void**)&pz2,    g_z2);
    cudaGetSymbolAddress((void**)&pdt2,   g_dt2);
    cudaGetSymbolAddress((void**)&pAx,    g_Ax);
    cudaGetSymbolAddress((void**)&pBwin,  g_Bwin);
    cudaGetSymbolAddress((void**)&pAxc,   g_Axc);
    cudaGetSymbolAddress((void**)&pBwx,   g_Bwx);
    cudaGetSymbolAddress((void**)&pAdt,   g_Adt);
    cudaGetSymbolAddress((void**)&pBwdt,  g_Bwdt);
    cudaGetSymbolAddress((void**)&pAy,    g_Ay);
    cudaGetSymbolAddress((void**)&pBwout, g_Bwout);
    cudaGetSymbolAddress((void**)&pAf,    g_Af);
    cudaGetSymbolAddress((void**)&pBw1,   g_Bw1);
    cudaGetSymbolAddress((void**)&pAh1,   g_Ah1);
    cudaGetSymbolAddress((void**)&pBw2,   g_Bw2);

    const int SMEM_B128 = 3 * (128 + 128) * 128 + 1024;   // 99328
    const int SMEM_B64  = 3 * (64  + 128) * 128 + 1024;   // 74752
    cudaFuncSetAttribute(tgbig_k<64,  0, 2>, cudaFuncAttributeMaxDynamicSharedMemorySize, SMEM_B64);
    cudaFuncSetAttribute(tgbig_k<128, 2, 3>, cudaFuncAttributeMaxDynamicSharedMemorySize, SMEM_B128);
    cudaFuncSetAttribute(tgbig_k<128, 0, 3>, cudaFuncAttributeMaxDynamicSharedMemorySize, SMEM_B128);
    cudaFuncSetAttribute(tgsm_k<64, true,  0, 0>, cudaFuncAttributeMaxDynamicSharedMemorySize, SMEM_B64);
    cudaFuncSetAttribute(tgsm_k<64, false, 1, 2>, cudaFuncAttributeMaxDynamicSharedMemorySize, SMEM_B64);
    cudaFuncSetAttribute(tgsm_k<64, false, 1, 0>, cudaFuncAttributeMaxDynamicSharedMemorySize, SMEM_B64);

    // weight job table: W_in/W_dt dup'd, others single
    WtJobs wj;
    const float* Ws[6]  = { W_in, W_x, W_dt, W_out, W1, W2 };
    __half* Os[6]       = { pBwin, pBwx, pBwdt, pBwout, pBw1, pBw2 };
    const int Ks[6]     = { DMODEL, DINNER, DTRANK, DINNER, DMODEL, 512 };
    const int Ns[6]     = { 2 * DINNER, PROJW, DINNER, DMODEL, 512, 256 };
    const int Dups[6]   = { 1, 0, 1, 0, 0, 0 };
    int acc = 0;
    for (int q = 0; q < 6; q++) {
        wj.W[q] = Ws[q]; wj.out[q] = Os[q]; wj.K[q] = Ks[q]; wj.N[q] = Ns[q];
        wj.dup[q] = Dups[q];
        wj.off[q] = acc;
        acc += (Ns[q] / 32) * (Ks[q] / 32);
    }
    wj.off[6] = acc;

    // 0) concat + split2
    concat_split_kernel<<<(NTOK * DMODEL + 255) / 256, 256>>>(spatial, temporal, pAx);
    // 1) all weight transposes in one launch
    wt_split_all<<<acc, dim3(32, 8)>>>(wj);
    // 2) G1 (conv-fused): xi tiles -> conv+silu -> xc single; z tiles -> fp16 z2
    tgbig_k<64, 0, 2><<<dim3(4096 / 128, NTOK / 64), 128, SMEM_B64>>>(
        pAx, pBwin, nullptr, nullptr, pAxc, pz2, NTOK, 4096, 2 * DMODEL, conv_w, conv_b);
    // 3) Gx: proj partials (split-K x4, single xc, K=DINNER)
    tgsm_k<64, true, 0, 0><<<dim3(1, NTOK / 64, 4), 256, SMEM_B64>>>(
        pAxc, pBwx, nullptr, pprojp, nullptr, NTOK, PROJW, DINNER, DINNER / 4);
    // 4) reduce partials -> proj + dt_raw split2
    reduce_dtraw_kernel<<<(NTOK * PROJW + 255) / 256, 256>>>(pprojp, pproj, pAdt);
    // 5) G3: dt = softplus(dt_raw @ W_dt + b_dt) -> fp16 dt2
    tgbig_k<128, 2, 3><<<dim3(DINNER / 128, NTOK / 128), 128, SMEM_B128>>>(
        pAdt, pBwdt, b_dt, nullptr, pdt2, nullptr, NTOK, DINNER, 2 * DTRANK, nullptr, nullptr);
    // 6) scan -> y single fp16
    scan_kernel<<<dim3(DINNER / 512, BSZ), 512>>>(pproj, pdt2, pAxc, pz2, A_log, D_skip, pAy);
    // 7) G4: f = y @ W_out -> single fp16 (K=DINNER)
    tgbig_k<128, 0, 3><<<dim3(DMODEL / 128, NTOK / 128), 128, SMEM_B128>>>(
        pAy, pBwout, nullptr, nullptr, pAf, nullptr, NTOK, DMODEL, DINNER, nullptr, nullptr);
    // 8) G5: h1 = relu(f @ W1 + b1) -> single fp16 (K=DMODEL)
    tgsm_k<64, false, 1, 2><<<dim3(512 / 128, NTOK / 64), 256, SMEM_B64>>>(
        pAf, pBw1, b1, nullptr, pAh1, NTOK, 512, DMODEL, 0);
    // 9) G6: h2 = relu(h1 @ W2 + b2) -> fp32 (K=512)
    tgsm_k<64, false, 1, 0><<<dim3(256 / 128, NTOK / 64), 256, SMEM_B64>>>(
        pAh1, pBw2, b2, ph2, nullptr, NTOK, 256, 512, 0);
    // 10) head
    head_kernel<<<NTOK / 8, 256>>>(ph2, W3, b3, out);
}

// round 16
// speedup vs baseline: 1.7626x; 1.0141x over previous
#include <cuda_runtime.h>
#include <cuda_fp16.h>
#include <math.h>
#include <stdint.h>

// ---------------- problem dims ----------------
#define BSZ     64
#define TSEQ    64
#define EDIM    512
#define DMODEL  1024
#define DINNER  2048
#define NTOK    (BSZ*TSEQ)       // 4096
#define DSTATE  16
#define DTRANK  64
#define PROJW   96

// ---------------- scratch (device globals, zero-initialized at load) ----------------
__device__ float g_proj [NTOK * PROJW];
__device__ float g_projp[4 * NTOK * PROJW];
__device__ __half g_z2  [NTOK * DINNER];
__device__ __half g_dt2 [NTOK * DINNER];
__device__ __half g_Ax   [NTOK * 2 * DMODEL];        // split2 input
__device__ __half g_Bwin [2 * DINNER * 2 * DMODEL];  // dup
__device__ __half g_Axc  [NTOK * DINNER];            // xc single
__device__ __half g_Bwx  [128 * DINNER];             // rows 96..127 = 0
__device__ __half g_Adt  [NTOK * 2 * DTRANK];        // dt_raw split2
__device__ __half g_Bwdt [DINNER * 2 * DTRANK];      // dup
__device__ __half g_Ay   [NTOK * DINNER];
__device__ __half g_Bwout[DMODEL * DINNER];
__device__ __half g_Af   [NTOK * DMODEL];
__device__ __half g_Bw1  [512 * DMODEL];
__device__ __half g_Ah1  [NTOK * 512];
__device__ __half g_Bw2  [256 * 512];

// ---------------- MUFU transcendentals ----------------
__device__ __forceinline__ float ex2f(float x) { float y; asm("ex2.approx.f32 %0, %1;" : "=f"(y) : "f"(x)); return y; }
__device__ __forceinline__ float lg2f(float x) { float y; asm("lg2.approx.f32 %0, %1;" : "=f"(y) : "f"(x)); return y; }
__device__ __forceinline__ float rcpf(float x) { float y; asm("rcp.approx.f32 %0, %1;" : "=f"(y) : "f"(x)); return y; }
#define LOG2E 1.4426950408889634f
#define LN2   0.6931471805599453f

__device__ __forceinline__ float softplus_f(float x) {
    if (x > 15.0f) return x;
    return LN2 * lg2f(1.0f + ex2f(LOG2E * x));
}
__device__ __forceinline__ float silu_f(float x) {
    return x * rcpf(1.0f + ex2f(-LOG2E * x));
}

// ---------------- PTX helpers ----------------
__device__ __forceinline__ uint32_t smem_u32(const void* p) {
    uint32_t a;
    asm("{ .reg .u64 t; cvta.to.shared.u64 t, %1; cvt.u32.u64 %0, t; }" : "=r"(a) : "l"(p));
    return a;
}
#define SWZ(off) ((off) ^ (((off) >> 3) & 0x70))

#define CP16(dst, src) asm volatile("cp.async.cg.shared.global [%0], [%1], 16;\n" :: "r"(dst), "l"(src) : "memory")
#define CP_COMMIT()    asm volatile("cp.async.commit_group;\n" ::: "memory")
#define CP_WAIT(n)     asm volatile("cp.async.wait_group %0;\n" :: "n"(n) : "memory")

#define LDSM_X4(r0, r1, r2, r3, addr) \
    asm volatile("ldmatrix.sync.aligned.m8n8.x4.shared.b16 {%0,%1,%2,%3}, [%4];" \
        : "=r"(r0), "=r"(r1), "=r"(r2), "=r"(r3) : "r"(addr))

#define MMA_F16(c0, c1, c2, c3, a0, a1, a2, a3, b0, b1) \
    asm volatile("mma.sync.aligned.m16n8k16.row.col.f32.f16.f16.f32 " \
        "{%0,%1,%2,%3}, {%4,%5,%6,%7}, {%8,%9}, {%0,%1,%2,%3};" \
        : "+f"(c0), "+f"(c1), "+f"(c2), "+f"(c3) \
        : "r"(a0), "r"(a1), "r"(a2), "r"(a3), "r"(b0), "r"(b1))

__device__ __forceinline__ void split_f16(float v, __half& hi, __half& lo) {
    hi = __float2half_rn(v);
    lo = __float2half_rn(v - __half2float(hi));
}

// ======================================================================
// BIG GEMM (unchanged from R15 winner)
// ======================================================================
template<int BMT, int ACT, int MODE>
__global__ void __launch_bounds__(128, (BMT == 64) ? 3 : 2) tgbig_k(
    const __half* __restrict__ A,
    const __half* __restrict__ B,
    const float* __restrict__ bias,
    float* __restrict__ Cout,
    __half* __restrict__ Cs,
    __half* __restrict__ Zs,
    int M, int N, int K2,
    const float* __restrict__ cw, const float* __restrict__ cb)
{
    constexpr int MT    = BMT / 32;
    constexpr int STAGE = (BMT + 128) * 128;
    extern __shared__ char dsm[];
    const uint32_t base = (smem_u32(dsm) + 1023u) & ~1023u;
    const uint32_t pad  = base - smem_u32(dsm);

    const int tid  = threadIdx.x;
    const int wid  = tid >> 5;
    const int lane = tid & 31;
    const int bm   = blockIdx.y * BMT;
    const int bn   = blockIdx.x * 128;

    const int wm = wid & 1;
    const int wn = wid >> 1;

    const uint32_t aRow  = (uint32_t)(wm * (BMT / 2) + (lane & 15));
    const uint32_t aKsel = (uint32_t)(((lane >> 4) & 1) * 16);
    const uint32_t bRow  = (uint32_t)(wn * 64 + (lane & 7) + ((lane >> 4) & 1) * 8);
    const uint32_t bKsel = (uint32_t)(((lane >> 3) & 1) * 16);

    float c[MT][8][4];
    #pragma unroll
    for (int mt = 0; mt < MT; mt++)
        #pragma unroll
        for (int nt = 0; nt < 8; nt++)
            #pragma unroll
            for (int r = 0; r < 4; r++) c[mt][nt][r] = 0.0f;

    const int S = K2 / 64;

    auto load_stage = [&](uint32_t abase, int k0) {
        const uint32_t bbase = abase + BMT * 128;
        #pragma unroll
        for (int i = 0; i < (BMT * 8) / 128; i++) {
            int cc = tid + i * 128;
            int row = cc >> 3, ch = cc & 7;
            uint32_t dst = abase + SWZ((uint32_t)(row * 128 + ch * 16));
            CP16(dst, A + (size_t)(bm + row) * K2 + k0 + ch * 8);
        }
        #pragma unroll
        for (int i = 0; i < 8; i++) {
            int cc = tid + i * 128;
            int row = cc >> 3, ch = cc & 7;
            uint32_t dst = bbase + SWZ((uint32_t)(row * 128 + ch * 16));
            CP16(dst, B + (size_t)(bn + row) * K2 + k0 + ch * 8);
        }
        CP_COMMIT();
    };

    load_stage(base,         0);
    load_stage(base + STAGE, 64);
    if (S > 2) load_stage(base + 2 * STAGE, 128);

    for (int s = 0; s < S; s++) {
        if (s + 3 <= S)      { CP_WAIT(2); }
        else if (s + 2 == S) { CP_WAIT(1); }
        else                 { CP_WAIT(0); }
        __syncthreads();

        const int buf = s % 3;
        const uint32_t ab = base + (uint32_t)buf * STAGE;
        const uint32_t bb = ab + BMT * 128;

        #pragma unroll
        for (int ks = 0; ks < 4; ks++) {
            uint32_t a[MT][4];
            #pragma unroll
            for (int mt = 0; mt < MT; mt++) {
                uint32_t addr = ab + SWZ((aRow + mt * 16) * 128 + (uint32_t)ks * 32 + aKsel);
                LDSM_X4(a[mt][0], a[mt][1], a[mt][2], a[mt][3], addr);
            }
            #pragma unroll
            for (int ntp = 0; ntp < 4; ntp++) {
                uint32_t b0, b1, b2, b3;
                uint32_t addr = bb + SWZ((bRow + ntp * 16) * 128 + (uint32_t)ks * 32 + bKsel);
                LDSM_X4(b0, b1, b2, b3, addr);
                #pragma unroll
                for (int mt = 0; mt < MT; mt++) {
                    MMA_F16(c[mt][2 * ntp][0], c[mt][2 * ntp][1],
                            c[mt][2 * ntp][2], c[mt][2 * ntp][3],
                            a[mt][0], a[mt][1], a[mt][2], a[mt][3], b0, b1);
                    MMA_F16(c[mt][2 * ntp + 1][0], c[mt][2 * ntp + 1][1],
                            c[mt][2 * ntp + 1][2], c[mt][2 * ntp + 1][3],
                            a[mt][0], a[mt][1], a[mt][2], a[mt][3], b2, b3);
                }
            }
        }

        __syncthreads();
        if (s + 3 < S)
            load_stage(base + (uint32_t)buf * STAGE, (s + 3) * 64);
    }

    const int g    = lane >> 2;
    const int tcol = (lane & 3) * 2;

    if (MODE == 2) {
        const bool is_xi = (bn < DINNER);
        if (is_xi) {
            float* sc = (float*)(dsm + pad);
            #pragma unroll
            for (int mt = 0; mt < MT; mt++)
                #pragma unroll
                for (int half = 0; half < 2; half++) {
                    const int rl = wm * (BMT / 2) + mt * 16 + half * 8 + g;
                    #pragma unroll
                    for (int nt = 0; nt < 8; nt++) {
                        const int cl = wn * 64 + nt * 8 + tcol;
                        *(float2*)&sc[rl * 128 + cl] =
                            make_float2(c[mt][nt][half * 2], c[mt][nt][half * 2 + 1]);
                    }
                }
            __syncthreads();
            const int d  = bn + tid;
            const float w0 = cw[d * 4 + 0], w1 = cw[d * 4 + 1];
            const float w2 = cw[d * 4 + 2], w3 = cw[d * 4 + 3];
            const float cbias = cb[d];
            float x0 = 0.f, x1 = 0.f, x2 = 0.f;
            for (int t = 0; t < TSEQ; t++) {
                const float x3 = sc[t * 128 + tid];
                const float v  = fmaf(w3, x3, fmaf(w2, x2, fmaf(w1, x1, w0 * x0))) + cbias;
                Cs[(size_t)(bm + t) * DINNER + d] = __float2half_rn(silu_f(v));
                x0 = x1; x1 = x2; x2 = x3;
            }
        } else {
            const int zc = bn - DINNER;
            #pragma unroll
            for (int mt = 0; mt < MT; mt++)
                #pragma unroll
                for (int half = 0; half < 2; half++) {
                    const int row = bm + wm * (BMT / 2) + mt * 16 + half * 8 + g;
                    #pragma unroll
                    for (int nt = 0; nt < 8; nt++) {
                        const int col = zc + wn * 64 + nt * 8 + tcol;
                        *(__half2*)(Zs + (size_t)row * DINNER + col) =
                            __halves2half2(__float2half_rn(c[mt][nt][half * 2]),
                                           __float2half_rn(c[mt][nt][half * 2 + 1]));
                    }
                }
        }
        return;
    }

    #pragma unroll
    for (int mt = 0; mt < MT; mt++) {
        #pragma unroll
        for (int half = 0; half < 2; half++) {
            const int row = bm + wm * (BMT / 2) + mt * 16 + half * 8 + g;
            #pragma unroll
            for (int nt = 0; nt < 8; nt++) {
                const int col = bn + wn * 64 + nt * 8 + tcol;
                float v0 = c[mt][nt][half * 2 + 0];
                float v1 = c[mt][nt][half * 2 + 1];
                if (bias) { v0 += __ldg(&bias[col]); v1 += __ldg(&bias[col + 1]); }
                if (ACT == 2) { v0 = softplus_f(v0); v1 = softplus_f(v1); }
                if (MODE == 3) {
                    *(__half2*)(Cs + (size_t)row * N + col) =
                        __halves2half2(__float2half_rn(v0), __float2half_rn(v1));
                } else {
                    *(float2*)(Cout + (size_t)row * N + col) = make_float2(v0, v1);
                }
            }
        }
    }
}

// ======================================================================
// SMALL GEMM (unchanged from R15 winner)
// ======================================================================
template<int BM_, bool SPLITK, int ACT, int OUT>
__global__ void __launch_bounds__(256, 2) tgsm_k(
    const __half* __restrict__ A,
    const __half* __restrict__ B,
    const float* __restrict__ bias,
    float* __restrict__ Cout,
    __half* __restrict__ Cs,
    int M, int Nout, int K2, int kchunk)
{
    constexpr int NWM = BM_ / 32;
    constexpr int NWN = 8 / NWM;
    constexpr int WNW = 128 / NWN;
    constexpr int NT  = WNW / 8;
    constexpr int STAGE = (BM_ + 128) * 128;
    extern __shared__ char dsm[];
    const uint32_t base = (smem_u32(dsm) + 1023u) & ~1023u;

    const int tid  = threadIdx.x;
    const int wid  = tid >> 5;
    const int lane = tid & 31;
    const int bm   = blockIdx.y * BM_;
    const int bn   = blockIdx.x * 128;

    const int kbeg = SPLITK ? blockIdx.z * kchunk : 0;
    const int S    = (SPLITK ? kchunk : K2) / 64;

    float* Cpart = SPLITK ? (Cout + (size_t)blockIdx.z * M * Nout) : Cout;

    const int wm = wid % NWM;
    const int wn = wid / NWM;

    const uint32_t aRow  = (uint32_t)(wm * 32 + (lane & 15));
    const uint32_t aKsel = (uint32_t)(((lane >> 4) & 1) * 16);
    const uint32_t bRow  = (uint32_t)(wn * WNW + (lane & 7) + ((lane >> 4) & 1) * 8);
    const uint32_t bKsel = (uint32_t)(((lane >> 3) & 1) * 16);

    float c[2][NT][4];
    #pragma unroll
    for (int mt = 0; mt < 2; mt++)
        #pragma unroll
        for (int nt = 0; nt < NT; nt++)
            #pragma unroll
            for (int r = 0; r < 4; r++) c[mt][nt][r] = 0.0f;

    auto load_stage = [&](uint32_t abase, int k0) {
        const uint32_t bbase = abase + BM_ * 128;
        #pragma unroll
        for (int i = 0; i < (BM_ * 8) / 256; i++) {
            int cc = tid + i * 256;
            int row = cc >> 3, ch = cc & 7;
            uint32_t dst = abase + SWZ((uint32_t)(row * 128 + ch * 16));
            CP16(dst, A + (size_t)(bm + row) * K2 + k0 + ch * 8);
        }
        #pragma unroll
        for (int i = 0; i < 4; i++) {
            int cc = tid + i * 256;
            int row = cc >> 3, ch = cc & 7;
            uint32_t dst = bbase + SWZ((uint32_t)(row * 128 + ch * 16));
            CP16(dst, B + (size_t)(bn + row) * K2 + k0 + ch * 8);
        }
        CP_COMMIT();
    };

    load_stage(base,         kbeg);
    load_stage(base + STAGE, kbeg + 64);
    if (S > 2) load_stage(base + 2 * STAGE, kbeg + 128);

    for (int s = 0; s < S; s++) {
        if (s + 3 <= S)      { CP_WAIT(2); }
        else if (s + 2 == S) { CP_WAIT(1); }
        else                 { CP_WAIT(0); }
        __syncthreads();

        const int buf = s % 3;
        const uint32_t ab = base + (uint32_t)buf * STAGE;
        const uint32_t bb = ab + BM_ * 128;

        #pragma unroll
        for (int ks = 0; ks < 4; ks++) {
            uint32_t a[2][4], b[NT / 2][4];
            #pragma unroll
            for (int mt = 0; mt < 2; mt++) {
                uint32_t addr = ab + SWZ((aRow + mt * 16) * 128 + (uint32_t)ks * 32 + aKsel);
                LDSM_X4(a[mt][0], a[mt][1], a[mt][2], a[mt][3], addr);
            }
            #pragma unroll
            for (int ntp = 0; ntp < NT / 2; ntp++) {
                uint32_t addr = bb + SWZ((bRow + ntp * 16) * 128 + (uint32_t)ks * 32 + bKsel);
                LDSM_X4(b[ntp][0], b[ntp][1], b[ntp][2], b[ntp][3], addr);
            }
            #pragma unroll
            for (int mt = 0; mt < 2; mt++)
                #pragma unroll
                for (int nt = 0; nt < NT; nt++) {
                    const int ntp = nt >> 1, hi = nt & 1;
                    MMA_F16(c[mt][nt][0], c[mt][nt][1], c[mt][nt][2], c[mt][nt][3],
                            a[mt][0], a[mt][1], a[mt][2], a[mt][3],
                            b[ntp][hi * 2], b[ntp][hi * 2 + 1]);
                }
        }

        __syncthreads();
        if (s + 3 < S)
            load_stage(base + (uint32_t)buf * STAGE, kbeg + (s + 3) * 64);
    }

    const int g    = lane >> 2;
    const int tcol = (lane & 3) * 2;
    #pragma unroll
    for (int mt = 0; mt < 2; mt++) {
        #pragma unroll
        for (int half = 0; half < 2; half++) {
            const int row = bm + wm * 32 + mt * 16 + half * 8 + g;
            #pragma unroll
            for (int nt = 0; nt < NT; nt++) {
                const int col = bn + wn * WNW + nt * 8 + tcol;
                if (col >= Nout) continue;
                float v0 = c[mt][nt][half * 2 + 0];
                float v1 = c[mt][nt][half * 2 + 1];
                if (SPLITK) {
                    if (col + 1 < Nout) {
                        *(float2*)(Cpart + (size_t)row * Nout + col) = make_float2(v0, v1);
                    } else {
                        Cpart[(size_t)row * Nout + col] = v0;
                    }
                } else {
                    if (bias) { v0 += __ldg(&bias[col]); v1 += __ldg(&bias[col + 1]); }
                    if (ACT == 1) { v0 = fmaxf(v0, 0.0f); v1 = fmaxf(v1, 0.0f); }
                    if (OUT == 2) {
                        *(__half2*)(Cs + (size_t)row * Nout + col) =
                            __halves2half2(__float2half_rn(v0), __float2half_rn(v1));
                    } else {
                        *(float2*)(Cout + (size_t)row * Nout + col) = make_float2(v0, v1);
                    }
                }
            }
        }
    }
}

// ======================================================================
// FINAL GEMM + HEAD fused: h2 = relu(h1 @ W2 + b2); out = h2 @ W3 + b3.
// BM=64, BN=256 (full width), 256 threads (8 warps, 2m x 4n, 32x64 tiles),
// K=512, 3-stage. h2 stays in smem; head reduction in-register.
// ======================================================================
__global__ void __launch_bounds__(256, 1) tgfinal_k(
    const __half* __restrict__ A,   // h1: NTOK x 512
    const __half* __restrict__ B,   // Bw2: 256 x 512
    const float* __restrict__ b2,
    const float* __restrict__ W3,   // 256 x 6
    const float* __restrict__ b3,
    float* __restrict__ out)        // NTOK x 6
{
    constexpr int K2 = 512, S = 8;
    constexpr int STAGE = (64 + 256) * 128;        // 40960
    extern __shared__ char dsm[];
    const uint32_t base = (smem_u32(dsm) + 1023u) & ~1023u;
    const uint32_t pad  = base - smem_u32(dsm);

    const int tid  = threadIdx.x;
    const int wid  = tid >> 5;
    const int lane = tid & 31;
    const int bm   = blockIdx.y * 64;

    const int wm = wid & 1;           // 2 m-warps, 32 rows each
    const int wn = wid >> 1;          // 4 n-warps, 64 cols each

    const uint32_t aRow  = (uint32_t)(wm * 32 + (lane & 15));
    const uint32_t aKsel = (uint32_t)(((lane >> 4) & 1) * 16);
    const uint32_t bRow  = (uint32_t)(wn * 64 + (lane & 7) + ((lane >> 4) & 1) * 8);
    const uint32_t bKsel = (uint32_t)(((lane >> 3) & 1) * 16);

    float c[2][8][4];
    #pragma unroll
    for (int mt = 0; mt < 2; mt++)
        #pragma unroll
        for (int nt = 0; nt < 8; nt++)
            #pragma unroll
            for (int r = 0; r < 4; r++) c[mt][nt][r] = 0.0f;

    auto load_stage = [&](uint32_t abase, int k0) {
        const uint32_t bbase = abase + 64 * 128;
        #pragma unroll
        for (int i = 0; i < 2; i++) {              // A: 64 rows x 8 chunks
            int cc = tid + i * 256;
            int row = cc >> 3, ch = cc & 7;
            uint32_t dst = abase + SWZ((uint32_t)(row * 128 + ch * 16));
            CP16(dst, A + (size_t)(bm + row) * K2 + k0 + ch * 8);
        }
        #pragma unroll
        for (int i = 0; i < 8; i++) {              // B: 256 rows x 8 chunks
            int cc = tid + i * 256;
            int row = cc >> 3, ch = cc & 7;
            uint32_t dst = bbase + SWZ((uint32_t)(row * 128 + ch * 16));
            CP16(dst, B + (size_t)row * K2 + k0 + ch * 8);
        }
        CP_COMMIT();
    };

    load_stage(base,             0);
    load_stage(base + STAGE,     64);
    load_stage(base + 2 * STAGE, 128);

    for (int s = 0; s < S; s++) {
        if (s + 3 <= S)      { CP_WAIT(2); }
        else if (s + 2 == S) { CP_WAIT(1); }
        else                 { CP_WAIT(0); }
        __syncthreads();

        const int buf = s % 3;
        const uint32_t ab = base + (uint32_t)buf * STAGE;
        const uint32_t bb = ab + 64 * 128;

        #pragma unroll
        for (int ks = 0; ks < 4; ks++) {
            uint32_t a[2][4];
            #pragma unroll
            for (int mt = 0; mt < 2; mt++) {
                uint32_t addr = ab + SWZ((aRow + mt * 16) * 128 + (uint32_t)ks * 32 + aKsel);
                LDSM_X4(a[mt][0], a[mt][1], a[mt][2], a[mt][3], addr);
            }
            #pragma unroll
            for (int ntp = 0; ntp < 4; ntp++) {
                uint32_t b0, b1, b2r, b3r;
                uint32_t addr = bb + SWZ((bRow + ntp * 16) * 128 + (uint32_t)ks * 32 + bKsel);
                LDSM_X4(b0, b1, b2r, b3r, addr);
                #pragma unroll
                for (int mt = 0; mt < 2; mt++) {
                    MMA_F16(c[mt][2 * ntp][0], c[mt][2 * ntp][1],
                            c[mt][2 * ntp][2], c[mt][2 * ntp][3],
                            a[mt][0], a[mt][1], a[mt][2], a[mt][3], b0, b1);
                    MMA_F16(c[mt][2 * ntp + 1][0], c[mt][2 * ntp + 1][1],
                            c[mt][2 * ntp + 1][2], c[mt][2 * ntp + 1][3],
                            a[mt][0], a[mt][1], a[mt][2], a[mt][3], b2r, b3r);
                }
            }
        }

        __syncthreads();
        if (s + 3 < S)
            load_stage(base + (uint32_t)buf * STAGE, (s + 3) * 64);
    }

    // epilogue: bias+relu into smem h2 [64][256] fp32, then head
    float* sh2 = (float*)(dsm + pad);              // 65536 B
    float* sW3 = (float*)(dsm + pad + 65536);      // 6144 B
    const int g    = lane >> 2;
    const int tcol = (lane & 3) * 2;
    #pragma unroll
    for (int mt = 0; mt < 2; mt++) {
        #pragma unroll
        for (int half = 0; half < 2; half++) {
            const int rl = wm * 32 + mt * 16 + half * 8 + g;
            #pragma unroll
            for (int nt = 0; nt < 8; nt++) {
                const int col = wn * 64 + nt * 8 + tcol;
                float v0 = fmaxf(c[mt][nt][half * 2 + 0] + __ldg(&b2[col]), 0.0f);
                float v1 = fmaxf(c[mt][nt][half * 2 + 1] + __ldg(&b2[col + 1]), 0.0f);
                *(float2*)&sh2[rl * 256 + col] = make_float2(v0, v1);
            }
        }
    }
    for (int i = tid; i < 256 * 6; i += 256) sW3[i] = W3[i];
    __syncthreads();

    // head: each warp handles 8 rows
    #pragma unroll
    for (int rr = 0; rr < 8; rr++) {
        const int r = wid * 8 + rr;
        float acc[6] = {0.f, 0.f, 0.f, 0.f, 0.f, 0.f};
        #pragma unroll
        for (int kk = 0; kk < 8; kk++) {
            const int k = kk * 32 + lane;
            const float v = sh2[r * 256 + k];
            #pragma unroll
            for (int j = 0; j < 6; j++) acc[j] = fmaf(v, sW3[k * 6 + j], acc[j]);
        }
        #pragma unroll
        for (int j = 0; j < 6; j++) {
            #pragma unroll
            for (int o = 16; o > 0; o >>= 1)
                acc[j] += __shfl_xor_sync(0xffffffffu, acc[j], o);
        }
        if (lane == 0) {
            #pragma unroll
            for (int j = 0; j < 6; j++)
                out[(size_t)(bm + r) * 6 + j] = acc[j] + b3[j];
        }
    }
}

// ---------------- batched prep: 6 weight transposes + concat in one launch ----------------
struct WtJobs {
    const float* W[6];
    __half*      out[7];   // [6] = concat dest
    int          K[7];
    int          N[7];
    int          dup[6];
    int          off[8];
};

__global__ void prep_all(WtJobs j, const float* __restrict__ sp,
                         const float* __restrict__ te) {
    __shared__ float s[32][33];
    const int b = blockIdx.x;
    int job = 0;
    #pragma unroll
    for (int q = 0; q < 6; q++) if (b >= j.off[q + 1]) job = q + 1;
    const int rel = b - j.off[job];
    const int tx = threadIdx.x, ty = threadIdx.y;

    if (job == 6) {
        // concat + split2: tile 32 tokens x 32 channels
        const int tilesN = DMODEL / 32;
        const int n0 = (rel % tilesN) * 32;
        const int k0 = (rel / tilesN) * 32;
        __half* ax = j.out[6];
        #pragma unroll
        for (int i = 0; i < 4; i++) {
            const int row = k0 + ty + 8 * i;
            const int c   = n0 + tx;
            float v = (c < EDIM) ? sp[(size_t)row * EDIM + c]
                                 : te[(size_t)row * EDIM + (c - EDIM)];
            __half hi, lo; split_f16(v, hi, lo);
            size_t bb = (size_t)row * (2 * DMODEL);
            ax[bb + c]          = hi;
            ax[bb + DMODEL + c] = lo;
        }
        return;
    }

    const float* W = j.W[job];
    __half* outp   = j.out[job];
    const int K = j.K[job], N = j.N[job], dup = j.dup[job];
    const int tilesN = N >> 5;
    const int n0 = (rel % tilesN) * 32;
    const int k0 = (rel / tilesN) * 32;
    const int stride = dup ? 2 * K : K;

    #pragma unroll
    for (int i = 0; i < 4; i++)
        s[ty + 8 * i][tx] = W[(size_t)(k0 + ty + 8 * i) * N + n0 + tx];
    __syncthreads();
    #pragma unroll
    for (int i = 0; i < 4; i++) {
        int n = n0 + ty + 8 * i;
        float v = s[tx][ty + 8 * i];
        __half hi = __float2half_rn(v);
        size_t bo = (size_t)n * stride + k0 + tx;
        outp[bo] = hi;
        if (dup) outp[bo + K] = hi;
    }
}

// ---------------- reduce partials -> proj fp32 + dt_raw split2 ----------------
__global__ void reduce_dtraw_kernel(const float* __restrict__ projp,
                                    float* __restrict__ proj,
                                    __half* __restrict__ adt) {
    int i = blockIdx.x * 256 + threadIdx.x;
    if (i < NTOK * PROJW) {
        float v = projp[i] + projp[i + NTOK * PROJW]
                + projp[i + 2 * NTOK * PROJW] + projp[i + 3 * NTOK * PROJW];
        proj[i] = v;
        int r = i / PROJW, c = i - r * PROJW;
        if (c < DTRANK) {
            __half hi, lo; split_f16(v, hi, lo);
            size_t b = (size_t)r * (2 * DTRANK);
            adt[b + c]          = hi;
            adt[b + DTRANK + c] = lo;
        }
    }
}

// ---------------- selective scan (all fp16 activations) ----------------
__global__ void __launch_bounds__(512) scan_kernel(
    const float* __restrict__ proj,
    const __half* __restrict__ dt2,
    const __half* __restrict__ xc2,
    const __half* __restrict__ z2,
    const float* __restrict__ A_log,
    const float* __restrict__ D_skip,
    __half* __restrict__ y2)
{
    const int b = blockIdx.y;
    const int d = blockIdx.x * 512 + threadIdx.x;

    __shared__ float sBC[TSEQ][32];
    for (int i = threadIdx.x; i < TSEQ * 32; i += 512) {
        int t = i >> 5, c = i & 31;
        sBC[t][c] = proj[((size_t)(b * TSEQ + t)) * PROJW + DTRANK + c];
    }
    __syncthreads();

    float A2[DSTATE];
    #pragma unroll
    for (int n = 0; n < DSTATE; n++)
        A2[n] = -ex2f(A_log[(size_t)d * DSTATE + n] * LOG2E) * LOG2E;
    const float Dv = D_skip[d];

    float h[DSTATE];
    #pragma unroll
    for (int n = 0; n < DSTATE; n++) h[n] = 0.0f;

    const size_t rbase = (size_t)b * TSEQ;
    for (int t = 0; t < TSEQ; t++) {
        const size_t row = rbase + t;
        const float dtv = __half2float(dt2[row * DINNER + d]);
        const float xv  = __half2float(xc2[row * DINNER + d]);
        const float zv  = __half2float(z2[row * DINNER + d]);
        const float dtx = dtv * xv;
        float yv = 0.0f;
        #pragma unroll
        for (int n = 0; n < DSTATE; n++) {
            const float dA = ex2f(dtv * A2[n]);
            h[n] = fmaf(dA, h[n], dtx * sBC[t][n]);
            yv   = fmaf(h[n], sBC[t][16 + n], yv);
        }
        yv = fmaf(xv, Dv, yv);
        const float val = yv * zv * rcpf(1.0f + ex2f(-LOG2E * zv));
        y2[row * DINNER + d] = __float2half_rn(val);
    }
}

// ---------------- launch ----------------
extern "C" void kernel_launch(void* const* d_in, const int* in_sizes, int n_in,
                              void* d_out, int out_size)
{
    const float* spatial  = (const float*)d_in[0];
    const float* temporal = (const float*)d_in[1];
    const float* W_in     = (const float*)d_in[2];
    const float* conv_w   = (const float*)d_in[3];
    const float* conv_b   = (const float*)d_in[4];
    const float* W_x      = (const float*)d_in[5];
    const float* W_dt     = (const float*)d_in[6];
    const float* b_dt     = (const float*)d_in[7];
    const float* A_log    = (const float*)d_in[8];
    const float* D_skip   = (const float*)d_in[9];
    const float* W_out    = (const float*)d_in[10];
    const float* W1       = (const float*)d_in[11];
    const float* b1       = (const float*)d_in[12];
    const float* W2       = (const float*)d_in[13];
    const float* b2       = (const float*)d_in[14];
    const float* W3       = (const float*)d_in[15];
    const float* b3       = (const float*)d_in[16];
    float* out = (float*)d_out;

    float *pproj, *pprojp;
    __half *pz2, *pdt2;
    __half *pAx, *pBwin, *pAxc, *pBwx, *pAdt, *pBwdt, *pAy, *pBwout,
           *pAf, *pBw1, *pAh1, *pBw2;
    cudaGetSymbolAddress((void**)&pproj,  g_proj);
    cudaGetSymbolAddress((void**)&pprojp, g_projp);
    cudaGetSymbolAddress((void**)&pz2,    g_z2);
    cudaGetSymbolAddress((void**)&pdt2,   g_dt2);
    cudaGetSymbolAddress((void**)&pAx,    g_Ax);
    cudaGetSymbolAddress((void**)&pBwin,  g_Bwin);
    cudaGetSymbolAddress((void**)&pAxc,   g_Axc);
    cudaGetSymbolAddress((void**)&pBwx,   g_Bwx);
    cudaGetSymbolAddress((void**)&pAdt,   g_Adt);
    cudaGetSymbolAddress((void**)&pBwdt,  g_Bwdt);
    cudaGetSymbolAddress((void**)&pAy,    g_Ay);
    cudaGetSymbolAddress((void**)&pBwout, g_Bwout);
    cudaGetSymbolAddress((void**)&pAf,    g_Af);
    cudaGetSymbolAddress((void**)&pBw1,   g_Bw1);
    cudaGetSymbolAddress((void**)&pAh1,   g_Ah1);
    cudaGetSymbolAddress((void**)&pBw2,   g_Bw2);

    const int SMEM_B128 = 3 * (128 + 128) * 128 + 1024;   // 99328
    const int SMEM_B64  = 3 * (64  + 128) * 128 + 1024;   // 74752
    const int SMEM_FIN  = 3 * (64  + 256) * 128 + 1024;   // 123904
    cudaFuncSetAttribute(tgbig_k<64,  0, 2>, cudaFuncAttributeMaxDynamicSharedMemorySize, SMEM_B64);
    cudaFuncSetAttribute(tgbig_k<128, 2, 3>, cudaFuncAttributeMaxDynamicSharedMemorySize, SMEM_B128);
    cudaFuncSetAttribute(tgbig_k<128, 0, 3>, cudaFuncAttributeMaxDynamicSharedMemorySize, SMEM_B128);
    cudaFuncSetAttribute(tgsm_k<64, true,  0, 0>, cudaFuncAttributeMaxDynamicSharedMemorySize, SMEM_B64);
    cudaFuncSetAttribute(tgsm_k<64, false, 1, 2>, cudaFuncAttributeMaxDynamicSharedMemorySize, SMEM_B64);
    cudaFuncSetAttribute(tgfinal_k, cudaFuncAttributeMaxDynamicSharedMemorySize, SMEM_FIN);

    // prep job table: 6 weight jobs + concat (job 6)
    WtJobs wj;
    const float* Ws[6]  = { W_in, W_x, W_dt, W_out, W1, W2 };
    __half* Os[7]       = { pBwin, pBwx, pBwdt, pBwout, pBw1, pBw2, pAx };
    const int Ks[7]     = { DMODEL, DINNER, DTRANK, DINNER, DMODEL, 512, NTOK };
    const int Ns[7]     = { 2 * DINNER, PROJW, DINNER, DMODEL, 512, 256, DMODEL };
    const int Dups[6]   = { 1, 0, 1, 0, 0, 0 };
    int acc = 0;
    for (int q = 0; q < 7; q++) {
        if (q < 6) { wj.W[q] = Ws[q]; wj.dup[q] = Dups[q]; }
        wj.out[q] = Os[q]; wj.K[q] = Ks[q]; wj.N[q] = Ns[q];
        wj.off[q] = acc;
        acc += (Ns[q] / 32) * (Ks[q] / 32);
    }
    wj.off[7] = acc;

    // 0) prep: all weight transposes + concat/split2
    prep_all<<<acc, dim3(32, 8)>>>(wj, spatial, temporal);
    // 1) G1 (conv-fused): xi tiles -> conv+silu -> xc single; z tiles -> fp16 z2
    tgbig_k<64, 0, 2><<<dim3(4096 / 128, NTOK / 64), 128, SMEM_B64>>>(
        pAx, pBwin, nullptr, nullptr, pAxc, pz2, NTOK, 4096, 2 * DMODEL, conv_w, conv_b);
    // 2) Gx: proj partials (split-K x4, K=DINNER)
    tgsm_k<64, true, 0, 0><<<dim3(1, NTOK / 64, 4), 256, SMEM_B64>>>(
        pAxc, pBwx, nullptr, pprojp, nullptr, NTOK, PROJW, DINNER, DINNER / 4);
    // 3) reduce partials -> proj + dt_raw split2
    reduce_dtraw_kernel<<<(NTOK * PROJW + 255) / 256, 256>>>(pprojp, pproj, pAdt);
    // 4) G3: dt = softplus(dt_raw @ W_dt + b_dt) -> fp16 dt2
    tgbig_k<128, 2, 3><<<dim3(DINNER / 128, NTOK / 128), 128, SMEM_B128>>>(
        pAdt, pBwdt, b_dt, nullptr, pdt2, nullptr, NTOK, DINNER, 2 * DTRANK, nullptr, nullptr);
    // 5) scan -> y single fp16
    scan_kernel<<<dim3(DINNER / 512, BSZ), 512>>>(pproj, pdt2, pAxc, pz2, A_log, D_skip, pAy);
    // 6) G4: f = y @ W_out -> single fp16 (K=DINNER)
    tgbig_k<128, 0, 3><<<dim3(DMODEL / 128, NTOK / 128), 128, SMEM_B128>>>(
        pAy, pBwout, nullptr, nullptr, pAf, nullptr, NTOK, DMODEL, DINNER, nullptr, nullptr);
    // 7) G5: h1 = relu(f @ W1 + b1) -> single fp16 (K=DMODEL)
    tgsm_k<64, false, 1, 2><<<dim3(512 / 128, NTOK / 64), 256, SMEM_B64>>>(
        pAf, pBw1, b1, nullptr, pAh1, NTOK, 512, DMODEL, 0);
    // 8) G6+head fused: out = relu(h1@W2+b2) @ W3 + b3
    tgfinal_k<<<dim3(1, NTOK / 64), 256, SMEM_FIN>>>(
        pAh1, pBw2, b2, W3, b3, out);
}